// round 2
// baseline (speedup 1.0000x reference)
#include <cuda_runtime.h>
#include <math.h>

// ---------------------------------------------------------------------------
// Problem constants
// ---------------------------------------------------------------------------
#define BB 2
#define CC 128
#define HH 192
#define WW2 192
#define NHEAD 4
#define HD 32
#define WS 8
#define NTOK 73728           // B*H*W
#define HID 512
#define EPS_V 1e-5f

// ---------------------------------------------------------------------------
// Scratch buffers (device globals; allocation-free)
// ---------------------------------------------------------------------------
__device__ float g_x   [NTOK * CC];
__device__ float g_src [NTOK * CC];
__device__ float g_tgt [NTOK * CC];
__device__ float g_q   [NTOK * CC];
__device__ float g_kv  [NTOK * 2 * CC];
__device__ float g_attn[NTOK * CC];
__device__ float g_proj[NTOK * CC];
__device__ float g_x1  [NTOK * CC];
__device__ float g_h   [NTOK * HID];
__device__ float g_sa  [NTOK * CC];
__device__ float g_ta  [NTOK * CC];

// ---------------------------------------------------------------------------
// Layout transforms
// ---------------------------------------------------------------------------
__global__ void nchw2nhwc(const float* __restrict__ in, float* __restrict__ out) {
    size_t i = (size_t)blockIdx.x * blockDim.x + threadIdx.x;   // over out idx (c fastest)
    if (i >= (size_t)NTOK * CC) return;
    int c = i % CC; size_t r = i / CC;
    int w = r % WW2; r /= WW2;
    int h = r % HH;  int b = r / HH;
    out[i] = in[(((size_t)b * CC + c) * HH + h) * WW2 + w];
}

__global__ void nhwc2nchw(const float* __restrict__ in, float* __restrict__ out) {
    size_t i = (size_t)blockIdx.x * blockDim.x + threadIdx.x;   // over out idx (w fastest)
    if (i >= (size_t)NTOK * CC) return;
    int w = i % WW2; size_t r = i / WW2;
    int h = r % HH; r /= HH;
    int c = r % CC; int b = r / CC;
    out[i] = in[(((size_t)b * HH + h) * WW2 + w) * CC + c];
}

// ---------------------------------------------------------------------------
// SGEMM: C[M,N] = epilogue(A[M,K] @ W[K,N]); M tile = 128 via blockIdx.y.
// EPI: 0 = *scale, 1 = (acc+bias)*scale, 2 = gelu((acc+bias)*scale)
// BM=BN=128, BK=8, 256 threads, 8x8 per thread. M,N,K multiples of 128/8.
// ---------------------------------------------------------------------------
template <int EPI>
__global__ void sgemm(const float* __restrict__ A, const float* __restrict__ W,
                      const float* __restrict__ bias, float* __restrict__ C,
                      int N, int K, float scale) {
    __shared__ float As[8][128];
    __shared__ float Bs[8][128];
    const int tid = threadIdx.x;
    const int tx = tid % 16, ty = tid / 16;
    const int bx = blockIdx.x, by = blockIdx.y;

    const float* Ablk = A + (size_t)by * 128 * K;
    const float* Wblk = W + (size_t)bx * 128;

    const int arow = tid >> 1;
    const int acol = (tid & 1) * 4;
    const int brow = tid >> 5;
    const int bcol = (tid & 31) * 4;

    float acc[8][8];
#pragma unroll
    for (int i = 0; i < 8; i++)
#pragma unroll
        for (int j = 0; j < 8; j++) acc[i][j] = 0.f;

    for (int k0 = 0; k0 < K; k0 += 8) {
        float4 a4 = *(const float4*)(Ablk + (size_t)arow * K + k0 + acol);
        As[acol + 0][arow] = a4.x;
        As[acol + 1][arow] = a4.y;
        As[acol + 2][arow] = a4.z;
        As[acol + 3][arow] = a4.w;
        float4 b4 = *(const float4*)(Wblk + (size_t)(k0 + brow) * N + bcol);
        *(float4*)&Bs[brow][bcol] = b4;
        __syncthreads();
#pragma unroll
        for (int kk = 0; kk < 8; kk++) {
            float af[8], bf[8];
#pragma unroll
            for (int i = 0; i < 8; i++) af[i] = As[kk][ty * 8 + i];
#pragma unroll
            for (int j = 0; j < 8; j++) bf[j] = Bs[kk][tx * 8 + j];
#pragma unroll
            for (int i = 0; i < 8; i++)
#pragma unroll
                for (int j = 0; j < 8; j++) acc[i][j] += af[i] * bf[j];
        }
        __syncthreads();
    }

#pragma unroll
    for (int i = 0; i < 8; i++) {
        int row = by * 128 + ty * 8 + i;
#pragma unroll
        for (int j = 0; j < 8; j += 4) {
            int col = bx * 128 + tx * 8 + j;
            float4 o;
            float* po = &o.x;
#pragma unroll
            for (int jj = 0; jj < 4; jj++) {
                float v = acc[i][j + jj];
                if (EPI >= 1) v += bias[col + jj];
                v *= scale;
                if (EPI == 2) v = v * normcdff(v);
                po[jj] = v;
            }
            *(float4*)(C + (size_t)row * N + col) = o;
        }
    }
}

// ---------------------------------------------------------------------------
// Windowed attention. One block = (window, batch, head). 64 threads = 64 query
// tokens. Gathers q/k/v through the shift mapping; scatters output back, so
// roll / window-partition / window-reverse never materialize.
// ---------------------------------------------------------------------------
__device__ __forceinline__ int region_label(int h, int w) {
    int rh = (h < HH - WS) ? 0 : ((h < HH - WS / 2) ? 1 : 2);
    int rw = (w < WW2 - WS) ? 0 : ((w < WW2 - WS / 2) ? 1 : 2);
    return rh * 3 + rw;
}

__global__ void attn_kernel(const float* __restrict__ q, const float* __restrict__ kv,
                            const float* __restrict__ relb, float* __restrict__ out,
                            int shift) {
    const int win = blockIdx.x;          // 0..575
    const int b   = blockIdx.y;
    const int h   = blockIdx.z;
    const int gy = win / (WW2 / WS), gx = win % (WW2 / WS);
    const int t  = threadIdx.x;          // query token 0..63
    const int ty = t >> 3, tx = t & 7;

    __shared__ float ks[64][33];
    __shared__ float vs[64][33];

    const int py = (gy * WS + ty + shift) % HH;
    const int px = (gx * WS + tx + shift) % WW2;
    const size_t pix = ((size_t)b * HH + py) * WW2 + px;

    const float* kvrow = kv + pix * (2 * CC) + h * HD;
#pragma unroll
    for (int d = 0; d < HD; d++) {
        ks[t][d] = kvrow[d];
        vs[t][d] = kvrow[CC + d];
    }
    float qr[HD];
    const float* qrow = q + pix * CC + h * HD;
#pragma unroll
    for (int d = 0; d < HD; d++) qr[d] = qrow[d];
    __syncthreads();

    int li = 0;
    if (shift) li = region_label(gy * WS + ty, gx * WS + tx);

    float s[64];
    float mx = -1e30f;
#pragma unroll
    for (int j = 0; j < 64; j++) {
        float acc = 0.f;
#pragma unroll
        for (int d = 0; d < HD; d++) acc += qr[d] * ks[j][d];
        int jy = j >> 3, jx = j & 7;
        acc += relb[((ty - jy + WS - 1) * (2 * WS - 1) + (tx - jx + WS - 1)) * NHEAD + h];
        if (shift) {
            int lj = region_label(gy * WS + jy, gx * WS + jx);
            if (lj != li) acc -= 100.0f;
        }
        s[j] = acc;
        mx = fmaxf(mx, acc);
    }
    float sum = 0.f;
#pragma unroll
    for (int j = 0; j < 64; j++) { s[j] = expf(s[j] - mx); sum += s[j]; }
    const float inv = 1.0f / sum;

    float* orow = out + pix * CC + h * HD;
#pragma unroll
    for (int d = 0; d < HD; d++) {
        float o = 0.f;
#pragma unroll
        for (int j = 0; j < 64; j++) o += s[j] * vs[j][d];
        orow[d] = o * inv;
    }
}

// ---------------------------------------------------------------------------
// out[t] = shortcut[t] + LayerNorm(y[t]) * g + b   (one token per 128-thr block)
// ---------------------------------------------------------------------------
__global__ void ln_residual(const float* __restrict__ y, const float* __restrict__ sc,
                            const float* __restrict__ g, const float* __restrict__ bta,
                            float* __restrict__ out) {
    const int tk = blockIdx.x;
    const int c  = threadIdx.x;
    __shared__ float red[4];
    float v = y[(size_t)tk * CC + c];

    float s = v;
#pragma unroll
    for (int o = 16; o; o >>= 1) s += __shfl_xor_sync(0xffffffffu, s, o);
    if ((c & 31) == 0) red[c >> 5] = s;
    __syncthreads();
    float mu = (red[0] + red[1] + red[2] + red[3]) * (1.f / CC);

    float dv = v - mu;
    float s2 = dv * dv;
#pragma unroll
    for (int o = 16; o; o >>= 1) s2 += __shfl_xor_sync(0xffffffffu, s2, o);
    __syncthreads();
    if ((c & 31) == 0) red[c >> 5] = s2;
    __syncthreads();
    float var = (red[0] + red[1] + red[2] + red[3]) * (1.f / CC);

    out[(size_t)tk * CC + c] = sc[(size_t)tk * CC + c] + dv * rsqrtf(var + EPS_V) * g[c] + bta[c];
}

// ---------------------------------------------------------------------------
// Direct 3x3 conv (256->128) + bias + PReLU. Block: 16 x-pixels, 1 row, 1 batch,
// 128 threads (one per out-channel). Input (sa|ta) staged in smem; smem reads
// are broadcast across threads (same address), so conflict-free.
// ---------------------------------------------------------------------------
__global__ void conv3_prelu(const float* __restrict__ sa, const float* __restrict__ ta,
                            const float* __restrict__ Wt, const float* __restrict__ bias,
                            const float* __restrict__ pa, float* __restrict__ out) {
    __shared__ float sm[3][18][128];
    const int x0 = blockIdx.x * 16;
    const int yy = blockIdx.y;
    const int b  = blockIdx.z;
    const int oc = threadIdx.x;

    float acc[16];
#pragma unroll
    for (int p = 0; p < 16; p++) acc[p] = bias[oc];

    for (int half = 0; half < 2; half++) {
        const float* src = half ? ta : sa;
        for (int idx = threadIdx.x; idx < 3 * 18 * 128; idx += 128) {
            int r = idx / (18 * 128);
            int rem = idx % (18 * 128);
            int p = rem / 128;
            int ic = rem % 128;
            int ys = yy - 1 + r, xs = x0 - 1 + p;
            float vv = 0.f;
            if (ys >= 0 && ys < HH && xs >= 0 && xs < WW2)
                vv = src[(((size_t)b * HH + ys) * WW2 + xs) * CC + ic];
            sm[r][p][ic] = vv;
        }
        __syncthreads();

        const float* wbase = Wt + ((size_t)oc * 256 + half * 128) * 9;
        for (int ic = 0; ic < 128; ic++) {
            float w[9];
#pragma unroll
            for (int qq = 0; qq < 9; qq++) w[qq] = wbase[(size_t)ic * 9 + qq];
#pragma unroll
            for (int ky = 0; ky < 3; ky++) {
                float sv[18];
#pragma unroll
                for (int p = 0; p < 18; p++) sv[p] = sm[ky][p][ic];
#pragma unroll
                for (int p = 0; p < 16; p++)
                    acc[p] += w[ky * 3 + 0] * sv[p] + w[ky * 3 + 1] * sv[p + 1] + w[ky * 3 + 2] * sv[p + 2];
            }
        }
        __syncthreads();
    }

    const float a = pa[oc];
#pragma unroll
    for (int p = 0; p < 16; p++) {
        float vv = acc[p];
        if (vv < 0.f) vv *= a;
        out[(((size_t)b * HH + yy) * WW2 + x0 + p) * CC + oc] = vv;
    }
}

// ---------------------------------------------------------------------------
// Host driver (graph-capturable: launches only)
// ---------------------------------------------------------------------------
template <typename T>
static float* sym(const T& s) {
    void* p = nullptr;
    cudaGetSymbolAddress(&p, s);
    return (float*)p;
}

extern "C" void kernel_launch(void* const* d_in, const int* in_sizes, int n_in,
                              void* d_out, int out_size) {
    const float* x      = (const float*)d_in[0];
    const float* source = (const float*)d_in[1];
    const float* target = (const float*)d_in[2];
    const float* qW     = (const float*)d_in[3];
    const float* qb     = (const float*)d_in[4];
    const float* kvW    = (const float*)d_in[5];
    const float* kvb    = (const float*)d_in[6];
    const float* pW     = (const float*)d_in[7];
    const float* pb     = (const float*)d_in[8];
    const float* relb   = (const float*)d_in[9];
    const float* mW     = (const float*)d_in[10];
    const float* n1g    = (const float*)d_in[11];
    const float* n1b    = (const float*)d_in[12];
    const float* f1W    = (const float*)d_in[13];
    const float* f1b    = (const float*)d_in[14];
    const float* f2W    = (const float*)d_in[15];
    const float* f2b    = (const float*)d_in[16];
    const float* n2g    = (const float*)d_in[17];
    const float* n2b    = (const float*)d_in[18];
    const float* convW  = (const float*)d_in[19];
    const float* convb  = (const float*)d_in[20];
    const float* pa     = (const float*)d_in[21];

    float* bx    = sym(g_x);
    float* bsrc  = sym(g_src);
    float* btgt  = sym(g_tgt);
    float* bq    = sym(g_q);
    float* bkv   = sym(g_kv);
    float* battn = sym(g_attn);
    float* bproj = sym(g_proj);
    float* bx1   = sym(g_x1);
    float* bh    = sym(g_h);
    float* bsa   = sym(g_sa);
    float* bta   = sym(g_ta);

    const float SCALE = 0.1767766952966369f;   // 32^-0.5
    const int nblk = (NTOK * CC + 255) / 256;
    const dim3 gM1(1, NTOK / 128), gM2(2, NTOK / 128), gM4(4, NTOK / 128);

    nchw2nhwc<<<nblk, 256>>>(x, bx);
    nchw2nhwc<<<nblk, 256>>>(source, bsrc);
    nchw2nhwc<<<nblk, 256>>>(target, btgt);

    for (int d = 0; d < 2; d++) {
        const int shift = (d % 2) ? (WS / 2) : 0;
        // q = (x @ qW + qb) * scale   (shared by both branches)
        sgemm<1><<<gM1, 256>>>(bx, qW + (size_t)d * CC * CC, qb + d * CC, bq, CC, CC, SCALE);

        for (int br = 0; br < 2; br++) {
            const float* feat = br ? btgt : bsrc;
            float* dest = br ? bta : bsa;
            // kv = feat @ kvW + kvb   [T, 256]
            sgemm<1><<<gM2, 256>>>(feat, kvW + (size_t)d * CC * 2 * CC, kvb + d * 2 * CC,
                                   bkv, 2 * CC, CC, 1.f);
            // windowed attention -> battn [T, 128]
            attn_kernel<<<dim3(576, BB, NHEAD), 64>>>(bq, bkv, relb + (size_t)d * 225 * NHEAD,
                                                      battn, shift);
            // proj
            sgemm<1><<<gM1, 256>>>(battn, pW + (size_t)d * CC * CC, pb + d * CC, bproj, CC, CC, 1.f);
            // y = proj @ mW (no bias) -> reuse battn
            sgemm<0><<<gM1, 256>>>(bproj, mW + (size_t)d * CC * CC, nullptr, battn, CC, CC, 1.f);
            // x1 = x + LN(y)
            ln_residual<<<NTOK, 128>>>(battn, bx, n1g + d * CC, n1b + d * CC, bx1);
            // h = gelu(x1 @ f1W + f1b)   [T, 512]
            sgemm<2><<<gM4, 256>>>(bx1, f1W + (size_t)d * CC * HID, f1b + d * HID, bh, HID, CC, 1.f);
            // y2 = h @ f2W + f2b -> reuse bproj
            sgemm<1><<<gM1, 256>>>(bh, f2W + (size_t)d * HID * CC, f2b + d * CC, bproj, CC, HID, 1.f);
            // out_branch = x1 + LN(y2)
            ln_residual<<<NTOK, 128>>>(bproj, bx1, n2g + d * CC, n2b + d * CC, dest);
        }
        // conv([sa; ta]) + bias + PReLU -> new x (NHWC)
        conv3_prelu<<<dim3(WW2 / 16, HH, BB), 128>>>(bsa, bta,
                                                     convW + (size_t)d * CC * 256 * 9,
                                                     convb + d * CC, pa + d * CC, bx);
    }

    nhwc2nchw<<<nblk, 256>>>(bx, (float*)d_out);
}

// round 6
// speedup vs baseline: 2.6598x; 2.6598x over previous
#include <cuda_runtime.h>
#include <math.h>

// ---------------------------------------------------------------------------
// Problem constants
// ---------------------------------------------------------------------------
#define BB 2
#define CC 128
#define HH 192
#define WW2 192
#define NHEAD 4
#define HD 32
#define WS 8
#define NTOK 73728           // B*H*W
#define HID 512
#define EPS_V 1e-5f
#define CONVK 2304           // 9 taps * 2 halves * 128 ic

// ---------------------------------------------------------------------------
// Scratch buffers (device globals; allocation-free)
// ---------------------------------------------------------------------------
__device__ float g_x   [NTOK * CC];
__device__ float g_src [NTOK * CC];
__device__ float g_tgt [NTOK * CC];
__device__ float g_q   [NTOK * CC];
__device__ float g_kv  [NTOK * 2 * CC];
__device__ float g_attn[NTOK * CC];
__device__ float g_proj[NTOK * CC];
__device__ float g_x1  [NTOK * CC];
__device__ float g_h   [NTOK * HID];
__device__ float g_sa  [NTOK * CC];
__device__ float g_ta  [NTOK * CC];
__device__ float g_wg  [CONVK * CC];   // repacked conv weights [K, OC]

// ---------------------------------------------------------------------------
// Layout transforms
// ---------------------------------------------------------------------------
__global__ void nchw2nhwc(const float* __restrict__ in, float* __restrict__ out) {
    size_t i = (size_t)blockIdx.x * blockDim.x + threadIdx.x;
    if (i >= (size_t)NTOK * CC) return;
    int c = i % CC; size_t r = i / CC;
    int w = r % WW2; r /= WW2;
    int h = r % HH;  int b = r / HH;
    out[i] = in[(((size_t)b * CC + c) * HH + h) * WW2 + w];
}

__global__ void nhwc2nchw(const float* __restrict__ in, float* __restrict__ out) {
    size_t i = (size_t)blockIdx.x * blockDim.x + threadIdx.x;
    if (i >= (size_t)NTOK * CC) return;
    int w = i % WW2; size_t r = i / WW2;
    int h = r % HH; r /= HH;
    int c = r % CC; int b = r / CC;
    out[i] = in[(((size_t)b * HH + h) * WW2 + w) * CC + c];
}

// ---------------------------------------------------------------------------
// Conv weight repack: OIHW [128, 256, 3, 3] -> [K=2304, OC=128]
// k = tap*256 + half*128 + ic,  tap = ky*3+kx,  cin = half*128+ic
// ---------------------------------------------------------------------------
__global__ void repack_w(const float* __restrict__ convW, float* __restrict__ wg) {
    int idx = blockIdx.x * blockDim.x + threadIdx.x;
    if (idx >= CONVK * CC) return;
    int oc = idx % CC;
    int k  = idx / CC;
    int tap = k >> 8;            // k / 256
    int cin = k & 255;           // half*128 + ic
    int ky = tap / 3, kx = tap % 3;
    wg[idx] = convW[(((size_t)oc * 256 + cin) * 3 + ky) * 3 + kx];
}

// ---------------------------------------------------------------------------
// SGEMM: C[M,N] = epilogue(A[M,K] @ W[K,N]); M tile = 128 via blockIdx.y.
// EPI: 0 = *scale, 1 = (acc+bias)*scale, 2 = gelu(acc+bias)
// BM=BN=128, BK=16, 256 threads, 8x8 per thread. N,K multiples of 128/16.
// ---------------------------------------------------------------------------
template <int EPI>
__global__ void __launch_bounds__(256)
sgemm(const float* __restrict__ A, const float* __restrict__ W,
      const float* __restrict__ bias, float* __restrict__ C,
      int N, int K, float scale) {
    __shared__ float As[16][128];
    __shared__ float Bs[16][128];
    const int tid = threadIdx.x;
    const int tx = tid % 16, ty = tid / 16;
    const int bx = blockIdx.x, by = blockIdx.y;

    const float* Ablk = A + (size_t)by * 128 * K;
    const float* Wblk = W + (size_t)bx * 128;

    const int arow = tid >> 1;
    const int acol = (tid & 1) * 8;
    const int brow = tid >> 4;
    const int bcol = (tid & 15) * 8;

    float acc[8][8];
#pragma unroll
    for (int i = 0; i < 8; i++)
#pragma unroll
        for (int j = 0; j < 8; j++) acc[i][j] = 0.f;

    for (int k0 = 0; k0 < K; k0 += 16) {
        float4 a0 = *(const float4*)(Ablk + (size_t)arow * K + k0 + acol);
        float4 a1 = *(const float4*)(Ablk + (size_t)arow * K + k0 + acol + 4);
        As[acol + 0][arow] = a0.x; As[acol + 1][arow] = a0.y;
        As[acol + 2][arow] = a0.z; As[acol + 3][arow] = a0.w;
        As[acol + 4][arow] = a1.x; As[acol + 5][arow] = a1.y;
        As[acol + 6][arow] = a1.z; As[acol + 7][arow] = a1.w;
        *(float4*)&Bs[brow][bcol]     = *(const float4*)(Wblk + (size_t)(k0 + brow) * N + bcol);
        *(float4*)&Bs[brow][bcol + 4] = *(const float4*)(Wblk + (size_t)(k0 + brow) * N + bcol + 4);
        __syncthreads();
#pragma unroll
        for (int kk = 0; kk < 16; kk++) {
            float af[8], bf[8];
#pragma unroll
            for (int i = 0; i < 8; i++) af[i] = As[kk][ty * 8 + i];
#pragma unroll
            for (int j = 0; j < 8; j++) bf[j] = Bs[kk][tx * 8 + j];
#pragma unroll
            for (int i = 0; i < 8; i++)
#pragma unroll
                for (int j = 0; j < 8; j++) acc[i][j] += af[i] * bf[j];
        }
        __syncthreads();
    }

#pragma unroll
    for (int i = 0; i < 8; i++) {
        int row = by * 128 + ty * 8 + i;
#pragma unroll
        for (int j = 0; j < 8; j += 4) {
            int col = bx * 128 + tx * 8 + j;
            float4 o;
            float* po = &o.x;
#pragma unroll
            for (int jj = 0; jj < 4; jj++) {
                float v = acc[i][j + jj];
                if (EPI >= 1) v += bias[col + jj];
                v *= scale;
                if (EPI == 2) v = v * normcdff(v);
                po[jj] = v;
            }
            *(float4*)(C + (size_t)row * N + col) = o;
        }
    }
}

// ---------------------------------------------------------------------------
// Conv as implicit GEMM: out[pix, oc] = sum_k A[pix, k] * Wg[k, oc]
// A[pix, k] gathered from sa/ta with the tap shift + boundary predicate.
// K = 2304 (tap-major, then half, then ic). Epilogue: bias + PReLU.
// ---------------------------------------------------------------------------
__global__ void __launch_bounds__(256)
conv_igemm(const float* __restrict__ sa, const float* __restrict__ ta,
           const float* __restrict__ Wg, const float* __restrict__ bias,
           const float* __restrict__ pa, float* __restrict__ out) {
    __shared__ float As[16][128];
    __shared__ float Bs[16][128];
    const int tid = threadIdx.x;
    const int tx = tid % 16, ty = tid / 16;
    const int by = blockIdx.y;

    const int arow = tid >> 1;
    const int acol = (tid & 1) * 8;
    const int brow = tid >> 4;
    const int bcol = (tid & 15) * 8;

    const int pixel = by * 128 + arow;
    const int xcrd = pixel % WW2;
    const int ycrd = (pixel / WW2) % HH;

    float acc[8][8];
#pragma unroll
    for (int i = 0; i < 8; i++)
#pragma unroll
        for (int j = 0; j < 8; j++) acc[i][j] = 0.f;

    for (int k0 = 0; k0 < CONVK; k0 += 16) {
        const int tap  = k0 >> 8;          // constant within 16-wide tile
        const int rem  = k0 & 255;
        const int half = rem >> 7;
        const int ic0  = (rem & 127) + acol;
        const int dy = tap / 3 - 1, dx = tap % 3 - 1;
        const int ys = ycrd + dy, xs = xcrd + dx;
        const bool valid = ((unsigned)ys < HH) && ((unsigned)xs < WW2);
        const float* src = half ? ta : sa;
        const float* ap = src + ((size_t)pixel + dy * WW2 + dx) * CC + ic0;

        float4 a0 = make_float4(0.f, 0.f, 0.f, 0.f), a1 = a0;
        if (valid) { a0 = *(const float4*)ap; a1 = *(const float4*)(ap + 4); }
        As[acol + 0][arow] = a0.x; As[acol + 1][arow] = a0.y;
        As[acol + 2][arow] = a0.z; As[acol + 3][arow] = a0.w;
        As[acol + 4][arow] = a1.x; As[acol + 5][arow] = a1.y;
        As[acol + 6][arow] = a1.z; As[acol + 7][arow] = a1.w;
        *(float4*)&Bs[brow][bcol]     = *(const float4*)(Wg + (size_t)(k0 + brow) * CC + bcol);
        *(float4*)&Bs[brow][bcol + 4] = *(const float4*)(Wg + (size_t)(k0 + brow) * CC + bcol + 4);
        __syncthreads();
#pragma unroll
        for (int kk = 0; kk < 16; kk++) {
            float af[8], bf[8];
#pragma unroll
            for (int i = 0; i < 8; i++) af[i] = As[kk][ty * 8 + i];
#pragma unroll
            for (int j = 0; j < 8; j++) bf[j] = Bs[kk][tx * 8 + j];
#pragma unroll
            for (int i = 0; i < 8; i++)
#pragma unroll
                for (int j = 0; j < 8; j++) acc[i][j] += af[i] * bf[j];
        }
        __syncthreads();
    }

    // bias / prelu params for this thread's 8 columns, loaded once
    float bcol8[8], pcol8[8];
#pragma unroll
    for (int j = 0; j < 8; j++) {
        bcol8[j] = bias[tx * 8 + j];
        pcol8[j] = pa[tx * 8 + j];
    }

#pragma unroll
    for (int i = 0; i < 8; i++) {
        int row = by * 128 + ty * 8 + i;
#pragma unroll
        for (int j = 0; j < 8; j += 4) {
            int col = tx * 8 + j;
            float4 o;
            float* po = &o.x;
#pragma unroll
            for (int jj = 0; jj < 4; jj++) {
                float v = acc[i][j + jj] + bcol8[j + jj];
                if (v < 0.f) v *= pcol8[j + jj];
                po[jj] = v;
            }
            *(float4*)(out + (size_t)row * CC + col) = o;
        }
    }
}

// ---------------------------------------------------------------------------
// Windowed attention. One block = (window, batch, head). 64 threads = 64 query
// tokens. Gathers q/k/v through the shift mapping; scatters output back.
// ---------------------------------------------------------------------------
__device__ __forceinline__ int region_label(int h, int w) {
    int rh = (h < HH - WS) ? 0 : ((h < HH - WS / 2) ? 1 : 2);
    int rw = (w < WW2 - WS) ? 0 : ((w < WW2 - WS / 2) ? 1 : 2);
    return rh * 3 + rw;
}

__global__ void attn_kernel(const float* __restrict__ q, const float* __restrict__ kv,
                            const float* __restrict__ relb, float* __restrict__ out,
                            int shift) {
    const int win = blockIdx.x;
    const int b   = blockIdx.y;
    const int h   = blockIdx.z;
    const int gy = win / (WW2 / WS), gx = win % (WW2 / WS);
    const int t  = threadIdx.x;
    const int ty = t >> 3, tx = t & 7;

    __shared__ float ks[64][36];   // padded; rows 16B-aligned for float4
    __shared__ float vs[64][36];

    const int py = (gy * WS + ty + shift) % HH;
    const int px = (gx * WS + tx + shift) % WW2;
    const size_t pix = ((size_t)b * HH + py) * WW2 + px;

    const float4* kvrow = (const float4*)(kv + pix * (2 * CC) + h * HD);
    const float4* vvrow = (const float4*)(kv + pix * (2 * CC) + CC + h * HD);
#pragma unroll
    for (int d4 = 0; d4 < HD / 4; d4++) {
        *(float4*)&ks[t][d4 * 4] = kvrow[d4];
        *(float4*)&vs[t][d4 * 4] = vvrow[d4];
    }
    float4 qr[HD / 4];
    const float4* qrow = (const float4*)(q + pix * CC + h * HD);
#pragma unroll
    for (int d4 = 0; d4 < HD / 4; d4++) qr[d4] = qrow[d4];
    __syncthreads();

    int li = 0;
    if (shift) li = region_label(gy * WS + ty, gx * WS + tx);

    float s[64];
    float mx = -1e30f;
#pragma unroll
    for (int j = 0; j < 64; j++) {
        float acc = 0.f;
        const float4* kr = (const float4*)&ks[j][0];
#pragma unroll
        for (int d4 = 0; d4 < HD / 4; d4++) {
            float4 kk = kr[d4];
            acc += qr[d4].x * kk.x + qr[d4].y * kk.y + qr[d4].z * kk.z + qr[d4].w * kk.w;
        }
        int jy = j >> 3, jx = j & 7;
        acc += relb[((ty - jy + WS - 1) * (2 * WS - 1) + (tx - jx + WS - 1)) * NHEAD + h];
        if (shift) {
            int lj = region_label(gy * WS + jy, gx * WS + jx);
            if (lj != li) acc -= 100.0f;
        }
        s[j] = acc;
        mx = fmaxf(mx, acc);
    }
    float sum = 0.f;
#pragma unroll
    for (int j = 0; j < 64; j++) { s[j] = expf(s[j] - mx); sum += s[j]; }
    const float inv = 1.0f / sum;

    float4 o4[HD / 4];
#pragma unroll
    for (int d4 = 0; d4 < HD / 4; d4++) o4[d4] = make_float4(0.f, 0.f, 0.f, 0.f);
#pragma unroll
    for (int j = 0; j < 64; j++) {
        const float sj = s[j];
        const float4* vr = (const float4*)&vs[j][0];
#pragma unroll
        for (int d4 = 0; d4 < HD / 4; d4++) {
            float4 vv = vr[d4];
            o4[d4].x += sj * vv.x; o4[d4].y += sj * vv.y;
            o4[d4].z += sj * vv.z; o4[d4].w += sj * vv.w;
        }
    }
    float4* orow = (float4*)(out + pix * CC + h * HD);
#pragma unroll
    for (int d4 = 0; d4 < HD / 4; d4++) {
        float4 o = o4[d4];
        o.x *= inv; o.y *= inv; o.z *= inv; o.w *= inv;
        orow[d4] = o;
    }
}

// ---------------------------------------------------------------------------
// out[t] = shortcut[t] + LayerNorm(y[t]) * g + b
// ---------------------------------------------------------------------------
__global__ void ln_residual(const float* __restrict__ y, const float* __restrict__ sc,
                            const float* __restrict__ g, const float* __restrict__ bta,
                            float* __restrict__ out) {
    const int tk = blockIdx.x;
    const int c  = threadIdx.x;
    __shared__ float red[4];
    float v = y[(size_t)tk * CC + c];

    float s = v;
#pragma unroll
    for (int o = 16; o; o >>= 1) s += __shfl_xor_sync(0xffffffffu, s, o);
    if ((c & 31) == 0) red[c >> 5] = s;
    __syncthreads();
    float mu = (red[0] + red[1] + red[2] + red[3]) * (1.f / CC);

    float dv = v - mu;
    float s2 = dv * dv;
#pragma unroll
    for (int o = 16; o; o >>= 1) s2 += __shfl_xor_sync(0xffffffffu, s2, o);
    __syncthreads();
    if ((c & 31) == 0) red[c >> 5] = s2;
    __syncthreads();
    float var = (red[0] + red[1] + red[2] + red[3]) * (1.f / CC);

    out[(size_t)tk * CC + c] = sc[(size_t)tk * CC + c] + dv * rsqrtf(var + EPS_V) * g[c] + bta[c];
}

// ---------------------------------------------------------------------------
// Host driver (graph-capturable: launches only)
// ---------------------------------------------------------------------------
template <typename T>
static float* sym(const T& s) {
    void* p = nullptr;
    cudaGetSymbolAddress(&p, s);
    return (float*)p;
}

extern "C" void kernel_launch(void* const* d_in, const int* in_sizes, int n_in,
                              void* d_out, int out_size) {
    const float* x      = (const float*)d_in[0];
    const float* source = (const float*)d_in[1];
    const float* target = (const float*)d_in[2];
    const float* qW     = (const float*)d_in[3];
    const float* qb     = (const float*)d_in[4];
    const float* kvW    = (const float*)d_in[5];
    const float* kvb    = (const float*)d_in[6];
    const float* pW     = (const float*)d_in[7];
    const float* pb     = (const float*)d_in[8];
    const float* relb   = (const float*)d_in[9];
    const float* mW     = (const float*)d_in[10];
    const float* n1g    = (const float*)d_in[11];
    const float* n1b    = (const float*)d_in[12];
    const float* f1W    = (const float*)d_in[13];
    const float* f1b    = (const float*)d_in[14];
    const float* f2W    = (const float*)d_in[15];
    const float* f2b    = (const float*)d_in[16];
    const float* n2g    = (const float*)d_in[17];
    const float* n2b    = (const float*)d_in[18];
    const float* convW  = (const float*)d_in[19];
    const float* convb  = (const float*)d_in[20];
    const float* pa     = (const float*)d_in[21];

    float* bx    = sym(g_x);
    float* bsrc  = sym(g_src);
    float* btgt  = sym(g_tgt);
    float* bq    = sym(g_q);
    float* bkv   = sym(g_kv);
    float* battn = sym(g_attn);
    float* bproj = sym(g_proj);
    float* bx1   = sym(g_x1);
    float* bh    = sym(g_h);
    float* bsa   = sym(g_sa);
    float* bta   = sym(g_ta);
    float* bwg   = sym(g_wg);

    const float SCALE = 0.1767766952966369f;   // 32^-0.5
    const int nblk = (NTOK * CC + 255) / 256;
    const dim3 gM1(1, NTOK / 128), gM2(2, NTOK / 128), gM4(4, NTOK / 128);

    nchw2nhwc<<<nblk, 256>>>(x, bx);
    nchw2nhwc<<<nblk, 256>>>(source, bsrc);
    nchw2nhwc<<<nblk, 256>>>(target, btgt);

    for (int d = 0; d < 2; d++) {
        const int shift = (d % 2) ? (WS / 2) : 0;
        // q = (x @ qW + qb) * scale   (shared by both branches)
        sgemm<1><<<gM1, 256>>>(bx, qW + (size_t)d * CC * CC, qb + d * CC, bq, CC, CC, SCALE);

        for (int br = 0; br < 2; br++) {
            const float* feat = br ? btgt : bsrc;
            float* dest = br ? bta : bsa;
            // kv = feat @ kvW + kvb   [T, 256]
            sgemm<1><<<gM2, 256>>>(feat, kvW + (size_t)d * CC * 2 * CC, kvb + d * 2 * CC,
                                   bkv, 2 * CC, CC, 1.f);
            // windowed attention -> battn [T, 128]
            attn_kernel<<<dim3(576, BB, NHEAD), 64>>>(bq, bkv, relb + (size_t)d * 225 * NHEAD,
                                                      battn, shift);
            // proj
            sgemm<1><<<gM1, 256>>>(battn, pW + (size_t)d * CC * CC, pb + d * CC, bproj, CC, CC, 1.f);
            // y = proj @ mW (no bias)
            sgemm<0><<<gM1, 256>>>(bproj, mW + (size_t)d * CC * CC, nullptr, battn, CC, CC, 1.f);
            // x1 = x + LN(y)
            ln_residual<<<NTOK, 128>>>(battn, bx, n1g + d * CC, n1b + d * CC, bx1);
            // h = gelu(x1 @ f1W + f1b)
            sgemm<2><<<gM4, 256>>>(bx1, f1W + (size_t)d * CC * HID, f1b + d * HID, bh, HID, CC, 1.f);
            // y2 = h @ f2W + f2b
            sgemm<1><<<gM1, 256>>>(bh, f2W + (size_t)d * HID * CC, f2b + d * CC, bproj, CC, HID, 1.f);
            // out_branch = x1 + LN(y2)
            ln_residual<<<NTOK, 128>>>(bproj, bx1, n2g + d * CC, n2b + d * CC, dest);
        }
        // conv([sa; ta]) + bias + PReLU -> new x (NHWC), as implicit GEMM
        repack_w<<<(CONVK * CC + 255) / 256, 256>>>(convW + (size_t)d * CC * 256 * 9, bwg);
        conv_igemm<<<dim3(1, NTOK / 128), 256>>>(bsa, bta, bwg, convb + d * CC, pa + d * CC, bx);
    }

    nhwc2nchw<<<nblk, 256>>>(bx, (float*)d_out);
}

// round 7
// speedup vs baseline: 3.2579x; 1.2249x over previous
#include <cuda_runtime.h>
#include <math.h>

// ---------------------------------------------------------------------------
// Problem constants
// ---------------------------------------------------------------------------
#define BB 2
#define CC 128
#define HH 192
#define WW2 192
#define NHEAD 4
#define HD 32
#define WS 8
#define NTOK 73728           // B*H*W
#define HID 512
#define EPS_V 1e-5f
#define CONVK 2304           // 9 taps * 2 halves * 128 ic

// ---------------------------------------------------------------------------
// Scratch buffers (device globals; allocation-free)
// ---------------------------------------------------------------------------
__device__ float g_x   [NTOK * CC];
__device__ float g_src [NTOK * CC];
__device__ float g_tgt [NTOK * CC];
__device__ float g_q   [NTOK * CC];
__device__ float g_kv  [NTOK * 2 * CC];
__device__ float g_attn[NTOK * CC];
__device__ float g_x1  [NTOK * CC];
__device__ float g_h   [NTOK * HID];
__device__ float g_sa  [NTOK * CC];
__device__ float g_ta  [NTOK * CC];
__device__ float g_wg  [CONVK * CC];   // repacked conv weights [K, OC]
__device__ float g_pwm [CC * CC];      // fused pW @ mW
__device__ float g_pbm [CC];           // fused pb @ mW

// ---------------------------------------------------------------------------
// Layout transforms
// ---------------------------------------------------------------------------
__global__ void nchw2nhwc(const float* __restrict__ in, float* __restrict__ out) {
    size_t i = (size_t)blockIdx.x * blockDim.x + threadIdx.x;
    if (i >= (size_t)NTOK * CC) return;
    int c = i % CC; size_t r = i / CC;
    int w = r % WW2; r /= WW2;
    int h = r % HH;  int b = r / HH;
    out[i] = in[(((size_t)b * CC + c) * HH + h) * WW2 + w];
}

__global__ void nhwc2nchw(const float* __restrict__ in, float* __restrict__ out) {
    size_t i = (size_t)blockIdx.x * blockDim.x + threadIdx.x;
    if (i >= (size_t)NTOK * CC) return;
    int w = i % WW2; size_t r = i / WW2;
    int h = r % HH; r /= HH;
    int c = r % CC; int b = r / CC;
    out[i] = in[(((size_t)b * HH + h) * WW2 + w) * CC + c];
}

// ---------------------------------------------------------------------------
// Conv weight repack: OIHW [128, 256, 3, 3] -> [K=2304, OC=128]
// ---------------------------------------------------------------------------
__global__ void repack_w(const float* __restrict__ convW, float* __restrict__ wg) {
    int idx = blockIdx.x * blockDim.x + threadIdx.x;
    if (idx >= CONVK * CC) return;
    int oc = idx % CC;
    int k  = idx / CC;
    int tap = k >> 8;
    int cin = k & 255;
    int ky = tap / 3, kx = tap % 3;
    wg[idx] = convW[(((size_t)oc * 256 + cin) * 3 + ky) * 3 + kx];
}

// pbm[n] = sum_k pb[k] * mW[k,n]
__global__ void fuse_bias(const float* __restrict__ pb, const float* __restrict__ mW,
                          float* __restrict__ pbm) {
    int n = threadIdx.x;
    float s = 0.f;
    for (int k = 0; k < CC; k++) s += pb[k] * mW[k * CC + n];
    pbm[n] = s;
}

// ---------------------------------------------------------------------------
// Shared GEMM building blocks: BM=BN=128, BK=16, 256 thr, 8 rows x (4+4) cols.
// Double-buffered smem, conflict-free B-fragment loads (two float4 groups).
// ---------------------------------------------------------------------------
#define GEMM_COMPUTE(As, Bs)                                                   \
    {                                                                          \
        _Pragma("unroll")                                                      \
        for (int kk = 0; kk < 16; kk++) {                                      \
            float4 af0 = *(const float4*)&As[kk][ty * 8];                      \
            float4 af1 = *(const float4*)&As[kk][ty * 8 + 4];                  \
            float4 bf0 = *(const float4*)&Bs[kk][tx * 4];                      \
            float4 bf1 = *(const float4*)&Bs[kk][64 + tx * 4];                 \
            float af[8] = {af0.x, af0.y, af0.z, af0.w, af1.x, af1.y, af1.z, af1.w}; \
            float bf[8] = {bf0.x, bf0.y, bf0.z, bf0.w, bf1.x, bf1.y, bf1.z, bf1.w}; \
            _Pragma("unroll")                                                  \
            for (int i = 0; i < 8; i++)                                        \
                _Pragma("unroll")                                              \
                for (int j = 0; j < 8; j++) acc[i][j] += af[i] * bf[j];        \
        }                                                                      \
    }

#define GEMM_STORE_SMEM(buf, a0, a1, b0, b1)                                   \
    {                                                                          \
        As[buf][acol + 0][arow] = a0.x; As[buf][acol + 1][arow] = a0.y;        \
        As[buf][acol + 2][arow] = a0.z; As[buf][acol + 3][arow] = a0.w;        \
        As[buf][acol + 4][arow] = a1.x; As[buf][acol + 5][arow] = a1.y;        \
        As[buf][acol + 6][arow] = a1.z; As[buf][acol + 7][arow] = a1.w;        \
        *(float4*)&Bs[buf][brow][bcol]     = b0;                               \
        *(float4*)&Bs[buf][brow][bcol + 4] = b1;                               \
    }

// ---------------------------------------------------------------------------
// SGEMM: C = epilogue(A[M,K] @ W[K,N]); EPI: 0:*scale 1:(+bias)*scale 2:gelu(+bias)
// ---------------------------------------------------------------------------
template <int EPI>
__global__ void __launch_bounds__(256, 2)
sgemm(const float* __restrict__ A, const float* __restrict__ W,
      const float* __restrict__ bias, float* __restrict__ C,
      int N, int K, float scale) {
    __shared__ float As[2][16][128];
    __shared__ float Bs[2][16][128];
    const int tid = threadIdx.x;
    const int tx = tid % 16, ty = tid / 16;
    const int bx = blockIdx.x, by = blockIdx.y;

    const float* Ablk = A + (size_t)by * 128 * K;
    const float* Wblk = W + (size_t)bx * 128;

    const int arow = tid >> 1;
    const int acol = (tid & 1) * 8;
    const int brow = tid >> 4;
    const int bcol = (tid & 15) * 8;

    float acc[8][8];
#pragma unroll
    for (int i = 0; i < 8; i++)
#pragma unroll
        for (int j = 0; j < 8; j++) acc[i][j] = 0.f;

    const int nc = K / 16;
    float4 ra0 = *(const float4*)(Ablk + (size_t)arow * K + acol);
    float4 ra1 = *(const float4*)(Ablk + (size_t)arow * K + acol + 4);
    float4 rb0 = *(const float4*)(Wblk + (size_t)brow * N + bcol);
    float4 rb1 = *(const float4*)(Wblk + (size_t)brow * N + bcol + 4);
    GEMM_STORE_SMEM(0, ra0, ra1, rb0, rb1);
    __syncthreads();

    for (int c = 0; c < nc; c++) {
        const int cur = c & 1;
        if (c + 1 < nc) {
            int k0 = (c + 1) * 16;
            ra0 = *(const float4*)(Ablk + (size_t)arow * K + k0 + acol);
            ra1 = *(const float4*)(Ablk + (size_t)arow * K + k0 + acol + 4);
            rb0 = *(const float4*)(Wblk + (size_t)(k0 + brow) * N + bcol);
            rb1 = *(const float4*)(Wblk + (size_t)(k0 + brow) * N + bcol + 4);
        }
        GEMM_COMPUTE(As[cur], Bs[cur]);
        if (c + 1 < nc) {
            GEMM_STORE_SMEM(cur ^ 1, ra0, ra1, rb0, rb1);
            __syncthreads();
        }
    }

    const int c0 = bx * 128 + tx * 4;
    const int c1 = bx * 128 + 64 + tx * 4;
#pragma unroll
    for (int i = 0; i < 8; i++) {
        int row = by * 128 + ty * 8 + i;
        float o[8];
#pragma unroll
        for (int j = 0; j < 8; j++) {
            float v = acc[i][j];
            if (EPI >= 1) v += bias[(j < 4 ? c0 : c1 - 4) + j];
            v *= scale;
            if (EPI == 2) v = v * normcdff(v);
            o[j] = v;
        }
        *(float4*)(C + (size_t)row * N + c0) = make_float4(o[0], o[1], o[2], o[3]);
        *(float4*)(C + (size_t)row * N + c1) = make_float4(o[4], o[5], o[6], o[7]);
    }
}

// ---------------------------------------------------------------------------
// SGEMM + fused (bias, LayerNorm over N=128, residual):
//   out = sc + LN(A@W + bias) * g + beta        (N fixed = 128, grid.x = 1)
// ---------------------------------------------------------------------------
__global__ void __launch_bounds__(256, 2)
sgemm_ln(const float* __restrict__ A, const float* __restrict__ W,
         const float* __restrict__ bias, const float* __restrict__ sc,
         const float* __restrict__ g, const float* __restrict__ beta,
         float* __restrict__ out, int K) {
    __shared__ float As[2][16][128];
    __shared__ float Bs[2][16][128];
    const int tid = threadIdx.x;
    const int tx = tid % 16, ty = tid / 16;
    const int by = blockIdx.y;

    const float* Ablk = A + (size_t)by * 128 * K;

    const int arow = tid >> 1;
    const int acol = (tid & 1) * 8;
    const int brow = tid >> 4;
    const int bcol = (tid & 15) * 8;

    float acc[8][8];
#pragma unroll
    for (int i = 0; i < 8; i++)
#pragma unroll
        for (int j = 0; j < 8; j++) acc[i][j] = 0.f;

    const int nc = K / 16;
    float4 ra0 = *(const float4*)(Ablk + (size_t)arow * K + acol);
    float4 ra1 = *(const float4*)(Ablk + (size_t)arow * K + acol + 4);
    float4 rb0 = *(const float4*)(W + (size_t)brow * 128 + bcol);
    float4 rb1 = *(const float4*)(W + (size_t)brow * 128 + bcol + 4);
    GEMM_STORE_SMEM(0, ra0, ra1, rb0, rb1);
    __syncthreads();

    for (int c = 0; c < nc; c++) {
        const int cur = c & 1;
        if (c + 1 < nc) {
            int k0 = (c + 1) * 16;
            ra0 = *(const float4*)(Ablk + (size_t)arow * K + k0 + acol);
            ra1 = *(const float4*)(Ablk + (size_t)arow * K + k0 + acol + 4);
            rb0 = *(const float4*)(W + (size_t)(k0 + brow) * 128 + bcol);
            rb1 = *(const float4*)(W + (size_t)(k0 + brow) * 128 + bcol + 4);
        }
        GEMM_COMPUTE(As[cur], Bs[cur]);
        if (c + 1 < nc) {
            GEMM_STORE_SMEM(cur ^ 1, ra0, ra1, rb0, rb1);
            __syncthreads();
        }
    }

    // epilogue: per-row LN across 128 cols (reduce over 16 tx lanes = half warp)
    const int c0 = tx * 4, c1 = 64 + tx * 4;
    float bj[8], gj[8], btj[8];
#pragma unroll
    for (int j = 0; j < 4; j++) {
        bj[j] = bias[c0 + j];      bj[j + 4] = bias[c1 + j];
        gj[j] = g[c0 + j];         gj[j + 4] = g[c1 + j];
        btj[j] = beta[c0 + j];     btj[j + 4] = beta[c1 + j];
    }

#pragma unroll
    for (int i = 0; i < 8; i++) {
        const int row = by * 128 + ty * 8 + i;
        float v[8], s1 = 0.f, s2 = 0.f;
#pragma unroll
        for (int j = 0; j < 8; j++) {
            v[j] = acc[i][j] + bj[j];
            s1 += v[j];
            s2 += v[j] * v[j];
        }
#pragma unroll
        for (int m = 1; m < 16; m <<= 1) {
            s1 += __shfl_xor_sync(0xffffffffu, s1, m);
            s2 += __shfl_xor_sync(0xffffffffu, s2, m);
        }
        const float mu = s1 * (1.f / 128.f);
        const float var = s2 * (1.f / 128.f) - mu * mu;
        const float rs = rsqrtf(var + EPS_V);

        float4 sc0 = *(const float4*)(sc + (size_t)row * 128 + c0);
        float4 sc1 = *(const float4*)(sc + (size_t)row * 128 + c1);
        const float* ps = &sc0.x;
        float o[8];
#pragma unroll
        for (int j = 0; j < 4; j++) o[j] = ps[j] + (v[j] - mu) * rs * gj[j] + btj[j];
        ps = &sc1.x;
#pragma unroll
        for (int j = 0; j < 4; j++) o[j + 4] = ps[j] + (v[j + 4] - mu) * rs * gj[j + 4] + btj[j + 4];
        *(float4*)(out + (size_t)row * 128 + c0) = make_float4(o[0], o[1], o[2], o[3]);
        *(float4*)(out + (size_t)row * 128 + c1) = make_float4(o[4], o[5], o[6], o[7]);
    }
}

// ---------------------------------------------------------------------------
// Conv as implicit GEMM (K=2304), double-buffered; epilogue bias + PReLU.
// ---------------------------------------------------------------------------
__global__ void __launch_bounds__(256, 2)
conv_igemm(const float* __restrict__ sa, const float* __restrict__ ta,
           const float* __restrict__ Wg, const float* __restrict__ bias,
           const float* __restrict__ pa, float* __restrict__ out) {
    __shared__ float As[2][16][128];
    __shared__ float Bs[2][16][128];
    const int tid = threadIdx.x;
    const int tx = tid % 16, ty = tid / 16;
    const int by = blockIdx.y;

    const int arow = tid >> 1;
    const int acol = (tid & 1) * 8;
    const int brow = tid >> 4;
    const int bcol = (tid & 15) * 8;

    const int pixel = by * 128 + arow;
    const int xcrd = pixel % WW2;
    const int ycrd = (pixel / WW2) % HH;

    auto loadA = [&](int c, float4& a0, float4& a1) {
        const int k0 = c * 16;
        const int tap  = k0 >> 8;
        const int rem  = k0 & 255;
        const int half = rem >> 7;
        const int ic0  = (rem & 127) + acol;
        const int dy = tap / 3 - 1, dx = tap % 3 - 1;
        const int ys = ycrd + dy, xs = xcrd + dx;
        const bool valid = ((unsigned)ys < HH) && ((unsigned)xs < WW2);
        const float* src = half ? ta : sa;
        const float* ap = src + ((size_t)pixel + dy * WW2 + dx) * CC + ic0;
        a0 = make_float4(0.f, 0.f, 0.f, 0.f); a1 = a0;
        if (valid) { a0 = *(const float4*)ap; a1 = *(const float4*)(ap + 4); }
    };
    auto loadB = [&](int c, float4& b0, float4& b1) {
        const int k0 = c * 16;
        b0 = *(const float4*)(Wg + (size_t)(k0 + brow) * CC + bcol);
        b1 = *(const float4*)(Wg + (size_t)(k0 + brow) * CC + bcol + 4);
    };

    float acc[8][8];
#pragma unroll
    for (int i = 0; i < 8; i++)
#pragma unroll
        for (int j = 0; j < 8; j++) acc[i][j] = 0.f;

    const int nc = CONVK / 16;   // 144
    float4 ra0, ra1, rb0, rb1;
    loadA(0, ra0, ra1); loadB(0, rb0, rb1);
    GEMM_STORE_SMEM(0, ra0, ra1, rb0, rb1);
    __syncthreads();

    for (int c = 0; c < nc; c++) {
        const int cur = c & 1;
        if (c + 1 < nc) { loadA(c + 1, ra0, ra1); loadB(c + 1, rb0, rb1); }
        GEMM_COMPUTE(As[cur], Bs[cur]);
        if (c + 1 < nc) {
            GEMM_STORE_SMEM(cur ^ 1, ra0, ra1, rb0, rb1);
            __syncthreads();
        }
    }

    const int c0 = tx * 4, c1 = 64 + tx * 4;
    float bcol8[8], pcol8[8];
#pragma unroll
    for (int j = 0; j < 4; j++) {
        bcol8[j] = bias[c0 + j]; bcol8[j + 4] = bias[c1 + j];
        pcol8[j] = pa[c0 + j];   pcol8[j + 4] = pa[c1 + j];
    }

#pragma unroll
    for (int i = 0; i < 8; i++) {
        int row = by * 128 + ty * 8 + i;
        float o[8];
#pragma unroll
        for (int j = 0; j < 8; j++) {
            float v = acc[i][j] + bcol8[j];
            if (v < 0.f) v *= pcol8[j];
            o[j] = v;
        }
        *(float4*)(out + (size_t)row * CC + c0) = make_float4(o[0], o[1], o[2], o[3]);
        *(float4*)(out + (size_t)row * CC + c1) = make_float4(o[4], o[5], o[6], o[7]);
    }
}

// ---------------------------------------------------------------------------
// Windowed attention (unchanged from R5).
// ---------------------------------------------------------------------------
__device__ __forceinline__ int region_label(int h, int w) {
    int rh = (h < HH - WS) ? 0 : ((h < HH - WS / 2) ? 1 : 2);
    int rw = (w < WW2 - WS) ? 0 : ((w < WW2 - WS / 2) ? 1 : 2);
    return rh * 3 + rw;
}

__global__ void attn_kernel(const float* __restrict__ q, const float* __restrict__ kv,
                            const float* __restrict__ relb, float* __restrict__ out,
                            int shift) {
    const int win = blockIdx.x;
    const int b   = blockIdx.y;
    const int h   = blockIdx.z;
    const int gy = win / (WW2 / WS), gx = win % (WW2 / WS);
    const int t  = threadIdx.x;
    const int ty = t >> 3, tx = t & 7;

    __shared__ float ks[64][36];
    __shared__ float vs[64][36];

    const int py = (gy * WS + ty + shift) % HH;
    const int px = (gx * WS + tx + shift) % WW2;
    const size_t pix = ((size_t)b * HH + py) * WW2 + px;

    const float4* kvrow = (const float4*)(kv + pix * (2 * CC) + h * HD);
    const float4* vvrow = (const float4*)(kv + pix * (2 * CC) + CC + h * HD);
#pragma unroll
    for (int d4 = 0; d4 < HD / 4; d4++) {
        *(float4*)&ks[t][d4 * 4] = kvrow[d4];
        *(float4*)&vs[t][d4 * 4] = vvrow[d4];
    }
    float4 qr[HD / 4];
    const float4* qrow = (const float4*)(q + pix * CC + h * HD);
#pragma unroll
    for (int d4 = 0; d4 < HD / 4; d4++) qr[d4] = qrow[d4];
    __syncthreads();

    int li = 0;
    if (shift) li = region_label(gy * WS + ty, gx * WS + tx);

    float s[64];
    float mx = -1e30f;
#pragma unroll
    for (int j = 0; j < 64; j++) {
        float acc = 0.f;
        const float4* kr = (const float4*)&ks[j][0];
#pragma unroll
        for (int d4 = 0; d4 < HD / 4; d4++) {
            float4 kk = kr[d4];
            acc += qr[d4].x * kk.x + qr[d4].y * kk.y + qr[d4].z * kk.z + qr[d4].w * kk.w;
        }
        int jy = j >> 3, jx = j & 7;
        acc += relb[((ty - jy + WS - 1) * (2 * WS - 1) + (tx - jx + WS - 1)) * NHEAD + h];
        if (shift) {
            int lj = region_label(gy * WS + jy, gx * WS + jx);
            if (lj != li) acc -= 100.0f;
        }
        s[j] = acc;
        mx = fmaxf(mx, acc);
    }
    float sum = 0.f;
#pragma unroll
    for (int j = 0; j < 64; j++) { s[j] = expf(s[j] - mx); sum += s[j]; }
    const float inv = 1.0f / sum;

    float4 o4[HD / 4];
#pragma unroll
    for (int d4 = 0; d4 < HD / 4; d4++) o4[d4] = make_float4(0.f, 0.f, 0.f, 0.f);
#pragma unroll
    for (int j = 0; j < 64; j++) {
        const float sj = s[j];
        const float4* vr = (const float4*)&vs[j][0];
#pragma unroll
        for (int d4 = 0; d4 < HD / 4; d4++) {
            float4 vv = vr[d4];
            o4[d4].x += sj * vv.x; o4[d4].y += sj * vv.y;
            o4[d4].z += sj * vv.z; o4[d4].w += sj * vv.w;
        }
    }
    float4* orow = (float4*)(out + pix * CC + h * HD);
#pragma unroll
    for (int d4 = 0; d4 < HD / 4; d4++) {
        float4 o = o4[d4];
        o.x *= inv; o.y *= inv; o.z *= inv; o.w *= inv;
        orow[d4] = o;
    }
}

// ---------------------------------------------------------------------------
// Host driver (graph-capturable: launches only)
// ---------------------------------------------------------------------------
template <typename T>
static float* sym(const T& s) {
    void* p = nullptr;
    cudaGetSymbolAddress(&p, s);
    return (float*)p;
}

extern "C" void kernel_launch(void* const* d_in, const int* in_sizes, int n_in,
                              void* d_out, int out_size) {
    const float* x      = (const float*)d_in[0];
    const float* source = (const float*)d_in[1];
    const float* target = (const float*)d_in[2];
    const float* qW     = (const float*)d_in[3];
    const float* qb     = (const float*)d_in[4];
    const float* kvW    = (const float*)d_in[5];
    const float* kvb    = (const float*)d_in[6];
    const float* pW     = (const float*)d_in[7];
    const float* pb     = (const float*)d_in[8];
    const float* relb   = (const float*)d_in[9];
    const float* mW     = (const float*)d_in[10];
    const float* n1g    = (const float*)d_in[11];
    const float* n1b    = (const float*)d_in[12];
    const float* f1W    = (const float*)d_in[13];
    const float* f1b    = (const float*)d_in[14];
    const float* f2W    = (const float*)d_in[15];
    const float* f2b    = (const float*)d_in[16];
    const float* n2g    = (const float*)d_in[17];
    const float* n2b    = (const float*)d_in[18];
    const float* convW  = (const float*)d_in[19];
    const float* convb  = (const float*)d_in[20];
    const float* pa     = (const float*)d_in[21];

    float* bx    = sym(g_x);
    float* bsrc  = sym(g_src);
    float* btgt  = sym(g_tgt);
    float* bq    = sym(g_q);
    float* bkv   = sym(g_kv);
    float* battn = sym(g_attn);
    float* bx1   = sym(g_x1);
    float* bh    = sym(g_h);
    float* bsa   = sym(g_sa);
    float* bta   = sym(g_ta);
    float* bwg   = sym(g_wg);
    float* bpwm  = sym(g_pwm);
    float* bpbm  = sym(g_pbm);

    const float SCALE = 0.1767766952966369f;   // 32^-0.5
    const int nblk = (NTOK * CC + 255) / 256;
    const dim3 gM1(1, NTOK / 128), gM2(2, NTOK / 128), gM4(4, NTOK / 128);

    nchw2nhwc<<<nblk, 256>>>(x, bx);
    nchw2nhwc<<<nblk, 256>>>(source, bsrc);
    nchw2nhwc<<<nblk, 256>>>(target, btgt);

    for (int d = 0; d < 2; d++) {
        const int shift = (d % 2) ? (WS / 2) : 0;

        // fused projection weights: pWm = pW @ mW, pbm = pb @ mW
        sgemm<0><<<dim3(1, 1), 256>>>(pW + (size_t)d * CC * CC, mW + (size_t)d * CC * CC,
                                      nullptr, bpwm, CC, CC, 1.f);
        fuse_bias<<<1, CC>>>(pb + d * CC, mW + (size_t)d * CC * CC, bpbm);

        // q = (x @ qW + qb) * scale   (shared by both branches)
        sgemm<1><<<gM1, 256>>>(bx, qW + (size_t)d * CC * CC, qb + d * CC, bq, CC, CC, SCALE);

        for (int br = 0; br < 2; br++) {
            const float* feat = br ? btgt : bsrc;
            float* dest = br ? bta : bsa;
            // kv = feat @ kvW + kvb   [T, 256]
            sgemm<1><<<gM2, 256>>>(feat, kvW + (size_t)d * CC * 2 * CC, kvb + d * 2 * CC,
                                   bkv, 2 * CC, CC, 1.f);
            // windowed attention -> battn [T, 128]
            attn_kernel<<<dim3(576, BB, NHEAD), 64>>>(bq, bkv, relb + (size_t)d * 225 * NHEAD,
                                                      battn, shift);
            // x1 = x + LN(attn @ pWm + pbm)   (proj+mW fused; LN fused in epilogue)
            sgemm_ln<<<gM1, 256>>>(battn, bpwm, bpbm, bx, n1g + d * CC, n1b + d * CC, bx1, CC);
            // h = gelu(x1 @ f1W + f1b)
            sgemm<2><<<gM4, 256>>>(bx1, f1W + (size_t)d * CC * HID, f1b + d * HID, bh, HID, CC, 1.f);
            // dest = x1 + LN(h @ f2W + f2b)
            sgemm_ln<<<gM1, 256>>>(bh, f2W + (size_t)d * HID * CC, f2b + d * CC, bx1,
                                   n2g + d * CC, n2b + d * CC, dest, HID);
        }
        // conv([sa; ta]) + bias + PReLU -> new x (NHWC), as implicit GEMM
        repack_w<<<(CONVK * CC + 255) / 256, 256>>>(convW + (size_t)d * CC * 256 * 9, bwg);
        conv_igemm<<<dim3(1, NTOK / 128), 256>>>(bsa, bta, bwg, convb + d * CC, pa + d * CC, bx);
    }

    nhwc2nchw<<<nblk, 256>>>(bx, (float*)d_out);
}

// round 10
// speedup vs baseline: 5.2887x; 1.6234x over previous
#include <cuda_runtime.h>
#include <math.h>

// ---------------------------------------------------------------------------
// Problem constants
// ---------------------------------------------------------------------------
#define BB 2
#define CC 128
#define HH 192
#define WW2 192
#define NHEAD 4
#define HD 32
#define WS 8
#define NTOK 73728           // B*H*W
#define HID 512
#define EPS_V 1e-5f
#define CONVK 2304           // 9 taps * 2 halves * 128 ic
#define SMS 136              // smem row stride (tg*8+g bank mapping -> conflict-free)

// ---------------------------------------------------------------------------
// Scratch buffers (device globals; allocation-free)
// ---------------------------------------------------------------------------
__device__ float g_x   [NTOK * CC];
__device__ float g_src [NTOK * CC];
__device__ float g_tgt [NTOK * CC];
__device__ float g_q   [NTOK * CC];
__device__ float g_kv  [NTOK * 2 * CC];
__device__ float g_attn[NTOK * CC];
__device__ float g_x1  [NTOK * CC];
__device__ float g_h   [NTOK * HID];
__device__ float g_sa  [NTOK * CC];
__device__ float g_ta  [NTOK * CC];
__device__ float g_wg  [CONVK * CC];   // repacked conv weights [K, OC]
__device__ float g_pwm [CC * CC];      // fused pW @ mW
__device__ float g_pbm [CC];           // fused pb @ mW

// ---------------------------------------------------------------------------
// tf32 helpers
// ---------------------------------------------------------------------------
__device__ __forceinline__ float to_tf32(float x) {
    float r;
    asm("cvt.rna.tf32.f32 %0, %1;" : "=f"(r) : "f"(x));
    return r;
}
__device__ __forceinline__ void cvt4(float4& v) {
    v.x = to_tf32(v.x); v.y = to_tf32(v.y); v.z = to_tf32(v.z); v.w = to_tf32(v.w);
}
__device__ __forceinline__ void mma8(float* d, const float* a, const float* b) {
    asm volatile(
        "mma.sync.aligned.m16n8k8.row.col.f32.tf32.tf32.f32 "
        "{%0,%1,%2,%3}, {%4,%5,%6,%7}, {%8,%9}, {%0,%1,%2,%3};\n"
        : "+f"(d[0]), "+f"(d[1]), "+f"(d[2]), "+f"(d[3])
        : "r"(__float_as_uint(a[0])), "r"(__float_as_uint(a[1])),
          "r"(__float_as_uint(a[2])), "r"(__float_as_uint(a[3])),
          "r"(__float_as_uint(b[0])), "r"(__float_as_uint(b[1])));
}

// ---------------------------------------------------------------------------
// Layout transforms
// ---------------------------------------------------------------------------
__global__ void nchw2nhwc(const float* __restrict__ in, float* __restrict__ out) {
    size_t i = (size_t)blockIdx.x * blockDim.x + threadIdx.x;
    if (i >= (size_t)NTOK * CC) return;
    int c = i % CC; size_t r = i / CC;
    int w = r % WW2; r /= WW2;
    int h = r % HH;  int b = r / HH;
    out[i] = in[(((size_t)b * CC + c) * HH + h) * WW2 + w];
}

__global__ void nhwc2nchw(const float* __restrict__ in, float* __restrict__ out) {
    size_t i = (size_t)blockIdx.x * blockDim.x + threadIdx.x;
    if (i >= (size_t)NTOK * CC) return;
    int w = i % WW2; size_t r = i / WW2;
    int h = r % HH; r /= HH;
    int c = r % CC; int b = r / CC;
    out[i] = in[(((size_t)b * HH + h) * WW2 + w) * CC + c];
}

// ---------------------------------------------------------------------------
// Conv weight repack: OIHW [128, 256, 3, 3] -> [K=2304, OC=128]
// ---------------------------------------------------------------------------
__global__ void repack_w(const float* __restrict__ convW, float* __restrict__ wg) {
    int idx = blockIdx.x * blockDim.x + threadIdx.x;
    if (idx >= CONVK * CC) return;
    int oc = idx % CC;
    int k  = idx / CC;
    int tap = k >> 8;
    int cin = k & 255;
    int ky = tap / 3, kx = tap % 3;
    wg[idx] = convW[(((size_t)oc * 256 + cin) * 3 + ky) * 3 + kx];
}

// exact fp32: pwm = pW @ mW (grid=128 row-blocks), pbm = pb @ mW (block 128)
__global__ void fuse_pwm(const float* __restrict__ pW, const float* __restrict__ mW,
                         float* __restrict__ pwm) {
    __shared__ float arow[CC];
    const int i = blockIdx.x, j = threadIdx.x;
    arow[j] = pW[i * CC + j];
    __syncthreads();
    float s = 0.f;
    for (int k = 0; k < CC; k++) s += arow[k] * mW[k * CC + j];
    pwm[i * CC + j] = s;
}
__global__ void fuse_bias(const float* __restrict__ pb, const float* __restrict__ mW,
                          float* __restrict__ pbm) {
    int n = threadIdx.x;
    float s = 0.f;
    for (int k = 0; k < CC; k++) s += pb[k] * mW[k * CC + n];
    pbm[n] = s;
}

// ---------------------------------------------------------------------------
// tf32 tensor-core GEMM: C = epi(A[M,K] @ W[K,N]); BM=BN=128, BK=16, 256 thr.
// 8 warps as 2(m) x 4(n); warp tile 64x32 via m16n8k8 frags.
// EPI: 0:*scale  1:(+bias)*scale  2:gelu(+bias)
// ---------------------------------------------------------------------------
template <int EPI>
__global__ void __launch_bounds__(256, 2)
mgemm(const float* __restrict__ A, const float* __restrict__ W,
      const float* __restrict__ bias, float* __restrict__ C,
      int N, int K, float scale) {
    __shared__ float As[2][16][SMS];
    __shared__ float Bs[2][16][SMS];
    const int tid = threadIdx.x;
    const int lane = tid & 31;
    const int g = lane >> 2, tg = lane & 3;
    const int wid = tid >> 5;
    const int r0 = (wid & 1) * 64;
    const int c0 = (wid >> 1) * 32;
    const int bx = blockIdx.x, by = blockIdx.y;

    const float* Ablk = A + (size_t)by * 128 * K;
    const float* Wblk = W + (size_t)bx * 128;

    const int arow = tid >> 1, acol = (tid & 1) * 8;
    const int brow = tid >> 4, bcol = (tid & 15) * 8;

    float acc[4][4][4];
#pragma unroll
    for (int mf = 0; mf < 4; mf++)
#pragma unroll
        for (int nf = 0; nf < 4; nf++)
#pragma unroll
            for (int r = 0; r < 4; r++) acc[mf][nf][r] = 0.f;

    const int nc = K / 16;
    float4 ra0, ra1, rb0, rb1;

#define MG_LDG(c)                                                              \
    {                                                                          \
        const int k0 = (c) * 16;                                               \
        ra0 = *(const float4*)(Ablk + (size_t)arow * K + k0 + acol);           \
        ra1 = *(const float4*)(Ablk + (size_t)arow * K + k0 + acol + 4);       \
        rb0 = *(const float4*)(Wblk + (size_t)(k0 + brow) * N + bcol);         \
        rb1 = *(const float4*)(Wblk + (size_t)(k0 + brow) * N + bcol + 4);     \
        cvt4(ra0); cvt4(ra1); cvt4(rb0); cvt4(rb1);                            \
    }
#define MG_STS(buf)                                                            \
    {                                                                          \
        As[buf][acol + 0][arow] = ra0.x; As[buf][acol + 1][arow] = ra0.y;      \
        As[buf][acol + 2][arow] = ra0.z; As[buf][acol + 3][arow] = ra0.w;      \
        As[buf][acol + 4][arow] = ra1.x; As[buf][acol + 5][arow] = ra1.y;      \
        As[buf][acol + 6][arow] = ra1.z; As[buf][acol + 7][arow] = ra1.w;      \
        *(float4*)&Bs[buf][brow][bcol]     = rb0;                              \
        *(float4*)&Bs[buf][brow][bcol + 4] = rb1;                              \
    }
#define MG_COMPUTE(buf)                                                        \
    {                                                                          \
        _Pragma("unroll")                                                      \
        for (int ks = 0; ks < 16; ks += 8) {                                   \
            float a[4][4], b[4][2];                                            \
            _Pragma("unroll")                                                  \
            for (int mf = 0; mf < 4; mf++) {                                   \
                const float* p0 = &As[buf][ks + tg][r0 + mf * 16 + g];         \
                const float* p1 = &As[buf][ks + tg + 4][r0 + mf * 16 + g];     \
                a[mf][0] = p0[0]; a[mf][1] = p0[8];                            \
                a[mf][2] = p1[0]; a[mf][3] = p1[8];                            \
            }                                                                  \
            _Pragma("unroll")                                                  \
            for (int nf = 0; nf < 4; nf++) {                                   \
                b[nf][0] = Bs[buf][ks + tg][c0 + nf * 8 + g];                  \
                b[nf][1] = Bs[buf][ks + tg + 4][c0 + nf * 8 + g];              \
            }                                                                  \
            _Pragma("unroll")                                                  \
            for (int mf = 0; mf < 4; mf++)                                     \
                _Pragma("unroll")                                              \
                for (int nf = 0; nf < 4; nf++)                                 \
                    mma8(acc[mf][nf], a[mf], b[nf]);                           \
        }                                                                      \
    }

    MG_LDG(0); MG_STS(0);
    __syncthreads();
    for (int c = 0; c < nc; c++) {
        const int cur = c & 1;
        if (c + 1 < nc) MG_LDG(c + 1);
        MG_COMPUTE(cur);
        if (c + 1 < nc) {
            MG_STS(cur ^ 1);
            __syncthreads();
        }
    }

#pragma unroll
    for (int nf = 0; nf < 4; nf++) {
        const int col = bx * 128 + c0 + nf * 8 + 2 * tg;
        float bv0 = 0.f, bv1 = 0.f;
        if (EPI >= 1) { bv0 = bias[col]; bv1 = bias[col + 1]; }
#pragma unroll
        for (int mf = 0; mf < 4; mf++) {
            const int row = by * 128 + r0 + mf * 16 + g;
            float d0 = acc[mf][nf][0], d1 = acc[mf][nf][1];
            float d2 = acc[mf][nf][2], d3 = acc[mf][nf][3];
            if (EPI >= 1) { d0 += bv0; d1 += bv1; d2 += bv0; d3 += bv1; }
            d0 *= scale; d1 *= scale; d2 *= scale; d3 *= scale;
            if (EPI == 2) {
                d0 = d0 * normcdff(d0); d1 = d1 * normcdff(d1);
                d2 = d2 * normcdff(d2); d3 = d3 * normcdff(d3);
            }
            *(float2*)(C + (size_t)row * N + col)       = make_float2(d0, d1);
            *(float2*)(C + (size_t)(row + 8) * N + col) = make_float2(d2, d3);
        }
    }
}

// ---------------------------------------------------------------------------
// Conv as implicit GEMM on tensor cores (K=2304); epilogue bias + PReLU.
// ---------------------------------------------------------------------------
__global__ void __launch_bounds__(256, 2)
conv_igemm(const float* __restrict__ sa, const float* __restrict__ ta,
           const float* __restrict__ Wg, const float* __restrict__ bias,
           const float* __restrict__ pa, float* __restrict__ out) {
    __shared__ float As[2][16][SMS];
    __shared__ float Bs[2][16][SMS];
    const int tid = threadIdx.x;
    const int lane = tid & 31;
    const int g = lane >> 2, tg = lane & 3;
    const int wid = tid >> 5;
    const int r0 = (wid & 1) * 64;
    const int c0 = (wid >> 1) * 32;
    const int by = blockIdx.y;

    const int arow = tid >> 1, acol = (tid & 1) * 8;
    const int brow = tid >> 4, bcol = (tid & 15) * 8;

    const int pixel = by * 128 + arow;
    const int xcrd = pixel % WW2;
    const int ycrd = (pixel / WW2) % HH;

    float acc[4][4][4];
#pragma unroll
    for (int mf = 0; mf < 4; mf++)
#pragma unroll
        for (int nf = 0; nf < 4; nf++)
#pragma unroll
            for (int r = 0; r < 4; r++) acc[mf][nf][r] = 0.f;

    const int nc = CONVK / 16;   // 144
    float4 ra0, ra1, rb0, rb1;

#define CV_LDG(c)                                                              \
    {                                                                          \
        const int k0 = (c) * 16;                                               \
        const int tap  = k0 >> 8;                                              \
        const int rem  = k0 & 255;                                             \
        const int half = rem >> 7;                                             \
        const int ic0  = (rem & 127) + acol;                                   \
        const int dy = tap / 3 - 1, dx = tap % 3 - 1;                          \
        const int ys = ycrd + dy, xs = xcrd + dx;                              \
        const bool valid = ((unsigned)ys < HH) && ((unsigned)xs < WW2);        \
        const float* src = half ? ta : sa;                                     \
        const float* ap = src + ((size_t)pixel + dy * WW2 + dx) * CC + ic0;    \
        ra0 = make_float4(0.f, 0.f, 0.f, 0.f); ra1 = ra0;                      \
        if (valid) { ra0 = *(const float4*)ap; ra1 = *(const float4*)(ap + 4); } \
        rb0 = *(const float4*)(Wg + (size_t)(k0 + brow) * CC + bcol);          \
        rb1 = *(const float4*)(Wg + (size_t)(k0 + brow) * CC + bcol + 4);      \
        cvt4(ra0); cvt4(ra1); cvt4(rb0); cvt4(rb1);                            \
    }

    CV_LDG(0); MG_STS(0);
    __syncthreads();
    for (int c = 0; c < nc; c++) {
        const int cur = c & 1;
        if (c + 1 < nc) CV_LDG(c + 1);
        MG_COMPUTE(cur);
        if (c + 1 < nc) {
            MG_STS(cur ^ 1);
            __syncthreads();
        }
    }

#pragma unroll
    for (int nf = 0; nf < 4; nf++) {
        const int col = c0 + nf * 8 + 2 * tg;
        const float bv0 = bias[col], bv1 = bias[col + 1];
        const float pv0 = pa[col],   pv1 = pa[col + 1];
#pragma unroll
        for (int mf = 0; mf < 4; mf++) {
            const int row = by * 128 + r0 + mf * 16 + g;
            float d0 = acc[mf][nf][0] + bv0, d1 = acc[mf][nf][1] + bv1;
            float d2 = acc[mf][nf][2] + bv0, d3 = acc[mf][nf][3] + bv1;
            if (d0 < 0.f) d0 *= pv0;
            if (d1 < 0.f) d1 *= pv1;
            if (d2 < 0.f) d2 *= pv0;
            if (d3 < 0.f) d3 *= pv1;
            *(float2*)(out + (size_t)row * CC + col)       = make_float2(d0, d1);
            *(float2*)(out + (size_t)(row + 8) * CC + col) = make_float2(d2, d3);
        }
    }
}

// ---------------------------------------------------------------------------
// out[t] = shortcut[t] + LayerNorm(y[t]) * g + b  (one token / 128-thr block)
// ---------------------------------------------------------------------------
__global__ void ln_residual(const float* __restrict__ y, const float* __restrict__ sc,
                            const float* __restrict__ g, const float* __restrict__ bta,
                            float* __restrict__ out) {
    const int tk = blockIdx.x;
    const int c  = threadIdx.x;
    __shared__ float red[4];
    float v = y[(size_t)tk * CC + c];

    float s = v;
#pragma unroll
    for (int o = 16; o; o >>= 1) s += __shfl_xor_sync(0xffffffffu, s, o);
    if ((c & 31) == 0) red[c >> 5] = s;
    __syncthreads();
    float mu = (red[0] + red[1] + red[2] + red[3]) * (1.f / CC);

    float dv = v - mu;
    float s2 = dv * dv;
#pragma unroll
    for (int o = 16; o; o >>= 1) s2 += __shfl_xor_sync(0xffffffffu, s2, o);
    __syncthreads();
    if ((c & 31) == 0) red[c >> 5] = s2;
    __syncthreads();
    float var = (red[0] + red[1] + red[2] + red[3]) * (1.f / CC);

    out[(size_t)tk * CC + c] = sc[(size_t)tk * CC + c] + dv * rsqrtf(var + EPS_V) * g[c] + bta[c];
}

// ---------------------------------------------------------------------------
// Windowed attention (exact fp32; gathers through shift mapping).
// ---------------------------------------------------------------------------
__device__ __forceinline__ int region_label(int h, int w) {
    int rh = (h < HH - WS) ? 0 : ((h < HH - WS / 2) ? 1 : 2);
    int rw = (w < WW2 - WS) ? 0 : ((w < WW2 - WS / 2) ? 1 : 2);
    return rh * 3 + rw;
}

__global__ void attn_kernel(const float* __restrict__ q, const float* __restrict__ kv,
                            const float* __restrict__ relb, float* __restrict__ out,
                            int shift) {
    const int win = blockIdx.x;
    const int b   = blockIdx.y;
    const int h   = blockIdx.z;
    const int gy = win / (WW2 / WS), gx = win % (WW2 / WS);
    const int t  = threadIdx.x;
    const int ty = t >> 3, tx = t & 7;

    __shared__ float ks[64][36];
    __shared__ float vs[64][36];

    const int py = (gy * WS + ty + shift) % HH;
    const int px = (gx * WS + tx + shift) % WW2;
    const size_t pix = ((size_t)b * HH + py) * WW2 + px;

    const float4* kvrow = (const float4*)(kv + pix * (2 * CC) + h * HD);
    const float4* vvrow = (const float4*)(kv + pix * (2 * CC) + CC + h * HD);
#pragma unroll
    for (int d4 = 0; d4 < HD / 4; d4++) {
        *(float4*)&ks[t][d4 * 4] = kvrow[d4];
        *(float4*)&vs[t][d4 * 4] = vvrow[d4];
    }
    float4 qr[HD / 4];
    const float4* qrow = (const float4*)(q + pix * CC + h * HD);
#pragma unroll
    for (int d4 = 0; d4 < HD / 4; d4++) qr[d4] = qrow[d4];
    __syncthreads();

    int li = 0;
    if (shift) li = region_label(gy * WS + ty, gx * WS + tx);

    float s[64];
    float mx = -1e30f;
#pragma unroll
    for (int j = 0; j < 64; j++) {
        float acc = 0.f;
        const float4* kr = (const float4*)&ks[j][0];
#pragma unroll
        for (int d4 = 0; d4 < HD / 4; d4++) {
            float4 kk = kr[d4];
            acc += qr[d4].x * kk.x + qr[d4].y * kk.y + qr[d4].z * kk.z + qr[d4].w * kk.w;
        }
        int jy = j >> 3, jx = j & 7;
        acc += relb[((ty - jy + WS - 1) * (2 * WS - 1) + (tx - jx + WS - 1)) * NHEAD + h];
        if (shift) {
            int lj = region_label(gy * WS + jy, gx * WS + jx);
            if (lj != li) acc -= 100.0f;
        }
        s[j] = acc;
        mx = fmaxf(mx, acc);
    }
    float sum = 0.f;
#pragma unroll
    for (int j = 0; j < 64; j++) { s[j] = expf(s[j] - mx); sum += s[j]; }
    const float inv = 1.0f / sum;

    float4 o4[HD / 4];
#pragma unroll
    for (int d4 = 0; d4 < HD / 4; d4++) o4[d4] = make_float4(0.f, 0.f, 0.f, 0.f);
#pragma unroll
    for (int j = 0; j < 64; j++) {
        const float sj = s[j];
        const float4* vr = (const float4*)&vs[j][0];
#pragma unroll
        for (int d4 = 0; d4 < HD / 4; d4++) {
            float4 vv = vr[d4];
            o4[d4].x += sj * vv.x; o4[d4].y += sj * vv.y;
            o4[d4].z += sj * vv.z; o4[d4].w += sj * vv.w;
        }
    }
    float4* orow = (float4*)(out + pix * CC + h * HD);
#pragma unroll
    for (int d4 = 0; d4 < HD / 4; d4++) {
        float4 o = o4[d4];
        o.x *= inv; o.y *= inv; o.z *= inv; o.w *= inv;
        orow[d4] = o;
    }
}

// ---------------------------------------------------------------------------
// Host driver (graph-capturable: launches only)
// ---------------------------------------------------------------------------
template <typename T>
static float* sym(const T& s) {
    void* p = nullptr;
    cudaGetSymbolAddress(&p, s);
    return (float*)p;
}

extern "C" void kernel_launch(void* const* d_in, const int* in_sizes, int n_in,
                              void* d_out, int out_size) {
    const float* x      = (const float*)d_in[0];
    const float* source = (const float*)d_in[1];
    const float* target = (const float*)d_in[2];
    const float* qW     = (const float*)d_in[3];
    const float* qb     = (const float*)d_in[4];
    const float* kvW    = (const float*)d_in[5];
    const float* kvb    = (const float*)d_in[6];
    const float* pW     = (const float*)d_in[7];
    const float* pb     = (const float*)d_in[8];
    const float* relb   = (const float*)d_in[9];
    const float* mW     = (const float*)d_in[10];
    const float* n1g    = (const float*)d_in[11];
    const float* n1b    = (const float*)d_in[12];
    const float* f1W    = (const float*)d_in[13];
    const float* f1b    = (const float*)d_in[14];
    const float* f2W    = (const float*)d_in[15];
    const float* f2b    = (const float*)d_in[16];
    const float* n2g    = (const float*)d_in[17];
    const float* n2b    = (const float*)d_in[18];
    const float* convW  = (const float*)d_in[19];
    const float* convb  = (const float*)d_in[20];
    const float* pa     = (const float*)d_in[21];

    float* bx    = sym(g_x);
    float* bsrc  = sym(g_src);
    float* btgt  = sym(g_tgt);
    float* bq    = sym(g_q);
    float* bkv   = sym(g_kv);
    float* battn = sym(g_attn);
    float* bx1   = sym(g_x1);
    float* bh    = sym(g_h);
    float* bsa   = sym(g_sa);
    float* bta   = sym(g_ta);
    float* bwg   = sym(g_wg);
    float* bpwm  = sym(g_pwm);
    float* bpbm  = sym(g_pbm);

    const float SCALE = 0.1767766952966369f;   // 32^-0.5
    const int nblk = (NTOK * CC + 255) / 256;
    const dim3 gM1(1, NTOK / 128), gM2(2, NTOK / 128), gM4(4, NTOK / 128);

    nchw2nhwc<<<nblk, 256>>>(x, bx);
    nchw2nhwc<<<nblk, 256>>>(source, bsrc);
    nchw2nhwc<<<nblk, 256>>>(target, btgt);

    for (int d = 0; d < 2; d++) {
        const int shift = (d % 2) ? (WS / 2) : 0;

        // fused projection weights: pWm = pW @ mW (exact fp32), pbm = pb @ mW
        fuse_pwm<<<CC, CC>>>(pW + (size_t)d * CC * CC, mW + (size_t)d * CC * CC, bpwm);
        fuse_bias<<<1, CC>>>(pb + d * CC, mW + (size_t)d * CC * CC, bpbm);

        // q = (x @ qW + qb) * scale   (shared by both branches)
        mgemm<1><<<gM1, 256>>>(bx, qW + (size_t)d * CC * CC, qb + d * CC, bq, CC, CC, SCALE);

        for (int br = 0; br < 2; br++) {
            const float* feat = br ? btgt : bsrc;
            float* dest = br ? bta : bsa;
            // kv = feat @ kvW + kvb   [T, 256]
            mgemm<1><<<gM2, 256>>>(feat, kvW + (size_t)d * CC * 2 * CC, kvb + d * 2 * CC,
                                   bkv, 2 * CC, CC, 1.f);
            // windowed attention -> battn [T, 128]
            attn_kernel<<<dim3(576, BB, NHEAD), 64>>>(bq, bkv, relb + (size_t)d * 225 * NHEAD,
                                                      battn, shift);
            // tmp = attn @ pWm + pbm  (proj+mW fused) -> reuse bkv
            mgemm<1><<<gM1, 256>>>(battn, bpwm, bpbm, bkv, CC, CC, 1.f);
            // x1 = x + LN(tmp)
            ln_residual<<<NTOK, 128>>>(bkv, bx, n1g + d * CC, n1b + d * CC, bx1);
            // h = gelu(x1 @ f1W + f1b)
            mgemm<2><<<gM4, 256>>>(bx1, f1W + (size_t)d * CC * HID, f1b + d * HID, bh, HID, CC, 1.f);
            // tmp2 = h @ f2W + f2b -> bkv
            mgemm<1><<<gM1, 256>>>(bh, f2W + (size_t)d * HID * CC, f2b + d * CC, bkv, CC, HID, 1.f);
            // dest = x1 + LN(tmp2)
            ln_residual<<<NTOK, 128>>>(bkv, bx1, n2g + d * CC, n2b + d * CC, dest);
        }
        // conv([sa; ta]) + bias + PReLU -> new x (NHWC), tensor-core implicit GEMM
        repack_w<<<(CONVK * CC + 255) / 256, 256>>>(convW + (size_t)d * CC * 256 * 9, bwg);
        conv_igemm<<<dim3(1, NTOK / 128), 256>>>(bsa, bta, bwg, convb + d * CC, pa + d * CC, bx);
    }

    nhwc2nchw<<<nblk, 256>>>(bx, (float*)d_out);
}

// round 12
// speedup vs baseline: 5.9860x; 1.1318x over previous
#include <cuda_runtime.h>
#include <math.h>

// ---------------------------------------------------------------------------
// Problem constants
// ---------------------------------------------------------------------------
#define BB 2
#define CC 128
#define HH 192
#define WW2 192
#define NHEAD 4
#define HD 32
#define WS 8
#define NTOK 73728           // B*H*W
#define NPIX 36864           // H*W
#define HID 512
#define EPS_V 1e-5f
#define CONVK 2304           // 9 taps * 2 halves * 128 ic
#define SMS 136              // smem row stride (tg*8+g bank mapping -> conflict-free)

// ---------------------------------------------------------------------------
// Scratch buffers (device globals; allocation-free)
// ---------------------------------------------------------------------------
__device__ float g_x   [NTOK * CC];
__device__ float g_src [NTOK * CC];
__device__ float g_tgt [NTOK * CC];
__device__ float g_q   [NTOK * CC];
__device__ float g_kv  [NTOK * 2 * CC];
__device__ float g_attn[NTOK * CC];
__device__ float g_x1  [NTOK * CC];
__device__ float g_h   [NTOK * HID];
__device__ float g_sa  [NTOK * CC];
__device__ float g_ta  [NTOK * CC];
__device__ float g_wg  [CONVK * CC];   // repacked conv weights [K, OC]
__device__ float g_pwm [CC * CC];      // fused pW @ mW
__device__ float g_pbm [CC];           // fused pb @ mW

// ---------------------------------------------------------------------------
// tf32 helpers
// ---------------------------------------------------------------------------
__device__ __forceinline__ float to_tf32(float x) {
    float r;
    asm("cvt.rna.tf32.f32 %0, %1;" : "=f"(r) : "f"(x));
    return r;
}
__device__ __forceinline__ void cvt4(float4& v) {
    v.x = to_tf32(v.x); v.y = to_tf32(v.y); v.z = to_tf32(v.z); v.w = to_tf32(v.w);
}
__device__ __forceinline__ void mma8(float* d, const float* a, const float* b) {
    asm volatile(
        "mma.sync.aligned.m16n8k8.row.col.f32.tf32.tf32.f32 "
        "{%0,%1,%2,%3}, {%4,%5,%6,%7}, {%8,%9}, {%0,%1,%2,%3};\n"
        : "+f"(d[0]), "+f"(d[1]), "+f"(d[2]), "+f"(d[3])
        : "r"(__float_as_uint(a[0])), "r"(__float_as_uint(a[1])),
          "r"(__float_as_uint(a[2])), "r"(__float_as_uint(a[3])),
          "r"(__float_as_uint(b[0])), "r"(__float_as_uint(b[1])));
}

// ---------------------------------------------------------------------------
// Tiled layout transforms: coalesced on both sides via 32x32 smem tiles.
// in:  [B][C][P]  ->  out: [B][P][C]       (and the inverse)
// ---------------------------------------------------------------------------
__global__ void t_nchw2nhwc(const float* __restrict__ in, float* __restrict__ out) {
    __shared__ float tile[32][33];
    const int b = blockIdx.z;
    const int c0 = blockIdx.y * 32, p0 = blockIdx.x * 32;
    const int tr = threadIdx.x >> 5, tc = threadIdx.x & 31;
#pragma unroll
    for (int i = 0; i < 32; i += 8)
        tile[tr + i][tc] = in[((size_t)b * CC + c0 + tr + i) * NPIX + p0 + tc];
    __syncthreads();
#pragma unroll
    for (int i = 0; i < 32; i += 8)
        out[((size_t)b * NPIX + p0 + tr + i) * CC + c0 + tc] = tile[tc][tr + i];
}

__global__ void t_nhwc2nchw(const float* __restrict__ in, float* __restrict__ out) {
    __shared__ float tile[32][33];
    const int b = blockIdx.z;
    const int c0 = blockIdx.y * 32, p0 = blockIdx.x * 32;
    const int tr = threadIdx.x >> 5, tc = threadIdx.x & 31;
#pragma unroll
    for (int i = 0; i < 32; i += 8)
        tile[tr + i][tc] = in[((size_t)b * NPIX + p0 + tr + i) * CC + c0 + tc];
    __syncthreads();
#pragma unroll
    for (int i = 0; i < 32; i += 8)
        out[((size_t)b * CC + c0 + tr + i) * NPIX + p0 + tc] = tile[tc][tr + i];
}

// ---------------------------------------------------------------------------
// Conv weight repack: OIHW [128, 256, 3, 3] -> [K=2304, OC=128]
// ---------------------------------------------------------------------------
__global__ void repack_w(const float* __restrict__ convW, float* __restrict__ wg) {
    int idx = blockIdx.x * blockDim.x + threadIdx.x;
    if (idx >= CONVK * CC) return;
    int oc = idx % CC;
    int k  = idx / CC;
    int tap = k >> 8;
    int cin = k & 255;
    int ky = tap / 3, kx = tap % 3;
    wg[idx] = convW[(((size_t)oc * 256 + cin) * 3 + ky) * 3 + kx];
}

// exact fp32 fused projection: blocks 0..127 -> pwm rows; block 128 -> pbm
__global__ void fuse_pwm_bias(const float* __restrict__ pW, const float* __restrict__ pb,
                              const float* __restrict__ mW, float* __restrict__ pwm,
                              float* __restrict__ pbm) {
    __shared__ float arow[CC];
    const int i = blockIdx.x, j = threadIdx.x;
    arow[j] = (i < CC) ? pW[i * CC + j] : pb[j];
    __syncthreads();
    float s = 0.f;
    for (int k = 0; k < CC; k++) s += arow[k] * mW[k * CC + j];
    if (i < CC) pwm[i * CC + j] = s;
    else pbm[j] = s;
}

// ---------------------------------------------------------------------------
// tf32 tensor-core GEMM: C = epi(A[M,K] @ W[K,N]); BM=BN=128, BK=16, 256 thr.
// 8 warps as 2(m) x 4(n); warp tile 64x32 via m16n8k8 frags.
// EPI: 0:*scale  1:(+bias)*scale  2:gelu(+bias)
// ---------------------------------------------------------------------------
#define MG_PROLOG                                                              \
    const int tid = threadIdx.x;                                               \
    const int lane = tid & 31;                                                 \
    const int g = lane >> 2, tg = lane & 3;                                    \
    const int wid = tid >> 5;                                                  \
    const int r0 = (wid & 1) * 64;                                             \
    const int c0 = (wid >> 1) * 32;                                            \
    const int arow = tid >> 1, acol = (tid & 1) * 8;                           \
    const int brow = tid >> 4, bcol = (tid & 15) * 8;                          \
    float acc[4][4][4];                                                        \
    _Pragma("unroll")                                                          \
    for (int mf = 0; mf < 4; mf++)                                             \
        _Pragma("unroll")                                                      \
        for (int nf = 0; nf < 4; nf++)                                         \
            _Pragma("unroll")                                                  \
            for (int r = 0; r < 4; r++) acc[mf][nf][r] = 0.f;

#define MG_STS(buf)                                                            \
    {                                                                          \
        As[buf][acol + 0][arow] = ra0.x; As[buf][acol + 1][arow] = ra0.y;      \
        As[buf][acol + 2][arow] = ra0.z; As[buf][acol + 3][arow] = ra0.w;      \
        As[buf][acol + 4][arow] = ra1.x; As[buf][acol + 5][arow] = ra1.y;      \
        As[buf][acol + 6][arow] = ra1.z; As[buf][acol + 7][arow] = ra1.w;      \
        *(float4*)&Bs[buf][brow][bcol]     = rb0;                              \
        *(float4*)&Bs[buf][brow][bcol + 4] = rb1;                              \
    }
#define MG_COMPUTE(buf)                                                        \
    {                                                                          \
        _Pragma("unroll")                                                      \
        for (int ks = 0; ks < 16; ks += 8) {                                   \
            float a[4][4], b[4][2];                                            \
            _Pragma("unroll")                                                  \
            for (int mf = 0; mf < 4; mf++) {                                   \
                const float* p0 = &As[buf][ks + tg][r0 + mf * 16 + g];         \
                const float* p1 = &As[buf][ks + tg + 4][r0 + mf * 16 + g];     \
                a[mf][0] = p0[0]; a[mf][1] = p0[8];                            \
                a[mf][2] = p1[0]; a[mf][3] = p1[8];                            \
            }                                                                  \
            _Pragma("unroll")                                                  \
            for (int nf = 0; nf < 4; nf++) {                                   \
                b[nf][0] = Bs[buf][ks + tg][c0 + nf * 8 + g];                  \
                b[nf][1] = Bs[buf][ks + tg + 4][c0 + nf * 8 + g];              \
            }                                                                  \
            _Pragma("unroll")                                                  \
            for (int mf = 0; mf < 4; mf++)                                     \
                _Pragma("unroll")                                              \
                for (int nf = 0; nf < 4; nf++)                                 \
                    mma8(acc[mf][nf], a[mf], b[nf]);                           \
        }                                                                      \
    }
#define MG_LDG(c)                                                              \
    {                                                                          \
        const int k0 = (c) * 16;                                               \
        ra0 = *(const float4*)(Ablk + (size_t)arow * K + k0 + acol);           \
        ra1 = *(const float4*)(Ablk + (size_t)arow * K + k0 + acol + 4);       \
        rb0 = *(const float4*)(Wblk + (size_t)(k0 + brow) * N + bcol);         \
        rb1 = *(const float4*)(Wblk + (size_t)(k0 + brow) * N + bcol + 4);     \
        cvt4(ra0); cvt4(ra1); cvt4(rb0); cvt4(rb1);                            \
    }
#define MG_MAINLOOP(LDG_MACRO)                                                 \
    {                                                                          \
        LDG_MACRO(0); MG_STS(0);                                               \
        __syncthreads();                                                       \
        for (int c = 0; c < nc; c++) {                                         \
            const int cur = c & 1;                                             \
            if (c + 1 < nc) LDG_MACRO(c + 1);                                  \
            MG_COMPUTE(cur);                                                   \
            if (c + 1 < nc) {                                                  \
                MG_STS(cur ^ 1);                                               \
                __syncthreads();                                               \
            }                                                                  \
        }                                                                      \
    }

template <int EPI>
__global__ void __launch_bounds__(256, 2)
mgemm(const float* __restrict__ A, const float* __restrict__ W,
      const float* __restrict__ bias, float* __restrict__ C,
      int N, int K, float scale) {
    __shared__ float As[2][16][SMS];
    __shared__ float Bs[2][16][SMS];
    MG_PROLOG
    const int bx = blockIdx.x, by = blockIdx.y;
    const float* Ablk = A + (size_t)by * 128 * K;
    const float* Wblk = W + (size_t)bx * 128;
    const int nc = K / 16;
    float4 ra0, ra1, rb0, rb1;
    MG_MAINLOOP(MG_LDG)

#pragma unroll
    for (int nf = 0; nf < 4; nf++) {
        const int col = bx * 128 + c0 + nf * 8 + 2 * tg;
        float bv0 = 0.f, bv1 = 0.f;
        if (EPI >= 1) { bv0 = bias[col]; bv1 = bias[col + 1]; }
#pragma unroll
        for (int mf = 0; mf < 4; mf++) {
            const int row = by * 128 + r0 + mf * 16 + g;
            float d0 = acc[mf][nf][0], d1 = acc[mf][nf][1];
            float d2 = acc[mf][nf][2], d3 = acc[mf][nf][3];
            if (EPI >= 1) { d0 += bv0; d1 += bv1; d2 += bv0; d3 += bv1; }
            d0 *= scale; d1 *= scale; d2 *= scale; d3 *= scale;
            if (EPI == 2) {
                d0 = d0 * normcdff(d0); d1 = d1 * normcdff(d1);
                d2 = d2 * normcdff(d2); d3 = d3 * normcdff(d3);
            }
            *(float2*)(C + (size_t)row * N + col)       = make_float2(d0, d1);
            *(float2*)(C + (size_t)(row + 8) * N + col) = make_float2(d2, d3);
        }
    }
}

// ---------------------------------------------------------------------------
// tf32 GEMM + fused (bias, LayerNorm over N=128, residual):
//   out = sc + LN(A@W + bias) * gamma + beta      (N == 128, grid.x == 1)
// Row stats: intra-warp shfl over tg lanes, cross-warp via 4KB smem stage.
// ---------------------------------------------------------------------------
__global__ void __launch_bounds__(256, 2)
mgemm_ln(const float* __restrict__ A, const float* __restrict__ W,
         const float* __restrict__ bias, const float* __restrict__ sc,
         const float* __restrict__ gamma, const float* __restrict__ beta,
         float* __restrict__ out, int K) {
    __shared__ float As[2][16][SMS];
    __shared__ float Bs[2][16][SMS];
    __shared__ float redS[128][4][2];
    MG_PROLOG
    const int by = blockIdx.y;
    const float* Ablk = A + (size_t)by * 128 * K;
    const float* Wblk = W;
    const int N = 128;
    const int nc = K / 16;
    const int wq = wid >> 1;
    float4 ra0, ra1, rb0, rb1;
    MG_MAINLOOP(MG_LDG)

    // add bias into acc
#pragma unroll
    for (int nf = 0; nf < 4; nf++) {
        const float2 bv = *(const float2*)&bias[c0 + nf * 8 + 2 * tg];
#pragma unroll
        for (int mf = 0; mf < 4; mf++) {
            acc[mf][nf][0] += bv.x; acc[mf][nf][1] += bv.y;
            acc[mf][nf][2] += bv.x; acc[mf][nf][3] += bv.y;
        }
    }

    // partial row sums (8 cols per thread per row), reduce over tg lanes
#pragma unroll
    for (int mf = 0; mf < 4; mf++) {
        float s1A = 0.f, s2A = 0.f, s1B = 0.f, s2B = 0.f;
#pragma unroll
        for (int nf = 0; nf < 4; nf++) {
            s1A += acc[mf][nf][0] + acc[mf][nf][1];
            s2A += acc[mf][nf][0] * acc[mf][nf][0] + acc[mf][nf][1] * acc[mf][nf][1];
            s1B += acc[mf][nf][2] + acc[mf][nf][3];
            s2B += acc[mf][nf][2] * acc[mf][nf][2] + acc[mf][nf][3] * acc[mf][nf][3];
        }
#pragma unroll
        for (int m = 1; m <= 2; m <<= 1) {
            s1A += __shfl_xor_sync(0xffffffffu, s1A, m);
            s2A += __shfl_xor_sync(0xffffffffu, s2A, m);
            s1B += __shfl_xor_sync(0xffffffffu, s1B, m);
            s2B += __shfl_xor_sync(0xffffffffu, s2B, m);
        }
        if (tg == 0) {
            const int rA = r0 + mf * 16 + g;
            redS[rA][wq][0] = s1A;     redS[rA][wq][1] = s2A;
            redS[rA + 8][wq][0] = s1B; redS[rA + 8][wq][1] = s2B;
        }
    }
    __syncthreads();

    // finish stats + apply LN + residual + store
    float gj[4][2], bj[4][2];
#pragma unroll
    for (int nf = 0; nf < 4; nf++) {
        const int col = c0 + nf * 8 + 2 * tg;
        *(float2*)gj[nf] = *(const float2*)&gamma[col];
        *(float2*)bj[nf] = *(const float2*)&beta[col];
    }
#pragma unroll
    for (int mf = 0; mf < 4; mf++) {
        const int rA = r0 + mf * 16 + g;
        float s1A = redS[rA][0][0] + redS[rA][1][0] + redS[rA][2][0] + redS[rA][3][0];
        float s2A = redS[rA][0][1] + redS[rA][1][1] + redS[rA][2][1] + redS[rA][3][1];
        float s1B = redS[rA + 8][0][0] + redS[rA + 8][1][0] + redS[rA + 8][2][0] + redS[rA + 8][3][0];
        float s2B = redS[rA + 8][0][1] + redS[rA + 8][1][1] + redS[rA + 8][2][1] + redS[rA + 8][3][1];
        const float muA = s1A * (1.f / 128.f);
        const float rsA = rsqrtf(s2A * (1.f / 128.f) - muA * muA + EPS_V);
        const float muB = s1B * (1.f / 128.f);
        const float rsB = rsqrtf(s2B * (1.f / 128.f) - muB * muB + EPS_V);
        const int rowA = by * 128 + rA;
#pragma unroll
        for (int nf = 0; nf < 4; nf++) {
            const int col = c0 + nf * 8 + 2 * tg;
            float2 scA = *(const float2*)(sc + (size_t)rowA * N + col);
            float2 scB = *(const float2*)(sc + (size_t)(rowA + 8) * N + col);
            float o0 = scA.x + (acc[mf][nf][0] - muA) * rsA * gj[nf][0] + bj[nf][0];
            float o1 = scA.y + (acc[mf][nf][1] - muA) * rsA * gj[nf][1] + bj[nf][1];
            float o2 = scB.x + (acc[mf][nf][2] - muB) * rsB * gj[nf][0] + bj[nf][0];
            float o3 = scB.y + (acc[mf][nf][3] - muB) * rsB * gj[nf][1] + bj[nf][1];
            *(float2*)(out + (size_t)rowA * N + col)       = make_float2(o0, o1);
            *(float2*)(out + (size_t)(rowA + 8) * N + col) = make_float2(o2, o3);
        }
    }
}

// ---------------------------------------------------------------------------
// Conv as implicit GEMM on tensor cores (K=2304); epilogue bias + PReLU.
// ---------------------------------------------------------------------------
__global__ void __launch_bounds__(256, 2)
conv_igemm(const float* __restrict__ sa, const float* __restrict__ ta,
           const float* __restrict__ Wg, const float* __restrict__ bias,
           const float* __restrict__ pa, float* __restrict__ out) {
    __shared__ float As[2][16][SMS];
    __shared__ float Bs[2][16][SMS];
    MG_PROLOG
    const int by = blockIdx.y;
    const int pixel = by * 128 + arow;
    const int xcrd = pixel % WW2;
    const int ycrd = (pixel / WW2) % HH;
    const int nc = CONVK / 16;   // 144
    float4 ra0, ra1, rb0, rb1;

#define CV_LDG(c)                                                              \
    {                                                                          \
        const int k0 = (c) * 16;                                               \
        const int tap  = k0 >> 8;                                              \
        const int rem  = k0 & 255;                                             \
        const int half = rem >> 7;                                             \
        const int ic0  = (rem & 127) + acol;                                   \
        const int dy = tap / 3 - 1, dx = tap % 3 - 1;                          \
        const int ys = ycrd + dy, xs = xcrd + dx;                              \
        const bool valid = ((unsigned)ys < HH) && ((unsigned)xs < WW2);        \
        const float* src = half ? ta : sa;                                     \
        const float* ap = src + ((size_t)pixel + dy * WW2 + dx) * CC + ic0;    \
        ra0 = make_float4(0.f, 0.f, 0.f, 0.f); ra1 = ra0;                      \
        if (valid) { ra0 = *(const float4*)ap; ra1 = *(const float4*)(ap + 4); } \
        rb0 = *(const float4*)(Wg + (size_t)(k0 + brow) * CC + bcol);          \
        rb1 = *(const float4*)(Wg + (size_t)(k0 + brow) * CC + bcol + 4);      \
        cvt4(ra0); cvt4(ra1); cvt4(rb0); cvt4(rb1);                            \
    }

    MG_MAINLOOP(CV_LDG)

#pragma unroll
    for (int nf = 0; nf < 4; nf++) {
        const int col = c0 + nf * 8 + 2 * tg;
        const float bv0 = bias[col], bv1 = bias[col + 1];
        const float pv0 = pa[col],   pv1 = pa[col + 1];
#pragma unroll
        for (int mf = 0; mf < 4; mf++) {
            const int row = by * 128 + r0 + mf * 16 + g;
            float d0 = acc[mf][nf][0] + bv0, d1 = acc[mf][nf][1] + bv1;
            float d2 = acc[mf][nf][2] + bv0, d3 = acc[mf][nf][3] + bv1;
            if (d0 < 0.f) d0 *= pv0;
            if (d1 < 0.f) d1 *= pv1;
            if (d2 < 0.f) d2 *= pv0;
            if (d3 < 0.f) d3 *= pv1;
            *(float2*)(out + (size_t)row * CC + col)       = make_float2(d0, d1);
            *(float2*)(out + (size_t)(row + 8) * CC + col) = make_float2(d2, d3);
        }
    }
}

// ---------------------------------------------------------------------------
// Windowed attention (exact fp32; gathers through shift mapping).
// ---------------------------------------------------------------------------
__device__ __forceinline__ int region_label(int h, int w) {
    int rh = (h < HH - WS) ? 0 : ((h < HH - WS / 2) ? 1 : 2);
    int rw = (w < WW2 - WS) ? 0 : ((w < WW2 - WS / 2) ? 1 : 2);
    return rh * 3 + rw;
}

__global__ void attn_kernel(const float* __restrict__ q, const float* __restrict__ kv,
                            const float* __restrict__ relb, float* __restrict__ out,
                            int shift) {
    const int win = blockIdx.x;
    const int b   = blockIdx.y;
    const int h   = blockIdx.z;
    const int gy = win / (WW2 / WS), gx = win % (WW2 / WS);
    const int t  = threadIdx.x;
    const int ty = t >> 3, tx = t & 7;

    __shared__ float ks[64][36];
    __shared__ float vs[64][36];

    const int py = (gy * WS + ty + shift) % HH;
    const int px = (gx * WS + tx + shift) % WW2;
    const size_t pix = ((size_t)b * HH + py) * WW2 + px;

    const float4* kvrow = (const float4*)(kv + pix * (2 * CC) + h * HD);
    const float4* vvrow = (const float4*)(kv + pix * (2 * CC) + CC + h * HD);
#pragma unroll
    for (int d4 = 0; d4 < HD / 4; d4++) {
        *(float4*)&ks[t][d4 * 4] = kvrow[d4];
        *(float4*)&vs[t][d4 * 4] = vvrow[d4];
    }
    float4 qr[HD / 4];
    const float4* qrow = (const float4*)(q + pix * CC + h * HD);
#pragma unroll
    for (int d4 = 0; d4 < HD / 4; d4++) qr[d4] = qrow[d4];
    __syncthreads();

    int li = 0;
    if (shift) li = region_label(gy * WS + ty, gx * WS + tx);

    float s[64];
    float mx = -1e30f;
#pragma unroll
    for (int j = 0; j < 64; j++) {
        float acc = 0.f;
        const float4* kr = (const float4*)&ks[j][0];
#pragma unroll
        for (int d4 = 0; d4 < HD / 4; d4++) {
            float4 kk = kr[d4];
            acc += qr[d4].x * kk.x + qr[d4].y * kk.y + qr[d4].z * kk.z + qr[d4].w * kk.w;
        }
        int jy = j >> 3, jx = j & 7;
        acc += relb[((ty - jy + WS - 1) * (2 * WS - 1) + (tx - jx + WS - 1)) * NHEAD + h];
        if (shift) {
            int lj = region_label(gy * WS + jy, gx * WS + jx);
            if (lj != li) acc -= 100.0f;
        }
        s[j] = acc;
        mx = fmaxf(mx, acc);
    }
    float sum = 0.f;
#pragma unroll
    for (int j = 0; j < 64; j++) { s[j] = expf(s[j] - mx); sum += s[j]; }
    const float inv = 1.0f / sum;

    float4 o4[HD / 4];
#pragma unroll
    for (int d4 = 0; d4 < HD / 4; d4++) o4[d4] = make_float4(0.f, 0.f, 0.f, 0.f);
#pragma unroll
    for (int j = 0; j < 64; j++) {
        const float sj = s[j];
        const float4* vr = (const float4*)&vs[j][0];
#pragma unroll
        for (int d4 = 0; d4 < HD / 4; d4++) {
            float4 vv = vr[d4];
            o4[d4].x += sj * vv.x; o4[d4].y += sj * vv.y;
            o4[d4].z += sj * vv.z; o4[d4].w += sj * vv.w;
        }
    }
    float4* orow = (float4*)(out + pix * CC + h * HD);
#pragma unroll
    for (int d4 = 0; d4 < HD / 4; d4++) {
        float4 o = o4[d4];
        o.x *= inv; o.y *= inv; o.z *= inv; o.w *= inv;
        orow[d4] = o;
    }
}

// ---------------------------------------------------------------------------
// Host driver (graph-capturable: launches only)
// ---------------------------------------------------------------------------
template <typename T>
static float* sym(const T& s) {
    void* p = nullptr;
    cudaGetSymbolAddress(&p, s);
    return (float*)p;
}

extern "C" void kernel_launch(void* const* d_in, const int* in_sizes, int n_in,
                              void* d_out, int out_size) {
    const float* x      = (const float*)d_in[0];
    const float* source = (const float*)d_in[1];
    const float* target = (const float*)d_in[2];
    const float* qW     = (const float*)d_in[3];
    const float* qb     = (const float*)d_in[4];
    const float* kvW    = (const float*)d_in[5];
    const float* kvb    = (const float*)d_in[6];
    const float* pW     = (const float*)d_in[7];
    const float* pb     = (const float*)d_in[8];
    const float* relb   = (const float*)d_in[9];
    const float* mW     = (const float*)d_in[10];
    const float* n1g    = (const float*)d_in[11];
    const float* n1b    = (const float*)d_in[12];
    const float* f1W    = (const float*)d_in[13];
    const float* f1b    = (const float*)d_in[14];
    const float* f2W    = (const float*)d_in[15];
    const float* f2b    = (const float*)d_in[16];
    const float* n2g    = (const float*)d_in[17];
    const float* n2b    = (const float*)d_in[18];
    const float* convW  = (const float*)d_in[19];
    const float* convb  = (const float*)d_in[20];
    const float* pa     = (const float*)d_in[21];

    float* bx    = sym(g_x);
    float* bsrc  = sym(g_src);
    float* btgt  = sym(g_tgt);
    float* bq    = sym(g_q);
    float* bkv   = sym(g_kv);
    float* battn = sym(g_attn);
    float* bx1   = sym(g_x1);
    float* bh    = sym(g_h);
    float* bsa   = sym(g_sa);
    float* bta   = sym(g_ta);
    float* bwg   = sym(g_wg);
    float* bpwm  = sym(g_pwm);
    float* bpbm  = sym(g_pbm);

    const float SCALE = 0.1767766952966369f;   // 32^-0.5
    const dim3 gT(NPIX / 32, CC / 32, BB);
    const dim3 gM1(1, NTOK / 128), gM2(2, NTOK / 128), gM4(4, NTOK / 128);

    t_nchw2nhwc<<<gT, 256>>>(x, bx);
    t_nchw2nhwc<<<gT, 256>>>(source, bsrc);
    t_nchw2nhwc<<<gT, 256>>>(target, btgt);

    for (int d = 0; d < 2; d++) {
        const int shift = (d % 2) ? (WS / 2) : 0;

        // fused projection weights: pWm = pW @ mW (exact fp32), pbm = pb @ mW
        fuse_pwm_bias<<<CC + 1, CC>>>(pW + (size_t)d * CC * CC, pb + d * CC,
                                      mW + (size_t)d * CC * CC, bpwm, bpbm);

        // q = (x @ qW + qb) * scale   (shared by both branches)
        mgemm<1><<<gM1, 256>>>(bx, qW + (size_t)d * CC * CC, qb + d * CC, bq, CC, CC, SCALE);

        for (int br = 0; br < 2; br++) {
            const float* feat = br ? btgt : bsrc;
            float* dest = br ? bta : bsa;
            // kv = feat @ kvW + kvb   [T, 256]
            mgemm<1><<<gM2, 256>>>(feat, kvW + (size_t)d * CC * 2 * CC, kvb + d * 2 * CC,
                                   bkv, 2 * CC, CC, 1.f);
            // windowed attention -> battn [T, 128]
            attn_kernel<<<dim3(576, BB, NHEAD), 64>>>(bq, bkv, relb + (size_t)d * 225 * NHEAD,
                                                      battn, shift);
            // x1 = x + LN(attn @ pWm + pbm)   (proj+mW fused; LN+residual in epilogue)
            mgemm_ln<<<gM1, 256>>>(battn, bpwm, bpbm, bx, n1g + d * CC, n1b + d * CC, bx1, CC);
            // h = gelu(x1 @ f1W + f1b)
            mgemm<2><<<gM4, 256>>>(bx1, f1W + (size_t)d * CC * HID, f1b + d * HID, bh, HID, CC, 1.f);
            // dest = x1 + LN(h @ f2W + f2b)
            mgemm_ln<<<gM1, 256>>>(bh, f2W + (size_t)d * HID * CC, f2b + d * CC, bx1,
                                   n2g + d * CC, n2b + d * CC, dest, HID);
        }
        // conv([sa; ta]) + bias + PReLU -> new x (NHWC), tensor-core implicit GEMM
        repack_w<<<(CONVK * CC + 255) / 256, 256>>>(convW + (size_t)d * CC * 256 * 9, bwg);
        conv_igemm<<<dim3(1, NTOK / 128), 256>>>(bsa, bta, bwg, convb + d * CC, pa + d * CC, bx);
    }

    t_nhwc2nchw<<<gT, 256>>>(bx, (float*)d_out);
}

// round 14
// speedup vs baseline: 6.3148x; 1.0549x over previous
#include <cuda_runtime.h>
#include <math.h>
#include <stdint.h>

// ---------------------------------------------------------------------------
// Problem constants
// ---------------------------------------------------------------------------
#define BB 2
#define CC 128
#define HH 192
#define WW2 192
#define NHEAD 4
#define HD 32
#define WS 8
#define NTOK 73728           // B*H*W
#define NPIX 36864           // H*W
#define HID 512
#define EPS_V 1e-5f
#define CONVK 2304           // 9 taps * 2 halves * 128 ic
#define SMS 136              // B smem row stride (conflict-free b-frag reads)

// ---------------------------------------------------------------------------
// Scratch buffers (device globals; allocation-free)
// ---------------------------------------------------------------------------
__device__ float g_x   [NTOK * CC];
__device__ float g_src [NTOK * CC];
__device__ float g_tgt [NTOK * CC];
__device__ float g_q   [NTOK * CC];
__device__ float g_kv  [NTOK * 2 * CC];
__device__ float g_attn[NTOK * CC];
__device__ float g_x1  [NTOK * CC];
__device__ float g_h   [NTOK * HID];
__device__ float g_sa  [NTOK * CC];
__device__ float g_ta  [NTOK * CC];
__device__ float g_wg  [CONVK * CC];   // repacked conv weights [K, OC] (tf32-rounded)
__device__ float g_pwm [CC * CC];      // fused pW @ mW (tf32-rounded)
__device__ float g_pbm [CC];           // fused pb @ mW (exact)
__device__ float g_wq  [CC * CC];      // tf32-rounded qW
__device__ float g_wkv [CC * 2 * CC];  // tf32-rounded kvW
__device__ float g_wf1 [CC * HID];     // tf32-rounded f1W
__device__ float g_wf2 [HID * CC];     // tf32-rounded f2W

// ---------------------------------------------------------------------------
// tf32 / cp.async helpers
// ---------------------------------------------------------------------------
__device__ __forceinline__ float to_tf32(float x) {
    float r;
    asm("cvt.rna.tf32.f32 %0, %1;" : "=f"(r) : "f"(x));
    return r;
}
__device__ __forceinline__ void cvt4(float4& v) {
    v.x = to_tf32(v.x); v.y = to_tf32(v.y); v.z = to_tf32(v.z); v.w = to_tf32(v.w);
}
__device__ __forceinline__ void mma8(float* d, const float* a, const float* b) {
    asm volatile(
        "mma.sync.aligned.m16n8k8.row.col.f32.tf32.tf32.f32 "
        "{%0,%1,%2,%3}, {%4,%5,%6,%7}, {%8,%9}, {%0,%1,%2,%3};\n"
        : "+f"(d[0]), "+f"(d[1]), "+f"(d[2]), "+f"(d[3])
        : "r"(__float_as_uint(a[0])), "r"(__float_as_uint(a[1])),
          "r"(__float_as_uint(a[2])), "r"(__float_as_uint(a[3])),
          "r"(__float_as_uint(b[0])), "r"(__float_as_uint(b[1])));
}
#define CP_ASYNC16(dst_u32, src_ptr)                                           \
    asm volatile("cp.async.cg.shared.global [%0], [%1], 16;\n"                 \
                 :: "r"(dst_u32), "l"(src_ptr))
#define CP_COMMIT  asm volatile("cp.async.commit_group;\n" ::: "memory")
#define CP_WAIT0   asm volatile("cp.async.wait_group 0;\n" ::: "memory")

// ---------------------------------------------------------------------------
// Layout transforms (32x32 smem tiles, coalesced both sides)
// ---------------------------------------------------------------------------
__global__ void t_nchw2nhwc(const float* __restrict__ in, float* __restrict__ out) {
    __shared__ float tile[32][33];
    const int b = blockIdx.z;
    const int c0 = blockIdx.y * 32, p0 = blockIdx.x * 32;
    const int tr = threadIdx.x >> 5, tc = threadIdx.x & 31;
#pragma unroll
    for (int i = 0; i < 32; i += 8)
        tile[tr + i][tc] = in[((size_t)b * CC + c0 + tr + i) * NPIX + p0 + tc];
    __syncthreads();
#pragma unroll
    for (int i = 0; i < 32; i += 8)
        out[((size_t)b * NPIX + p0 + tr + i) * CC + c0 + tc] = tile[tc][tr + i];
}

__global__ void t_nhwc2nchw(const float* __restrict__ in, float* __restrict__ out) {
    __shared__ float tile[32][33];
    const int b = blockIdx.z;
    const int c0 = blockIdx.y * 32, p0 = blockIdx.x * 32;
    const int tr = threadIdx.x >> 5, tc = threadIdx.x & 31;
#pragma unroll
    for (int i = 0; i < 32; i += 8)
        tile[tr + i][tc] = in[((size_t)b * NPIX + p0 + tr + i) * CC + c0 + tc];
    __syncthreads();
#pragma unroll
    for (int i = 0; i < 32; i += 8)
        out[((size_t)b * CC + c0 + tr + i) * NPIX + p0 + tc] = tile[tc][tr + i];
}

// ---------------------------------------------------------------------------
// Weight prep
// ---------------------------------------------------------------------------
__global__ void round_copy(const float* __restrict__ src, float* __restrict__ dst, int n) {
    int i = blockIdx.x * 256 + threadIdx.x;
    if (i < n) dst[i] = to_tf32(src[i]);
}

// Conv weight repack: OIHW [128, 256, 3, 3] -> [K=2304, OC=128], tf32-rounded
__global__ void repack_w(const float* __restrict__ convW, float* __restrict__ wg) {
    int idx = blockIdx.x * blockDim.x + threadIdx.x;
    if (idx >= CONVK * CC) return;
    int oc = idx % CC;
    int k  = idx / CC;
    int tap = k >> 8;
    int cin = k & 255;
    int ky = tap / 3, kx = tap % 3;
    wg[idx] = to_tf32(convW[(((size_t)oc * 256 + cin) * 3 + ky) * 3 + kx]);
}

// exact fp32 fused projection: blocks 0..127 -> pwm rows (tf32-rounded); 128 -> pbm
__global__ void fuse_pwm_bias(const float* __restrict__ pW, const float* __restrict__ pb,
                              const float* __restrict__ mW, float* __restrict__ pwm,
                              float* __restrict__ pbm) {
    __shared__ float arow[CC];
    const int i = blockIdx.x, j = threadIdx.x;
    arow[j] = (i < CC) ? pW[i * CC + j] : pb[j];
    __syncthreads();
    float s = 0.f;
    for (int k = 0; k < CC; k++) s += arow[k] * mW[k * CC + j];
    if (i < CC) pwm[i * CC + j] = to_tf32(s);
    else pbm[j] = s;
}

// ---------------------------------------------------------------------------
// tf32 tensor-core GEMM core. BM=BN=128, BK=16, 256 thr, warps 2(m) x 4(n),
// warp tile 64x32 (m16n8k8). A staged register->smem in FRAGMENT-MAJOR layout
// (XOR-swizzled; one LDS.128 per a-frag). B via cp.async from pre-rounded
// tf32 weights. Pipeline order per chunk: wait -> sync -> issue next copies
// -> compute -> stage next A. (cp.async issue strictly after the barrier
// that retires all reads of its destination buffer.)
// ---------------------------------------------------------------------------
#define MG_PROLOG                                                              \
    const int tid = threadIdx.x;                                               \
    const int lane = tid & 31;                                                 \
    const int g = lane >> 2, tg = lane & 3;                                    \
    const int wid = tid >> 5;                                                  \
    const int r0 = (wid & 1) * 64;                                             \
    const int c0 = (wid >> 1) * 32;                                            \
    const int arow = tid >> 1, acol = (tid & 1) * 8;                           \
    const int brow = tid >> 4, bcol = (tid & 15) * 8;                          \
    const int x7 = arow & 7;                                                   \
    const int S0 = ((x7 << 2) ^ x7);                                           \
    const int regb = (arow >> 3) & 1;                                          \
    const int atile = ((tid & 1) << 3) + (arow >> 4);                          \
    const int lswz = (lane ^ ((lane >> 2) & 7)) << 2;                          \
    float acc[4][4][4];                                                        \
    _Pragma("unroll")                                                          \
    for (int mf = 0; mf < 4; mf++)                                             \
        _Pragma("unroll")                                                      \
        for (int nf = 0; nf < 4; nf++)                                         \
            _Pragma("unroll")                                                  \
            for (int r = 0; r < 4; r++) acc[mf][nf][r] = 0.f;                  \
    uint32_t bsm[2];                                                           \
    bsm[0] = (uint32_t)__cvta_generic_to_shared(&Bs[0][brow][bcol]);           \
    bsm[1] = (uint32_t)__cvta_generic_to_shared(&Bs[1][brow][bcol]);

// store A regs (8 tf32 values of row arow, k-halves acol..acol+7) frag-major
#define MG_STSA(buf)                                                           \
    {                                                                          \
        float* At = &Asf[buf][atile * 128];                                    \
        At[((S0 ^ 0) << 2) + regb]     = ra0.x;                                \
        At[((S0 ^ 1) << 2) + regb]     = ra0.y;                                \
        At[((S0 ^ 2) << 2) + regb]     = ra0.z;                                \
        At[((S0 ^ 3) << 2) + regb]     = ra0.w;                                \
        At[((S0 ^ 0) << 2) + regb + 2] = ra1.x;                                \
        At[((S0 ^ 1) << 2) + regb + 2] = ra1.y;                                \
        At[((S0 ^ 2) << 2) + regb + 2] = ra1.z;                                \
        At[((S0 ^ 3) << 2) + regb + 2] = ra1.w;                                \
    }

#define MG_COMPUTE(buf)                                                        \
    {                                                                          \
        _Pragma("unroll")                                                      \
        for (int ks = 0; ks < 16; ks += 8) {                                   \
            float4 a4[4];                                                      \
            _Pragma("unroll")                                                  \
            for (int mf = 0; mf < 4; mf++)                                     \
                a4[mf] = *(const float4*)&Asf[buf][(ks + (wid & 1) * 4 + mf) * 128 + lswz]; \
            float b[4][2];                                                     \
            _Pragma("unroll")                                                  \
            for (int nf = 0; nf < 4; nf++) {                                   \
                b[nf][0] = Bs[buf][ks + tg][c0 + nf * 8 + g];                  \
                b[nf][1] = Bs[buf][ks + tg + 4][c0 + nf * 8 + g];              \
            }                                                                  \
            _Pragma("unroll")                                                  \
            for (int mf = 0; mf < 4; mf++)                                     \
                _Pragma("unroll")                                              \
                for (int nf = 0; nf < 4; nf++)                                 \
                    mma8(acc[mf][nf], (const float*)&a4[mf], b[nf]);           \
        }                                                                      \
    }

// A LDG + cvt (activations, rna-rounded at load)
#define MG_LDGA(c)                                                             \
    {                                                                          \
        const int k0 = (c) * 16;                                               \
        ra0 = *(const float4*)(Ablk + (size_t)arow * K + k0 + acol);           \
        ra1 = *(const float4*)(Ablk + (size_t)arow * K + k0 + acol + 4);       \
        cvt4(ra0); cvt4(ra1);                                                  \
    }
// B cp.async (pre-rounded weights)
#define MG_CPB(c, buf)                                                         \
    {                                                                          \
        const float* wsrc = Wblk + (size_t)((c) * 16 + brow) * N + bcol;       \
        CP_ASYNC16(bsm[buf], wsrc);                                            \
        CP_ASYNC16(bsm[buf] + 16, wsrc + 4);                                   \
        CP_COMMIT;                                                             \
    }

#define MG_MAINLOOP(LDGA_MACRO, CPB_MACRO)                                     \
    {                                                                          \
        LDGA_MACRO(0); CPB_MACRO(0, 0); MG_STSA(0);                            \
        for (int c = 0; c < nc; c++) {                                         \
            const int cur = c & 1;                                             \
            CP_WAIT0;               /* own group c complete */                 \
            __syncthreads();        /* all reads of buf cur^1 retired */       \
            if (c + 1 < nc) {                                                  \
                LDGA_MACRO(c + 1);                                             \
                CPB_MACRO(c + 1, cur ^ 1);                                     \
            }                                                                  \
            MG_COMPUTE(cur);                                                   \
            if (c + 1 < nc) MG_STSA(cur ^ 1);                                  \
        }                                                                      \
    }

// ---------------------------------------------------------------------------
// mgemm: C = epi(A @ W); EPI 0:*scale 1:(+bias)*scale 2:gelu(+bias)
// ---------------------------------------------------------------------------
template <int EPI>
__global__ void __launch_bounds__(256, 2)
mgemm(const float* __restrict__ A, const float* __restrict__ W,
      const float* __restrict__ bias, float* __restrict__ C,
      int N, int K, float scale) {
    __shared__ float Asf[2][2048];
    __shared__ float Bs[2][16][SMS];
    MG_PROLOG
    const int bx = blockIdx.x, by = blockIdx.y;
    const float* Ablk = A + (size_t)by * 128 * K;
    const float* Wblk = W + (size_t)bx * 128;
    const int nc = K / 16;
    float4 ra0, ra1;
    MG_MAINLOOP(MG_LDGA, MG_CPB)

#pragma unroll
    for (int nf = 0; nf < 4; nf++) {
        const int col = bx * 128 + c0 + nf * 8 + 2 * tg;
        float bv0 = 0.f, bv1 = 0.f;
        if (EPI >= 1) { bv0 = bias[col]; bv1 = bias[col + 1]; }
#pragma unroll
        for (int mf = 0; mf < 4; mf++) {
            const int row = by * 128 + r0 + mf * 16 + g;
            float d0 = acc[mf][nf][0], d1 = acc[mf][nf][1];
            float d2 = acc[mf][nf][2], d3 = acc[mf][nf][3];
            if (EPI >= 1) { d0 += bv0; d1 += bv1; d2 += bv0; d3 += bv1; }
            d0 *= scale; d1 *= scale; d2 *= scale; d3 *= scale;
            if (EPI == 2) {
                d0 = d0 * normcdff(d0); d1 = d1 * normcdff(d1);
                d2 = d2 * normcdff(d2); d3 = d3 * normcdff(d3);
            }
            *(float2*)(C + (size_t)row * N + col)       = make_float2(d0, d1);
            *(float2*)(C + (size_t)(row + 8) * N + col) = make_float2(d2, d3);
        }
    }
}

// ---------------------------------------------------------------------------
// mgemm_ln: out = sc + LN(A@W + bias)*gamma + beta   (N == 128, grid.x == 1)
// ---------------------------------------------------------------------------
__global__ void __launch_bounds__(256, 2)
mgemm_ln(const float* __restrict__ A, const float* __restrict__ W,
         const float* __restrict__ bias, const float* __restrict__ sc,
         const float* __restrict__ gamma, const float* __restrict__ beta,
         float* __restrict__ out, int K) {
    __shared__ float Asf[2][2048];
    __shared__ float Bs[2][16][SMS];
    __shared__ float redS[128][4][2];
    MG_PROLOG
    const int by = blockIdx.y;
    const float* Ablk = A + (size_t)by * 128 * K;
    const float* Wblk = W;
    const int N = 128;
    const int nc = K / 16;
    const int wq = wid >> 1;
    float4 ra0, ra1;
    MG_MAINLOOP(MG_LDGA, MG_CPB)

#pragma unroll
    for (int nf = 0; nf < 4; nf++) {
        const float2 bv = *(const float2*)&bias[c0 + nf * 8 + 2 * tg];
#pragma unroll
        for (int mf = 0; mf < 4; mf++) {
            acc[mf][nf][0] += bv.x; acc[mf][nf][1] += bv.y;
            acc[mf][nf][2] += bv.x; acc[mf][nf][3] += bv.y;
        }
    }

#pragma unroll
    for (int mf = 0; mf < 4; mf++) {
        float s1A = 0.f, s2A = 0.f, s1B = 0.f, s2B = 0.f;
#pragma unroll
        for (int nf = 0; nf < 4; nf++) {
            s1A += acc[mf][nf][0] + acc[mf][nf][1];
            s2A += acc[mf][nf][0] * acc[mf][nf][0] + acc[mf][nf][1] * acc[mf][nf][1];
            s1B += acc[mf][nf][2] + acc[mf][nf][3];
            s2B += acc[mf][nf][2] * acc[mf][nf][2] + acc[mf][nf][3] * acc[mf][nf][3];
        }
#pragma unroll
        for (int m = 1; m <= 2; m <<= 1) {
            s1A += __shfl_xor_sync(0xffffffffu, s1A, m);
            s2A += __shfl_xor_sync(0xffffffffu, s2A, m);
            s1B += __shfl_xor_sync(0xffffffffu, s1B, m);
            s2B += __shfl_xor_sync(0xffffffffu, s2B, m);
        }
        if (tg == 0) {
            const int rA = r0 + mf * 16 + g;
            redS[rA][wq][0] = s1A;     redS[rA][wq][1] = s2A;
            redS[rA + 8][wq][0] = s1B; redS[rA + 8][wq][1] = s2B;
        }
    }
    __syncthreads();

    float gj[4][2], bj[4][2];
#pragma unroll
    for (int nf = 0; nf < 4; nf++) {
        const int col = c0 + nf * 8 + 2 * tg;
        *(float2*)gj[nf] = *(const float2*)&gamma[col];
        *(float2*)bj[nf] = *(const float2*)&beta[col];
    }
#pragma unroll
    for (int mf = 0; mf < 4; mf++) {
        const int rA = r0 + mf * 16 + g;
        float s1A = redS[rA][0][0] + redS[rA][1][0] + redS[rA][2][0] + redS[rA][3][0];
        float s2A = redS[rA][0][1] + redS[rA][1][1] + redS[rA][2][1] + redS[rA][3][1];
        float s1B = redS[rA + 8][0][0] + redS[rA + 8][1][0] + redS[rA + 8][2][0] + redS[rA + 8][3][0];
        float s2B = redS[rA + 8][0][1] + redS[rA + 8][1][1] + redS[rA + 8][2][1] + redS[rA + 8][3][1];
        const float muA = s1A * (1.f / 128.f);
        const float rsA = rsqrtf(s2A * (1.f / 128.f) - muA * muA + EPS_V);
        const float muB = s1B * (1.f / 128.f);
        const float rsB = rsqrtf(s2B * (1.f / 128.f) - muB * muB + EPS_V);
        const int rowA = by * 128 + rA;
#pragma unroll
        for (int nf = 0; nf < 4; nf++) {
            const int col = c0 + nf * 8 + 2 * tg;
            float2 scA = *(const float2*)(sc + (size_t)rowA * N + col);
            float2 scB = *(const float2*)(sc + (size_t)(rowA + 8) * N + col);
            float o0 = scA.x + (acc[mf][nf][0] - muA) * rsA * gj[nf][0] + bj[nf][0];
            float o1 = scA.y + (acc[mf][nf][1] - muA) * rsA * gj[nf][1] + bj[nf][1];
            float o2 = scB.x + (acc[mf][nf][2] - muB) * rsB * gj[nf][0] + bj[nf][0];
            float o3 = scB.y + (acc[mf][nf][3] - muB) * rsB * gj[nf][1] + bj[nf][1];
            *(float2*)(out + (size_t)rowA * N + col)       = make_float2(o0, o1);
            *(float2*)(out + (size_t)(rowA + 8) * N + col) = make_float2(o2, o3);
        }
    }
}

// ---------------------------------------------------------------------------
// Conv implicit GEMM (K=2304); epilogue bias + PReLU.
// ---------------------------------------------------------------------------
__global__ void __launch_bounds__(256, 2)
conv_igemm(const float* __restrict__ sa, const float* __restrict__ ta,
           const float* __restrict__ Wg, const float* __restrict__ bias,
           const float* __restrict__ pa, float* __restrict__ out) {
    __shared__ float Asf[2][2048];
    __shared__ float Bs[2][16][SMS];
    MG_PROLOG
    const int by = blockIdx.y;
    const int pixel = by * 128 + arow;
    const int xcrd = pixel % WW2;
    const int ycrd = (pixel / WW2) % HH;
    const int nc = CONVK / 16;   // 144
    const float* Wblk = Wg;
    const int N = CC;
    float4 ra0, ra1;

#define CV_LDGA(c)                                                             \
    {                                                                          \
        const int k0 = (c) * 16;                                               \
        const int tap  = k0 >> 8;                                              \
        const int rem  = k0 & 255;                                             \
        const int half = rem >> 7;                                             \
        const int ic0  = (rem & 127) + acol;                                   \
        const int dy = tap / 3 - 1, dx = tap % 3 - 1;                          \
        const int ys = ycrd + dy, xs = xcrd + dx;                              \
        const bool valid = ((unsigned)ys < HH) && ((unsigned)xs < WW2);        \
        const float* src = half ? ta : sa;                                     \
        const float* ap = src + ((size_t)pixel + dy * WW2 + dx) * CC + ic0;    \
        ra0 = make_float4(0.f, 0.f, 0.f, 0.f); ra1 = ra0;                      \
        if (valid) { ra0 = *(const float4*)ap; ra1 = *(const float4*)(ap + 4); } \
        cvt4(ra0); cvt4(ra1);                                                  \
    }

    MG_MAINLOOP(CV_LDGA, MG_CPB)

#pragma unroll
    for (int nf = 0; nf < 4; nf++) {
        const int col = c0 + nf * 8 + 2 * tg;
        const float bv0 = bias[col], bv1 = bias[col + 1];
        const float pv0 = pa[col],   pv1 = pa[col + 1];
#pragma unroll
        for (int mf = 0; mf < 4; mf++) {
            const int row = by * 128 + r0 + mf * 16 + g;
            float d0 = acc[mf][nf][0] + bv0, d1 = acc[mf][nf][1] + bv1;
            float d2 = acc[mf][nf][2] + bv0, d3 = acc[mf][nf][3] + bv1;
            if (d0 < 0.f) d0 *= pv0;
            if (d1 < 0.f) d1 *= pv1;
            if (d2 < 0.f) d2 *= pv0;
            if (d3 < 0.f) d3 *= pv1;
            *(float2*)(out + (size_t)row * CC + col)       = make_float2(d0, d1);
            *(float2*)(out + (size_t)(row + 8) * CC + col) = make_float2(d2, d3);
        }
    }
}

// ---------------------------------------------------------------------------
// Windowed attention (exact fp32; gathers through shift mapping).
// ---------------------------------------------------------------------------
__device__ __forceinline__ int region_label(int h, int w) {
    int rh = (h < HH - WS) ? 0 : ((h < HH - WS / 2) ? 1 : 2);
    int rw = (w < WW2 - WS) ? 0 : ((w < WW2 - WS / 2) ? 1 : 2);
    return rh * 3 + rw;
}

__global__ void attn_kernel(const float* __restrict__ q, const float* __restrict__ kv,
                            const float* __restrict__ relb, float* __restrict__ out,
                            int shift) {
    const int win = blockIdx.x;
    const int b   = blockIdx.y;
    const int h   = blockIdx.z;
    const int gy = win / (WW2 / WS), gx = win % (WW2 / WS);
    const int t  = threadIdx.x;
    const int ty = t >> 3, tx = t & 7;

    __shared__ float ks[64][36];
    __shared__ float vs[64][36];

    const int py = (gy * WS + ty + shift) % HH;
    const int px = (gx * WS + tx + shift) % WW2;
    const size_t pix = ((size_t)b * HH + py) * WW2 + px;

    const float4* kvrow = (const float4*)(kv + pix * (2 * CC) + h * HD);
    const float4* vvrow = (const float4*)(kv + pix * (2 * CC) + CC + h * HD);
#pragma unroll
    for (int d4 = 0; d4 < HD / 4; d4++) {
        *(float4*)&ks[t][d4 * 4] = kvrow[d4];
        *(float4*)&vs[t][d4 * 4] = vvrow[d4];
    }
    float4 qr[HD / 4];
    const float4* qrow = (const float4*)(q + pix * CC + h * HD);
#pragma unroll
    for (int d4 = 0; d4 < HD / 4; d4++) qr[d4] = qrow[d4];
    __syncthreads();

    int li = 0;
    if (shift) li = region_label(gy * WS + ty, gx * WS + tx);

    float s[64];
    float mx = -1e30f;
#pragma unroll
    for (int j = 0; j < 64; j++) {
        float acc = 0.f;
        const float4* kr = (const float4*)&ks[j][0];
#pragma unroll
        for (int d4 = 0; d4 < HD / 4; d4++) {
            float4 kk = kr[d4];
            acc += qr[d4].x * kk.x + qr[d4].y * kk.y + qr[d4].z * kk.z + qr[d4].w * kk.w;
        }
        int jy = j >> 3, jx = j & 7;
        acc += relb[((ty - jy + WS - 1) * (2 * WS - 1) + (tx - jx + WS - 1)) * NHEAD + h];
        if (shift) {
            int lj = region_label(gy * WS + jy, gx * WS + jx);
            if (lj != li) acc -= 100.0f;
        }
        s[j] = acc;
        mx = fmaxf(mx, acc);
    }
    float sum = 0.f;
#pragma unroll
    for (int j = 0; j < 64; j++) { s[j] = expf(s[j] - mx); sum += s[j]; }
    const float inv = 1.0f / sum;

    float4 o4[HD / 4];
#pragma unroll
    for (int d4 = 0; d4 < HD / 4; d4++) o4[d4] = make_float4(0.f, 0.f, 0.f, 0.f);
#pragma unroll
    for (int j = 0; j < 64; j++) {
        const float sj = s[j];
        const float4* vr = (const float4*)&vs[j][0];
#pragma unroll
        for (int d4 = 0; d4 < HD / 4; d4++) {
            float4 vv = vr[d4];
            o4[d4].x += sj * vv.x; o4[d4].y += sj * vv.y;
            o4[d4].z += sj * vv.z; o4[d4].w += sj * vv.w;
        }
    }
    float4* orow = (float4*)(out + pix * CC + h * HD);
#pragma unroll
    for (int d4 = 0; d4 < HD / 4; d4++) {
        float4 o = o4[d4];
        o.x *= inv; o.y *= inv; o.z *= inv; o.w *= inv;
        orow[d4] = o;
    }
}

// ---------------------------------------------------------------------------
// Host driver (graph-capturable: launches only)
// ---------------------------------------------------------------------------
template <typename T>
static float* sym(const T& s) {
    void* p = nullptr;
    cudaGetSymbolAddress(&p, s);
    return (float*)p;
}

extern "C" void kernel_launch(void* const* d_in, const int* in_sizes, int n_in,
                              void* d_out, int out_size) {
    const float* x      = (const float*)d_in[0];
    const float* source = (const float*)d_in[1];
    const float* target = (const float*)d_in[2];
    const float* qW     = (const float*)d_in[3];
    const float* qb     = (const float*)d_in[4];
    const float* kvW    = (const float*)d_in[5];
    const float* kvb    = (const float*)d_in[6];
    const float* pW     = (const float*)d_in[7];
    const float* pb     = (const float*)d_in[8];
    const float* relb   = (const float*)d_in[9];
    const float* mW     = (const float*)d_in[10];
    const float* n1g    = (const float*)d_in[11];
    const float* n1b    = (const float*)d_in[12];
    const float* f1W    = (const float*)d_in[13];
    const float* f1b    = (const float*)d_in[14];
    const float* f2W    = (const float*)d_in[15];
    const float* f2b    = (const float*)d_in[16];
    const float* n2g    = (const float*)d_in[17];
    const float* n2b    = (const float*)d_in[18];
    const float* convW  = (const float*)d_in[19];
    const float* convb  = (const float*)d_in[20];
    const float* pa     = (const float*)d_in[21];

    float* bx    = sym(g_x);
    float* bsrc  = sym(g_src);
    float* btgt  = sym(g_tgt);
    float* bq    = sym(g_q);
    float* bkv   = sym(g_kv);
    float* battn = sym(g_attn);
    float* bx1   = sym(g_x1);
    float* bh    = sym(g_h);
    float* bsa   = sym(g_sa);
    float* bta   = sym(g_ta);
    float* bwg   = sym(g_wg);
    float* bpwm  = sym(g_pwm);
    float* bpbm  = sym(g_pbm);
    float* bwq   = sym(g_wq);
    float* bwkv  = sym(g_wkv);
    float* bwf1  = sym(g_wf1);
    float* bwf2  = sym(g_wf2);

    const float SCALE = 0.1767766952966369f;   // 32^-0.5
    const dim3 gT(NPIX / 32, CC / 32, BB);
    const dim3 gM1(1, NTOK / 128), gM2(2, NTOK / 128), gM4(4, NTOK / 128);

    t_nchw2nhwc<<<gT, 256>>>(x, bx);
    t_nchw2nhwc<<<gT, 256>>>(source, bsrc);
    t_nchw2nhwc<<<gT, 256>>>(target, btgt);

    for (int d = 0; d < 2; d++) {
        const int shift = (d % 2) ? (WS / 2) : 0;

        // weight prep: tf32-round weight matrices once per depth
        round_copy<<<(CC * CC + 255) / 256, 256>>>(qW + (size_t)d * CC * CC, bwq, CC * CC);
        round_copy<<<(CC * 2 * CC + 255) / 256, 256>>>(kvW + (size_t)d * CC * 2 * CC, bwkv, CC * 2 * CC);
        round_copy<<<(CC * HID + 255) / 256, 256>>>(f1W + (size_t)d * CC * HID, bwf1, CC * HID);
        round_copy<<<(HID * CC + 255) / 256, 256>>>(f2W + (size_t)d * HID * CC, bwf2, HID * CC);
        fuse_pwm_bias<<<CC + 1, CC>>>(pW + (size_t)d * CC * CC, pb + d * CC,
                                      mW + (size_t)d * CC * CC, bpwm, bpbm);
        repack_w<<<(CONVK * CC + 255) / 256, 256>>>(convW + (size_t)d * CC * 256 * 9, bwg);

        // q = (x @ qW + qb) * scale   (shared by both branches)
        mgemm<1><<<gM1, 256>>>(bx, bwq, qb + d * CC, bq, CC, CC, SCALE);

        for (int br = 0; br < 2; br++) {
            const float* feat = br ? btgt : bsrc;
            float* dest = br ? bta : bsa;
            // kv = feat @ kvW + kvb   [T, 256]
            mgemm<1><<<gM2, 256>>>(feat, bwkv, kvb + d * 2 * CC, bkv, 2 * CC, CC, 1.f);
            // windowed attention -> battn [T, 128]
            attn_kernel<<<dim3(576, BB, NHEAD), 64>>>(bq, bkv, relb + (size_t)d * 225 * NHEAD,
                                                      battn, shift);
            // x1 = x + LN(attn @ pWm + pbm)
            mgemm_ln<<<gM1, 256>>>(battn, bpwm, bpbm, bx, n1g + d * CC, n1b + d * CC, bx1, CC);
            // h = gelu(x1 @ f1W + f1b)
            mgemm<2><<<gM4, 256>>>(bx1, bwf1, f1b + d * HID, bh, HID, CC, 1.f);
            // dest = x1 + LN(h @ f2W + f2b)
            mgemm_ln<<<gM1, 256>>>(bh, bwf2, f2b + d * CC, bx1,
                                   n2g + d * CC, n2b + d * CC, dest, HID);
        }
        // conv([sa; ta]) + bias + PReLU -> new x (NHWC)
        conv_igemm<<<dim3(1, NTOK / 128), 256>>>(bsa, bta, bwg, convb + d * CC, pa + d * CC, bx);
    }

    t_nhwc2nchw<<<gT, 256>>>(bx, (float*)d_out);
}

// round 15
// speedup vs baseline: 6.5744x; 1.0411x over previous
#include <cuda_runtime.h>
#include <math.h>
#include <stdint.h>

// ---------------------------------------------------------------------------
// Problem constants
// ---------------------------------------------------------------------------
#define BB 2
#define CC 128
#define HH 192
#define WW2 192
#define NHEAD 4
#define HD 32
#define WS 8
#define NTOK 73728           // B*H*W
#define NPIX 36864           // H*W
#define HID 512
#define EPS_V 1e-5f
#define CONVK 2304           // 9 taps * 2 halves * 128 ic
#define SMS 136              // B smem row stride (conflict-free b-frag reads)

// ---------------------------------------------------------------------------
// Scratch buffers (device globals; allocation-free). [2]-indexed = per branch.
// ---------------------------------------------------------------------------
__device__ float g_x   [NTOK * CC];
__device__ float g_st  [2 * NTOK * CC];       // src | tgt
__device__ float g_q   [NTOK * CC];
__device__ float g_kv  [2 * NTOK * 2 * CC];
__device__ float g_attn[2 * NTOK * CC];
__device__ float g_x1  [2 * NTOK * CC];
__device__ float g_h   [2 * NTOK * HID];
__device__ float g_br  [2 * NTOK * CC];       // sa | ta
__device__ float g_wg  [2 * CONVK * CC];      // repacked conv weights (tf32)
__device__ float g_pwm [2 * CC * CC];         // fused pW @ mW (tf32)
__device__ float g_pbm [2 * CC];              // fused pb @ mW (exact)
__device__ float g_wq  [2 * CC * CC];
__device__ float g_wkv [2 * CC * 2 * CC];
__device__ float g_wf1 [2 * CC * HID];
__device__ float g_wf2 [2 * HID * CC];

// ---------------------------------------------------------------------------
// tf32 / cp.async helpers
// ---------------------------------------------------------------------------
__device__ __forceinline__ float to_tf32(float x) {
    float r;
    asm("cvt.rna.tf32.f32 %0, %1;" : "=f"(r) : "f"(x));
    return r;
}
__device__ __forceinline__ void cvt4(float4& v) {
    v.x = to_tf32(v.x); v.y = to_tf32(v.y); v.z = to_tf32(v.z); v.w = to_tf32(v.w);
}
__device__ __forceinline__ void mma8(float* d, const float* a, const float* b) {
    asm volatile(
        "mma.sync.aligned.m16n8k8.row.col.f32.tf32.tf32.f32 "
        "{%0,%1,%2,%3}, {%4,%5,%6,%7}, {%8,%9}, {%0,%1,%2,%3};\n"
        : "+f"(d[0]), "+f"(d[1]), "+f"(d[2]), "+f"(d[3])
        : "r"(__float_as_uint(a[0])), "r"(__float_as_uint(a[1])),
          "r"(__float_as_uint(a[2])), "r"(__float_as_uint(a[3])),
          "r"(__float_as_uint(b[0])), "r"(__float_as_uint(b[1])));
}
#define CP_ASYNC16(dst_u32, src_ptr)                                           \
    asm volatile("cp.async.cg.shared.global [%0], [%1], 16;\n"                 \
                 :: "r"(dst_u32), "l"(src_ptr))
#define CP_COMMIT  asm volatile("cp.async.commit_group;\n" ::: "memory")
#define CP_WAIT0   asm volatile("cp.async.wait_group 0;\n" ::: "memory")

// ---------------------------------------------------------------------------
// Layout transforms (32x32 smem tiles, coalesced both sides)
// ---------------------------------------------------------------------------
__global__ void t_nchw2nhwc(const float* __restrict__ in, float* __restrict__ out) {
    __shared__ float tile[32][33];
    const int b = blockIdx.z;
    const int c0 = blockIdx.y * 32, p0 = blockIdx.x * 32;
    const int tr = threadIdx.x >> 5, tc = threadIdx.x & 31;
#pragma unroll
    for (int i = 0; i < 32; i += 8)
        tile[tr + i][tc] = in[((size_t)b * CC + c0 + tr + i) * NPIX + p0 + tc];
    __syncthreads();
#pragma unroll
    for (int i = 0; i < 32; i += 8)
        out[((size_t)b * NPIX + p0 + tr + i) * CC + c0 + tc] = tile[tc][tr + i];
}

__global__ void t_nhwc2nchw(const float* __restrict__ in, float* __restrict__ out) {
    __shared__ float tile[32][33];
    const int b = blockIdx.z;
    const int c0 = blockIdx.y * 32, p0 = blockIdx.x * 32;
    const int tr = threadIdx.x >> 5, tc = threadIdx.x & 31;
#pragma unroll
    for (int i = 0; i < 32; i += 8)
        tile[tr + i][tc] = in[((size_t)b * NPIX + p0 + tr + i) * CC + c0 + tc];
    __syncthreads();
#pragma unroll
    for (int i = 0; i < 32; i += 8)
        out[((size_t)b * CC + c0 + tr + i) * NPIX + p0 + tc] = tile[tc][tr + i];
}

// ---------------------------------------------------------------------------
// Mega weight prep: tf32-round all GEMM weights (both depths) + repack conv.
// Flat-index dispatch over segments.
// ---------------------------------------------------------------------------
#define NQ_  (2 * CC * CC)
#define NKV_ (2 * CC * 2 * CC)
#define NF1_ (2 * CC * HID)
#define NF2_ (2 * HID * CC)
#define NCV_ (2 * CONVK * CC)
#define NPREP (NQ_ + NKV_ + NF1_ + NF2_ + NCV_)

__global__ void prep_all(const float* __restrict__ qW, const float* __restrict__ kvW,
                         const float* __restrict__ f1W, const float* __restrict__ f2W,
                         const float* __restrict__ convW) {
    int i = blockIdx.x * 256 + threadIdx.x;
    if (i < NQ_) { g_wq[i] = to_tf32(qW[i]); return; }
    i -= NQ_;
    if (i < NKV_) { g_wkv[i] = to_tf32(kvW[i]); return; }
    i -= NKV_;
    if (i < NF1_) { g_wf1[i] = to_tf32(f1W[i]); return; }
    i -= NF1_;
    if (i < NF2_) { g_wf2[i] = to_tf32(f2W[i]); return; }
    i -= NF2_;
    if (i < NCV_) {
        const int d = i / (CONVK * CC);
        const int idx = i % (CONVK * CC);
        const int oc = idx % CC;
        const int k  = idx / CC;
        const int tap = k >> 8;
        const int cin = k & 255;
        const int ky = tap / 3, kx = tap % 3;
        g_wg[i] = to_tf32(convW[(size_t)d * CC * 256 * 9 +
                                (((size_t)oc * 256 + cin) * 3 + ky) * 3 + kx]);
    }
}

// exact fp32 fused projection; grid (129, 2 depths)
__global__ void fuse_pwm_bias(const float* __restrict__ pW, const float* __restrict__ pb,
                              const float* __restrict__ mW) {
    __shared__ float arow[CC];
    const int d = blockIdx.y;
    const int i = blockIdx.x, j = threadIdx.x;
    const float* pWd = pW + (size_t)d * CC * CC;
    const float* mWd = mW + (size_t)d * CC * CC;
    arow[j] = (i < CC) ? pWd[i * CC + j] : pb[d * CC + j];
    __syncthreads();
    float s = 0.f;
    for (int k = 0; k < CC; k++) s += arow[k] * mWd[k * CC + j];
    if (i < CC) g_pwm[(size_t)d * CC * CC + i * CC + j] = to_tf32(s);
    else g_pbm[d * CC + j] = s;
}

// ---------------------------------------------------------------------------
// tf32 tensor-core GEMM core (unchanged from R13 except z-batching).
// ---------------------------------------------------------------------------
#define MG_PROLOG                                                              \
    const int tid = threadIdx.x;                                               \
    const int lane = tid & 31;                                                 \
    const int g = lane >> 2, tg = lane & 3;                                    \
    const int wid = tid >> 5;                                                  \
    const int r0 = (wid & 1) * 64;                                             \
    const int c0 = (wid >> 1) * 32;                                            \
    const int arow = tid >> 1, acol = (tid & 1) * 8;                           \
    const int brow = tid >> 4, bcol = (tid & 15) * 8;                          \
    const int x7 = arow & 7;                                                   \
    const int S0 = ((x7 << 2) ^ x7);                                           \
    const int regb = (arow >> 3) & 1;                                          \
    const int atile = ((tid & 1) << 3) + (arow >> 4);                          \
    const int lswz = (lane ^ ((lane >> 2) & 7)) << 2;                          \
    float acc[4][4][4];                                                        \
    _Pragma("unroll")                                                          \
    for (int mf = 0; mf < 4; mf++)                                             \
        _Pragma("unroll")                                                      \
        for (int nf = 0; nf < 4; nf++)                                         \
            _Pragma("unroll")                                                  \
            for (int r = 0; r < 4; r++) acc[mf][nf][r] = 0.f;                  \
    uint32_t bsm[2];                                                           \
    bsm[0] = (uint32_t)__cvta_generic_to_shared(&Bs[0][brow][bcol]);           \
    bsm[1] = (uint32_t)__cvta_generic_to_shared(&Bs[1][brow][bcol]);

#define MG_STSA(buf)                                                           \
    {                                                                          \
        float* At = &Asf[buf][atile * 128];                                    \
        At[((S0 ^ 0) << 2) + regb]     = ra0.x;                                \
        At[((S0 ^ 1) << 2) + regb]     = ra0.y;                                \
        At[((S0 ^ 2) << 2) + regb]     = ra0.z;                                \
        At[((S0 ^ 3) << 2) + regb]     = ra0.w;                                \
        At[((S0 ^ 0) << 2) + regb + 2] = ra1.x;                                \
        At[((S0 ^ 1) << 2) + regb + 2] = ra1.y;                                \
        At[((S0 ^ 2) << 2) + regb + 2] = ra1.z;                                \
        At[((S0 ^ 3) << 2) + regb + 2] = ra1.w;                                \
    }

#define MG_COMPUTE(buf)                                                        \
    {                                                                          \
        _Pragma("unroll")                                                      \
        for (int ks = 0; ks < 16; ks += 8) {                                   \
            float4 a4[4];                                                      \
            _Pragma("unroll")                                                  \
            for (int mf = 0; mf < 4; mf++)                                     \
                a4[mf] = *(const float4*)&Asf[buf][(ks + (wid & 1) * 4 + mf) * 128 + lswz]; \
            float b[4][2];                                                     \
            _Pragma("unroll")                                                  \
            for (int nf = 0; nf < 4; nf++) {                                   \
                b[nf][0] = Bs[buf][ks + tg][c0 + nf * 8 + g];                  \
                b[nf][1] = Bs[buf][ks + tg + 4][c0 + nf * 8 + g];              \
            }                                                                  \
            _Pragma("unroll")                                                  \
            for (int mf = 0; mf < 4; mf++)                                     \
                _Pragma("unroll")                                              \
                for (int nf = 0; nf < 4; nf++)                                 \
                    mma8(acc[mf][nf], (const float*)&a4[mf], b[nf]);           \
        }                                                                      \
    }

#define MG_LDGA(c)                                                             \
    {                                                                          \
        const int k0 = (c) * 16;                                               \
        ra0 = *(const float4*)(Ablk + (size_t)arow * K + k0 + acol);           \
        ra1 = *(const float4*)(Ablk + (size_t)arow * K + k0 + acol + 4);       \
        cvt4(ra0); cvt4(ra1);                                                  \
    }
#define MG_CPB(c, buf)                                                         \
    {                                                                          \
        const float* wsrc = Wblk + (size_t)((c) * 16 + brow) * N + bcol;       \
        CP_ASYNC16(bsm[buf], wsrc);                                            \
        CP_ASYNC16(bsm[buf] + 16, wsrc + 4);                                   \
        CP_COMMIT;                                                             \
    }

#define MG_MAINLOOP(LDGA_MACRO, CPB_MACRO)                                     \
    {                                                                          \
        LDGA_MACRO(0); CPB_MACRO(0, 0); MG_STSA(0);                            \
        for (int c = 0; c < nc; c++) {                                         \
            const int cur = c & 1;                                             \
            CP_WAIT0;                                                          \
            __syncthreads();                                                   \
            if (c + 1 < nc) {                                                  \
                LDGA_MACRO(c + 1);                                             \
                CPB_MACRO(c + 1, cur ^ 1);                                     \
            }                                                                  \
            MG_COMPUTE(cur);                                                   \
            if (c + 1 < nc) MG_STSA(cur ^ 1);                                  \
        }                                                                      \
    }

// ---------------------------------------------------------------------------
// mgemm: C = epi(A @ W); EPI 0:*scale 1:(+bias)*scale 2:gelu(+bias)
// Batched over blockIdx.z with element strides zA / zC.
// ---------------------------------------------------------------------------
template <int EPI>
__global__ void __launch_bounds__(256, 2)
mgemm(const float* __restrict__ A, const float* __restrict__ W,
      const float* __restrict__ bias, float* __restrict__ C,
      int N, int K, float scale, long long zA, long long zC) {
    __shared__ float Asf[2][2048];
    __shared__ float Bs[2][16][SMS];
    MG_PROLOG
    const int bx = blockIdx.x, by = blockIdx.y;
    A += (size_t)blockIdx.z * zA;
    C += (size_t)blockIdx.z * zC;
    const float* Ablk = A + (size_t)by * 128 * K;
    const float* Wblk = W + (size_t)bx * 128;
    const int nc = K / 16;
    float4 ra0, ra1;
    MG_MAINLOOP(MG_LDGA, MG_CPB)

#pragma unroll
    for (int nf = 0; nf < 4; nf++) {
        const int col = bx * 128 + c0 + nf * 8 + 2 * tg;
        float bv0 = 0.f, bv1 = 0.f;
        if (EPI >= 1) { bv0 = bias[col]; bv1 = bias[col + 1]; }
#pragma unroll
        for (int mf = 0; mf < 4; mf++) {
            const int row = by * 128 + r0 + mf * 16 + g;
            float d0 = acc[mf][nf][0], d1 = acc[mf][nf][1];
            float d2 = acc[mf][nf][2], d3 = acc[mf][nf][3];
            if (EPI >= 1) { d0 += bv0; d1 += bv1; d2 += bv0; d3 += bv1; }
            d0 *= scale; d1 *= scale; d2 *= scale; d3 *= scale;
            if (EPI == 2) {
                d0 = d0 * normcdff(d0); d1 = d1 * normcdff(d1);
                d2 = d2 * normcdff(d2); d3 = d3 * normcdff(d3);
            }
            *(float2*)(C + (size_t)row * N + col)       = make_float2(d0, d1);
            *(float2*)(C + (size_t)(row + 8) * N + col) = make_float2(d2, d3);
        }
    }
}

// ---------------------------------------------------------------------------
// mgemm_ln: out = sc + LN(A@W + bias)*gamma + beta   (N == 128)
// Batched over blockIdx.z with element strides zA / zSc / zOut.
// ---------------------------------------------------------------------------
__global__ void __launch_bounds__(256, 2)
mgemm_ln(const float* __restrict__ A, const float* __restrict__ W,
         const float* __restrict__ bias, const float* __restrict__ sc,
         const float* __restrict__ gamma, const float* __restrict__ beta,
         float* __restrict__ out, int K,
         long long zA, long long zSc, long long zOut) {
    __shared__ float Asf[2][2048];
    __shared__ float Bs[2][16][SMS];
    __shared__ float redS[128][4][2];
    MG_PROLOG
    const int by = blockIdx.y;
    A += (size_t)blockIdx.z * zA;
    sc += (size_t)blockIdx.z * zSc;
    out += (size_t)blockIdx.z * zOut;
    const float* Ablk = A + (size_t)by * 128 * K;
    const float* Wblk = W;
    const int N = 128;
    const int nc = K / 16;
    const int wq = wid >> 1;
    float4 ra0, ra1;
    MG_MAINLOOP(MG_LDGA, MG_CPB)

#pragma unroll
    for (int nf = 0; nf < 4; nf++) {
        const float2 bv = *(const float2*)&bias[c0 + nf * 8 + 2 * tg];
#pragma unroll
        for (int mf = 0; mf < 4; mf++) {
            acc[mf][nf][0] += bv.x; acc[mf][nf][1] += bv.y;
            acc[mf][nf][2] += bv.x; acc[mf][nf][3] += bv.y;
        }
    }

#pragma unroll
    for (int mf = 0; mf < 4; mf++) {
        float s1A = 0.f, s2A = 0.f, s1B = 0.f, s2B = 0.f;
#pragma unroll
        for (int nf = 0; nf < 4; nf++) {
            s1A += acc[mf][nf][0] + acc[mf][nf][1];
            s2A += acc[mf][nf][0] * acc[mf][nf][0] + acc[mf][nf][1] * acc[mf][nf][1];
            s1B += acc[mf][nf][2] + acc[mf][nf][3];
            s2B += acc[mf][nf][2] * acc[mf][nf][2] + acc[mf][nf][3] * acc[mf][nf][3];
        }
#pragma unroll
        for (int m = 1; m <= 2; m <<= 1) {
            s1A += __shfl_xor_sync(0xffffffffu, s1A, m);
            s2A += __shfl_xor_sync(0xffffffffu, s2A, m);
            s1B += __shfl_xor_sync(0xffffffffu, s1B, m);
            s2B += __shfl_xor_sync(0xffffffffu, s2B, m);
        }
        if (tg == 0) {
            const int rA = r0 + mf * 16 + g;
            redS[rA][wq][0] = s1A;     redS[rA][wq][1] = s2A;
            redS[rA + 8][wq][0] = s1B; redS[rA + 8][wq][1] = s2B;
        }
    }
    __syncthreads();

    float gj[4][2], bj[4][2];
#pragma unroll
    for (int nf = 0; nf < 4; nf++) {
        const int col = c0 + nf * 8 + 2 * tg;
        *(float2*)gj[nf] = *(const float2*)&gamma[col];
        *(float2*)bj[nf] = *(const float2*)&beta[col];
    }
#pragma unroll
    for (int mf = 0; mf < 4; mf++) {
        const int rA = r0 + mf * 16 + g;
        float s1A = redS[rA][0][0] + redS[rA][1][0] + redS[rA][2][0] + redS[rA][3][0];
        float s2A = redS[rA][0][1] + redS[rA][1][1] + redS[rA][2][1] + redS[rA][3][1];
        float s1B = redS[rA + 8][0][0] + redS[rA + 8][1][0] + redS[rA + 8][2][0] + redS[rA + 8][3][0];
        float s2B = redS[rA + 8][0][1] + redS[rA + 8][1][1] + redS[rA + 8][2][1] + redS[rA + 8][3][1];
        const float muA = s1A * (1.f / 128.f);
        const float rsA = rsqrtf(s2A * (1.f / 128.f) - muA * muA + EPS_V);
        const float muB = s1B * (1.f / 128.f);
        const float rsB = rsqrtf(s2B * (1.f / 128.f) - muB * muB + EPS_V);
        const int rowA = by * 128 + rA;
#pragma unroll
        for (int nf = 0; nf < 4; nf++) {
            const int col = c0 + nf * 8 + 2 * tg;
            float2 scA = *(const float2*)(sc + (size_t)rowA * N + col);
            float2 scB = *(const float2*)(sc + (size_t)(rowA + 8) * N + col);
            float o0 = scA.x + (acc[mf][nf][0] - muA) * rsA * gj[nf][0] + bj[nf][0];
            float o1 = scA.y + (acc[mf][nf][1] - muA) * rsA * gj[nf][1] + bj[nf][1];
            float o2 = scB.x + (acc[mf][nf][2] - muB) * rsB * gj[nf][0] + bj[nf][0];
            float o3 = scB.y + (acc[mf][nf][3] - muB) * rsB * gj[nf][1] + bj[nf][1];
            *(float2*)(out + (size_t)rowA * N + col)       = make_float2(o0, o1);
            *(float2*)(out + (size_t)(rowA + 8) * N + col) = make_float2(o2, o3);
        }
    }
}

// ---------------------------------------------------------------------------
// Conv implicit GEMM (K=2304); epilogue bias + PReLU.
// ---------------------------------------------------------------------------
__global__ void __launch_bounds__(256, 2)
conv_igemm(const float* __restrict__ sa, const float* __restrict__ ta,
           const float* __restrict__ Wg, const float* __restrict__ bias,
           const float* __restrict__ pa, float* __restrict__ out) {
    __shared__ float Asf[2][2048];
    __shared__ float Bs[2][16][SMS];
    MG_PROLOG
    const int by = blockIdx.y;
    const int pixel = by * 128 + arow;
    const int xcrd = pixel % WW2;
    const int ycrd = (pixel / WW2) % HH;
    const int nc = CONVK / 16;   // 144
    const float* Wblk = Wg;
    const int N = CC;
    float4 ra0, ra1;

#define CV_LDGA(c)                                                             \
    {                                                                          \
        const int k0 = (c) * 16;                                               \
        const int tap  = k0 >> 8;                                              \
        const int rem  = k0 & 255;                                             \
        const int half = rem >> 7;                                             \
        const int ic0  = (rem & 127) + acol;                                   \
        const int dy = tap / 3 - 1, dx = tap % 3 - 1;                          \
        const int ys = ycrd + dy, xs = xcrd + dx;                              \
        const bool valid = ((unsigned)ys < HH) && ((unsigned)xs < WW2);        \
        const float* src = half ? ta : sa;                                     \
        const float* ap = src + ((size_t)pixel + dy * WW2 + dx) * CC + ic0;    \
        ra0 = make_float4(0.f, 0.f, 0.f, 0.f); ra1 = ra0;                      \
        if (valid) { ra0 = *(const float4*)ap; ra1 = *(const float4*)(ap + 4); } \
        cvt4(ra0); cvt4(ra1);                                                  \
    }

    MG_MAINLOOP(CV_LDGA, MG_CPB)

#pragma unroll
    for (int nf = 0; nf < 4; nf++) {
        const int col = c0 + nf * 8 + 2 * tg;
        const float bv0 = bias[col], bv1 = bias[col + 1];
        const float pv0 = pa[col],   pv1 = pa[col + 1];
#pragma unroll
        for (int mf = 0; mf < 4; mf++) {
            const int row = by * 128 + r0 + mf * 16 + g;
            float d0 = acc[mf][nf][0] + bv0, d1 = acc[mf][nf][1] + bv1;
            float d2 = acc[mf][nf][2] + bv0, d3 = acc[mf][nf][3] + bv1;
            if (d0 < 0.f) d0 *= pv0;
            if (d1 < 0.f) d1 *= pv1;
            if (d2 < 0.f) d2 *= pv0;
            if (d3 < 0.f) d3 *= pv1;
            *(float2*)(out + (size_t)row * CC + col)       = make_float2(d0, d1);
            *(float2*)(out + (size_t)(row + 8) * CC + col) = make_float2(d2, d3);
        }
    }
}

// ---------------------------------------------------------------------------
// Windowed attention, rewritten: one 256-thr block per (window, batch, branch),
// 4 heads x 64 tokens. K/V slab cooperatively loaded (coalesced); compute-phase
// smem reads are warp-broadcast (warps are head-uniform). Math order per thread
// identical to previous version.
// ---------------------------------------------------------------------------
__device__ __forceinline__ int region_label(int h, int w) {
    int rh = (h < HH - WS) ? 0 : ((h < HH - WS / 2) ? 1 : 2);
    int rw = (w < WW2 - WS) ? 0 : ((w < WW2 - WS / 2) ? 1 : 2);
    return rh * 3 + rw;
}

__global__ void __launch_bounds__(256)
attn_kernel(const float* __restrict__ q, const float* __restrict__ kv,
            const float* __restrict__ relb, float* __restrict__ out,
            int shift) {
    const int win = blockIdx.x;
    const int b   = blockIdx.y;
    const int br  = blockIdx.z;
    const int gy = win / (WW2 / WS), gx = win % (WW2 / WS);
    const int tid = threadIdx.x;
    const int h = tid >> 6;          // head 0..3
    const int t = tid & 63;          // token 0..63
    const int ty = t >> 3, tx = t & 7;

    const float* kvB = kv + (size_t)br * NTOK * 2 * CC;
    float* outB = out + (size_t)br * NTOK * CC;

    __shared__ float ks[64][132];    // [token][dim 0..127], padded rows
    __shared__ float vs[64][132];
    __shared__ float rb[225 * NHEAD];

    for (int i = tid; i < 225 * NHEAD; i += 256) rb[i] = relb[i];

    // cooperative K/V slab load: 4 threads per token, 16 float4 each
    {
        const int tt = tid >> 2;     // token
        const int j  = tid & 3;
        const int tty = tt >> 3, ttx = tt & 7;
        const int lpy = (gy * WS + tty + shift) % HH;
        const int lpx = (gx * WS + ttx + shift) % WW2;
        const float4* src = (const float4*)(kvB + (((size_t)b * HH + lpy) * WW2 + lpx) * (2 * CC));
#pragma unroll
        for (int k4 = 0; k4 < 16; k4++) {
            const int fi = j + k4 * 4;            // float4 index 0..63
            float4 v = src[fi];
            if (fi < 32) *(float4*)&ks[tt][fi * 4] = v;
            else         *(float4*)&vs[tt][(fi - 32) * 4] = v;
        }
    }

    const int py = (gy * WS + ty + shift) % HH;
    const int px = (gx * WS + tx + shift) % WW2;
    const size_t pix = ((size_t)b * HH + py) * WW2 + px;

    float4 qr[HD / 4];
    const float4* qrow = (const float4*)(q + pix * CC + h * HD);
#pragma unroll
    for (int d4 = 0; d4 < HD / 4; d4++) qr[d4] = qrow[d4];
    __syncthreads();

    int li = 0;
    if (shift) li = region_label(gy * WS + ty, gx * WS + tx);

    float s[64];
    float mx = -1e30f;
#pragma unroll
    for (int j = 0; j < 64; j++) {
        float acc = 0.f;
        const float4* kr = (const float4*)&ks[j][h * HD];
#pragma unroll
        for (int d4 = 0; d4 < HD / 4; d4++) {
            float4 kk = kr[d4];
            acc += qr[d4].x * kk.x + qr[d4].y * kk.y + qr[d4].z * kk.z + qr[d4].w * kk.w;
        }
        int jy = j >> 3, jx = j & 7;
        acc += rb[((ty - jy + WS - 1) * (2 * WS - 1) + (tx - jx + WS - 1)) * NHEAD + h];
        if (shift) {
            int lj = region_label(gy * WS + jy, gx * WS + jx);
            if (lj != li) acc -= 100.0f;
        }
        s[j] = acc;
        mx = fmaxf(mx, acc);
    }
    float sum = 0.f;
#pragma unroll
    for (int j = 0; j < 64; j++) { s[j] = expf(s[j] - mx); sum += s[j]; }
    const float inv = 1.0f / sum;

    float4 o4[HD / 4];
#pragma unroll
    for (int d4 = 0; d4 < HD / 4; d4++) o4[d4] = make_float4(0.f, 0.f, 0.f, 0.f);
#pragma unroll
    for (int j = 0; j < 64; j++) {
        const float sj = s[j];
        const float4* vr = (const float4*)&vs[j][h * HD];
#pragma unroll
        for (int d4 = 0; d4 < HD / 4; d4++) {
            float4 vv = vr[d4];
            o4[d4].x += sj * vv.x; o4[d4].y += sj * vv.y;
            o4[d4].z += sj * vv.z; o4[d4].w += sj * vv.w;
        }
    }
    float4* orow = (float4*)(outB + pix * CC + h * HD);
#pragma unroll
    for (int d4 = 0; d4 < HD / 4; d4++) {
        float4 o = o4[d4];
        o.x *= inv; o.y *= inv; o.z *= inv; o.w *= inv;
        orow[d4] = o;
    }
}

// ---------------------------------------------------------------------------
// Host driver (graph-capturable: launches only)
// ---------------------------------------------------------------------------
template <typename T>
static float* sym(const T& s) {
    void* p = nullptr;
    cudaGetSymbolAddress(&p, s);
    return (float*)p;
}

extern "C" void kernel_launch(void* const* d_in, const int* in_sizes, int n_in,
                              void* d_out, int out_size) {
    const float* x      = (const float*)d_in[0];
    const float* source = (const float*)d_in[1];
    const float* target = (const float*)d_in[2];
    const float* qW     = (const float*)d_in[3];
    const float* qb     = (const float*)d_in[4];
    const float* kvW    = (const float*)d_in[5];
    const float* kvb    = (const float*)d_in[6];
    const float* pW     = (const float*)d_in[7];
    const float* pb     = (const float*)d_in[8];
    const float* relb   = (const float*)d_in[9];
    const float* mW     = (const float*)d_in[10];
    const float* n1g    = (const float*)d_in[11];
    const float* n1b    = (const float*)d_in[12];
    const float* f1W    = (const float*)d_in[13];
    const float* f1b    = (const float*)d_in[14];
    const float* f2W    = (const float*)d_in[15];
    const float* f2b    = (const float*)d_in[16];
    const float* n2g    = (const float*)d_in[17];
    const float* n2b    = (const float*)d_in[18];
    const float* convW  = (const float*)d_in[19];
    const float* convb  = (const float*)d_in[20];
    const float* pa     = (const float*)d_in[21];

    float* bx    = sym(g_x);
    float* bst   = sym(g_st);
    float* bq    = sym(g_q);
    float* bkv   = sym(g_kv);
    float* battn = sym(g_attn);
    float* bx1   = sym(g_x1);
    float* bh    = sym(g_h);
    float* bbr   = sym(g_br);
    float* bwg   = sym(g_wg);
    float* bpwm  = sym(g_pwm);
    float* bpbm  = sym(g_pbm);
    float* bwq   = sym(g_wq);
    float* bwkv  = sym(g_wkv);
    float* bwf1  = sym(g_wf1);
    float* bwf2  = sym(g_wf2);

    const float SCALE = 0.1767766952966369f;   // 32^-0.5
    const long long ZC = (long long)NTOK * CC;
    const long long ZK = (long long)NTOK * 2 * CC;
    const long long ZH = (long long)NTOK * HID;
    const dim3 gT(NPIX / 32, CC / 32, BB);

    t_nchw2nhwc<<<gT, 256>>>(x, bx);
    t_nchw2nhwc<<<gT, 256>>>(source, bst);
    t_nchw2nhwc<<<gT, 256>>>(target, bst + ZC);

    prep_all<<<(NPREP + 255) / 256, 256>>>(qW, kvW, f1W, f2W, convW);
    fuse_pwm_bias<<<dim3(CC + 1, 2), CC>>>(pW, pb, mW);

    for (int d = 0; d < 2; d++) {
        const int shift = (d % 2) ? (WS / 2) : 0;

        // q = (x @ qW + qb) * scale   (shared by both branches)
        mgemm<1><<<dim3(1, NTOK / 128, 1), 256>>>(bx, bwq + (size_t)d * CC * CC,
                                                  qb + d * CC, bq, CC, CC, SCALE, 0, 0);
        // kv (both branches)
        mgemm<1><<<dim3(2, NTOK / 128, 2), 256>>>(bst, bwkv + (size_t)d * CC * 2 * CC,
                                                  kvb + d * 2 * CC, bkv, 2 * CC, CC, 1.f, ZC, ZK);
        // attention (both branches)
        attn_kernel<<<dim3(576, BB, 2), 256>>>(bq, bkv, relb + (size_t)d * 225 * NHEAD,
                                               battn, shift);
        // x1 = x + LN(attn @ pWm + pbm)   (both branches; shared shortcut bx)
        mgemm_ln<<<dim3(1, NTOK / 128, 2), 256>>>(battn, bpwm + (size_t)d * CC * CC,
                                                  bpbm + d * CC, bx, n1g + d * CC, n1b + d * CC,
                                                  bx1, CC, ZC, 0, ZC);
        // h = gelu(x1 @ f1W + f1b)
        mgemm<2><<<dim3(4, NTOK / 128, 2), 256>>>(bx1, bwf1 + (size_t)d * CC * HID,
                                                  f1b + d * HID, bh, HID, CC, 1.f, ZC, ZH);
        // branch out = x1 + LN(h @ f2W + f2b)
        mgemm_ln<<<dim3(1, NTOK / 128, 2), 256>>>(bh, bwf2 + (size_t)d * HID * CC,
                                                  f2b + d * CC, bx1, n2g + d * CC, n2b + d * CC,
                                                  bbr, HID, ZH, ZC, ZC);
        // conv([sa; ta]) + bias + PReLU -> new x (NHWC)
        conv_igemm<<<dim3(1, NTOK / 128), 256>>>(bbr, bbr + ZC, bwg + (size_t)d * CONVK * CC,
                                                 convb + d * CC, pa + d * CC, bx);
    }

    t_nhwc2nchw<<<gT, 256>>>(bx, (float*)d_out);
}

// round 16
// speedup vs baseline: 6.7123x; 1.0210x over previous
#include <cuda_runtime.h>
#include <math.h>
#include <stdint.h>

// ---------------------------------------------------------------------------
// Problem constants
// ---------------------------------------------------------------------------
#define BB 2
#define CC 128
#define HH 192
#define WW2 192
#define NHEAD 4
#define HD 32
#define WS 8
#define NTOK 73728           // B*H*W
#define NPIX 36864           // H*W
#define HID 512
#define EPS_V 1e-5f
#define CONVK 2304           // 9 taps * 2 halves * 128 ic
#define SMS 136              // B smem row stride (conflict-free b-frag reads)

// dynamic smem layout (floats): Asf[2][4096] | Bs[2][32][SMS] | redS[128][4][2]
#define SM_ASF_F   (2 * 4096)
#define SM_BS_F    (2 * 32 * SMS)
#define SM_GEMM_B  ((SM_ASF_F + SM_BS_F) * 4)
#define SM_LN_B    (SM_GEMM_B + 128 * 4 * 2 * 4)

// ---------------------------------------------------------------------------
// Scratch buffers (device globals; allocation-free). [2]-indexed = per branch.
// ---------------------------------------------------------------------------
__device__ float g_x   [NTOK * CC];
__device__ float g_st  [2 * NTOK * CC];       // src | tgt
__device__ float g_q   [NTOK * CC];
__device__ float g_kv  [2 * NTOK * 2 * CC];
__device__ float g_attn[2 * NTOK * CC];
__device__ float g_x1  [2 * NTOK * CC];
__device__ float g_h   [2 * NTOK * HID];
__device__ float g_br  [2 * NTOK * CC];       // sa | ta
__device__ float g_wg  [2 * CONVK * CC];      // repacked conv weights (tf32)
__device__ float g_pwm [2 * CC * CC];         // fused pW @ mW (tf32)
__device__ float g_pbm [2 * CC];              // fused pb @ mW (exact)
__device__ float g_wq  [2 * CC * CC];
__device__ float g_wkv [2 * CC * 2 * CC];
__device__ float g_wf1 [2 * CC * HID];
__device__ float g_wf2 [2 * HID * CC];

// ---------------------------------------------------------------------------
// tf32 / cp.async helpers
// ---------------------------------------------------------------------------
__device__ __forceinline__ float to_tf32(float x) {
    float r;
    asm("cvt.rna.tf32.f32 %0, %1;" : "=f"(r) : "f"(x));
    return r;
}
__device__ __forceinline__ void cvt4(float4& v) {
    v.x = to_tf32(v.x); v.y = to_tf32(v.y); v.z = to_tf32(v.z); v.w = to_tf32(v.w);
}
__device__ __forceinline__ void mma8(float* d, const float* a, const float* b) {
    asm volatile(
        "mma.sync.aligned.m16n8k8.row.col.f32.tf32.tf32.f32 "
        "{%0,%1,%2,%3}, {%4,%5,%6,%7}, {%8,%9}, {%0,%1,%2,%3};\n"
        : "+f"(d[0]), "+f"(d[1]), "+f"(d[2]), "+f"(d[3])
        : "r"(__float_as_uint(a[0])), "r"(__float_as_uint(a[1])),
          "r"(__float_as_uint(a[2])), "r"(__float_as_uint(a[3])),
          "r"(__float_as_uint(b[0])), "r"(__float_as_uint(b[1])));
}
#define CP_ASYNC16(dst_u32, src_ptr)                                           \
    asm volatile("cp.async.cg.shared.global [%0], [%1], 16;\n"                 \
                 :: "r"(dst_u32), "l"(src_ptr))
#define CP_COMMIT  asm volatile("cp.async.commit_group;\n" ::: "memory")
#define CP_WAIT0   asm volatile("cp.async.wait_group 0;\n" ::: "memory")

// ---------------------------------------------------------------------------
// Layout transforms (32x32 smem tiles, coalesced both sides)
// ---------------------------------------------------------------------------
__global__ void t_nchw2nhwc(const float* __restrict__ in, float* __restrict__ out) {
    __shared__ float tile[32][33];
    const int b = blockIdx.z;
    const int c0 = blockIdx.y * 32, p0 = blockIdx.x * 32;
    const int tr = threadIdx.x >> 5, tc = threadIdx.x & 31;
#pragma unroll
    for (int i = 0; i < 32; i += 8)
        tile[tr + i][tc] = in[((size_t)b * CC + c0 + tr + i) * NPIX + p0 + tc];
    __syncthreads();
#pragma unroll
    for (int i = 0; i < 32; i += 8)
        out[((size_t)b * NPIX + p0 + tr + i) * CC + c0 + tc] = tile[tc][tr + i];
}

__global__ void t_nhwc2nchw(const float* __restrict__ in, float* __restrict__ out) {
    __shared__ float tile[32][33];
    const int b = blockIdx.z;
    const int c0 = blockIdx.y * 32, p0 = blockIdx.x * 32;
    const int tr = threadIdx.x >> 5, tc = threadIdx.x & 31;
#pragma unroll
    for (int i = 0; i < 32; i += 8)
        tile[tr + i][tc] = in[((size_t)b * NPIX + p0 + tr + i) * CC + c0 + tc];
    __syncthreads();
#pragma unroll
    for (int i = 0; i < 32; i += 8)
        out[((size_t)b * CC + c0 + tr + i) * NPIX + p0 + tc] = tile[tc][tr + i];
}

// ---------------------------------------------------------------------------
// Mega weight prep: tf32-round all GEMM weights (both depths) + repack conv.
// ---------------------------------------------------------------------------
#define NQ_  (2 * CC * CC)
#define NKV_ (2 * CC * 2 * CC)
#define NF1_ (2 * CC * HID)
#define NF2_ (2 * HID * CC)
#define NCV_ (2 * CONVK * CC)
#define NPREP (NQ_ + NKV_ + NF1_ + NF2_ + NCV_)

__global__ void prep_all(const float* __restrict__ qW, const float* __restrict__ kvW,
                         const float* __restrict__ f1W, const float* __restrict__ f2W,
                         const float* __restrict__ convW) {
    int i = blockIdx.x * 256 + threadIdx.x;
    if (i < NQ_) { g_wq[i] = to_tf32(qW[i]); return; }
    i -= NQ_;
    if (i < NKV_) { g_wkv[i] = to_tf32(kvW[i]); return; }
    i -= NKV_;
    if (i < NF1_) { g_wf1[i] = to_tf32(f1W[i]); return; }
    i -= NF1_;
    if (i < NF2_) { g_wf2[i] = to_tf32(f2W[i]); return; }
    i -= NF2_;
    if (i < NCV_) {
        const int d = i / (CONVK * CC);
        const int idx = i % (CONVK * CC);
        const int oc = idx % CC;
        const int k  = idx / CC;
        const int tap = k >> 8;
        const int cin = k & 255;
        const int ky = tap / 3, kx = tap % 3;
        g_wg[i] = to_tf32(convW[(size_t)d * CC * 256 * 9 +
                                (((size_t)oc * 256 + cin) * 3 + ky) * 3 + kx]);
    }
}

// exact fp32 fused projection; grid (129, 2 depths)
__global__ void fuse_pwm_bias(const float* __restrict__ pW, const float* __restrict__ pb,
                              const float* __restrict__ mW) {
    __shared__ float arow[CC];
    const int d = blockIdx.y;
    const int i = blockIdx.x, j = threadIdx.x;
    const float* pWd = pW + (size_t)d * CC * CC;
    const float* mWd = mW + (size_t)d * CC * CC;
    arow[j] = (i < CC) ? pWd[i * CC + j] : pb[d * CC + j];
    __syncthreads();
    float s = 0.f;
    for (int k = 0; k < CC; k++) s += arow[k] * mWd[k * CC + j];
    if (i < CC) g_pwm[(size_t)d * CC * CC + i * CC + j] = to_tf32(s);
    else g_pbm[d * CC + j] = s;
}

// ---------------------------------------------------------------------------
// tf32 tensor-core GEMM core. BM=BN=128, BK=32, 256 thr, warps 2(m) x 4(n),
// warp tile 64x32 (m16n8k8). A staged reg->smem fragment-major (XOR swizzle);
// B via cp.async from pre-rounded tf32 weights. BK=32 doubles the latency
// window per barrier vs BK=16. k-order inside a chunk = sub0(k0..15) then
// sub1(k16..31) -> accumulation order identical to BK=16 version.
// Dynamic smem: Asf[2][4096] | Bs[2][32][SMS] | (redS for ln variant).
// ---------------------------------------------------------------------------
#define MG_PROLOG                                                              \
    extern __shared__ float dsm[];                                             \
    float (*Asf)[4096] = (float(*)[4096])dsm;                                  \
    float (*Bs)[32][SMS] = (float(*)[32][SMS])(dsm + SM_ASF_F);                \
    const int tid = threadIdx.x;                                               \
    const int lane = tid & 31;                                                 \
    const int g = lane >> 2, tg = lane & 3;                                    \
    const int wid = tid >> 5;                                                  \
    const int r0 = (wid & 1) * 64;                                             \
    const int c0 = (wid >> 1) * 32;                                            \
    const int arow = tid >> 1, acol = (tid & 1) * 8;                           \
    const int brow = tid >> 4, bcol = (tid & 15) * 8;                          \
    const int x7 = arow & 7;                                                   \
    const int S0 = ((x7 << 2) ^ x7);                                           \
    const int regb = (arow >> 3) & 1;                                          \
    const int atile = ((tid & 1) << 3) + (arow >> 4);                          \
    const int lswz = (lane ^ ((lane >> 2) & 7)) << 2;                          \
    float acc[4][4][4];                                                        \
    _Pragma("unroll")                                                          \
    for (int mf = 0; mf < 4; mf++)                                             \
        _Pragma("unroll")                                                      \
        for (int nf = 0; nf < 4; nf++)                                         \
            _Pragma("unroll")                                                  \
            for (int r = 0; r < 4; r++) acc[mf][nf][r] = 0.f;                  \
    uint32_t bsm[2];                                                           \
    bsm[0] = (uint32_t)__cvta_generic_to_shared(&Bs[0][brow][bcol]);           \
    bsm[1] = (uint32_t)__cvta_generic_to_shared(&Bs[1][brow][bcol]);

// stage one 16k half (regs p0,p1) into Asf[buf] sub-block
#define MG_STSA_HALF(buf, sub, p0, p1)                                         \
    {                                                                          \
        float* At = &Asf[buf][(sub) * 2048 + atile * 128];                     \
        At[((S0 ^ 0) << 2) + regb]     = p0.x;                                 \
        At[((S0 ^ 1) << 2) + regb]     = p0.y;                                 \
        At[((S0 ^ 2) << 2) + regb]     = p0.z;                                 \
        At[((S0 ^ 3) << 2) + regb]     = p0.w;                                 \
        At[((S0 ^ 0) << 2) + regb + 2] = p1.x;                                 \
        At[((S0 ^ 1) << 2) + regb + 2] = p1.y;                                 \
        At[((S0 ^ 2) << 2) + regb + 2] = p1.z;                                 \
        At[((S0 ^ 3) << 2) + regb + 2] = p1.w;                                 \
    }
#define MG_STSA2(buf)                                                          \
    { MG_STSA_HALF(buf, 0, ra0, ra1) MG_STSA_HALF(buf, 1, ra2, ra3) }

#define MG_COMPUTE2(buf)                                                       \
    {                                                                          \
        _Pragma("unroll")                                                      \
        for (int sub = 0; sub < 2; sub++) {                                    \
            _Pragma("unroll")                                                  \
            for (int ks = 0; ks < 16; ks += 8) {                               \
                float4 a4[4];                                                  \
                _Pragma("unroll")                                              \
                for (int mf = 0; mf < 4; mf++)                                 \
                    a4[mf] = *(const float4*)&Asf[buf][sub * 2048 +            \
                              (ks + (wid & 1) * 4 + mf) * 128 + lswz];         \
                float b[4][2];                                                 \
                _Pragma("unroll")                                              \
                for (int nf = 0; nf < 4; nf++) {                               \
                    b[nf][0] = Bs[buf][sub * 16 + ks + tg][c0 + nf * 8 + g];   \
                    b[nf][1] = Bs[buf][sub * 16 + ks + tg + 4][c0 + nf * 8 + g]; \
                }                                                              \
                _Pragma("unroll")                                              \
                for (int mf = 0; mf < 4; mf++)                                 \
                    _Pragma("unroll")                                          \
                    for (int nf = 0; nf < 4; nf++)                             \
                        mma8(acc[mf][nf], (const float*)&a4[mf], b[nf]);       \
            }                                                                  \
        }                                                                      \
    }

// A LDG + cvt for one BK=32 chunk (two 16k halves)
#define MG_LDGA2(c)                                                            \
    {                                                                          \
        const int k0 = (c) * 32;                                               \
        ra0 = *(const float4*)(Ablk + (size_t)arow * K + k0 + acol);           \
        ra1 = *(const float4*)(Ablk + (size_t)arow * K + k0 + acol + 4);       \
        ra2 = *(const float4*)(Ablk + (size_t)arow * K + k0 + 16 + acol);      \
        ra3 = *(const float4*)(Ablk + (size_t)arow * K + k0 + 16 + acol + 4);  \
        cvt4(ra0); cvt4(ra1); cvt4(ra2); cvt4(ra3);                            \
    }
// B cp.async for one BK=32 chunk (two 16-row halves)
#define MG_CPB2(c, buf)                                                        \
    {                                                                          \
        const float* w0 = Wblk + (size_t)((c) * 32 + brow) * N + bcol;         \
        const float* w1 = w0 + (size_t)16 * N;                                 \
        CP_ASYNC16(bsm[buf], w0);                                              \
        CP_ASYNC16(bsm[buf] + 16, w0 + 4);                                     \
        CP_ASYNC16(bsm[buf] + 16 * SMS * 4, w1);                               \
        CP_ASYNC16(bsm[buf] + 16 * SMS * 4 + 16, w1 + 4);                      \
        CP_COMMIT;                                                             \
    }

#define MG_MAINLOOP(LDGA_MACRO, CPB_MACRO)                                     \
    {                                                                          \
        LDGA_MACRO(0); CPB_MACRO(0, 0); MG_STSA2(0);                           \
        for (int c = 0; c < nc; c++) {                                         \
            const int cur = c & 1;                                             \
            CP_WAIT0;                                                          \
            __syncthreads();                                                   \
            if (c + 1 < nc) {                                                  \
                LDGA_MACRO(c + 1);                                             \
                CPB_MACRO(c + 1, cur ^ 1);                                     \
            }                                                                  \
            MG_COMPUTE2(cur);                                                  \
            if (c + 1 < nc) MG_STSA2(cur ^ 1);                                 \
        }                                                                      \
    }

// ---------------------------------------------------------------------------
// mgemm: C = epi(A @ W); EPI 0:*scale 1:(+bias)*scale 2:gelu(+bias)
// Batched over blockIdx.z with element strides zA / zC.
// ---------------------------------------------------------------------------
template <int EPI>
__global__ void __launch_bounds__(256, 2)
mgemm(const float* __restrict__ A, const float* __restrict__ W,
      const float* __restrict__ bias, float* __restrict__ C,
      int N, int K, float scale, long long zA, long long zC) {
    MG_PROLOG
    const int bx = blockIdx.x, by = blockIdx.y;
    A += (size_t)blockIdx.z * zA;
    C += (size_t)blockIdx.z * zC;
    const float* Ablk = A + (size_t)by * 128 * K;
    const float* Wblk = W + (size_t)bx * 128;
    const int nc = K / 32;
    float4 ra0, ra1, ra2, ra3;
    MG_MAINLOOP(MG_LDGA2, MG_CPB2)

#pragma unroll
    for (int nf = 0; nf < 4; nf++) {
        const int col = bx * 128 + c0 + nf * 8 + 2 * tg;
        float bv0 = 0.f, bv1 = 0.f;
        if (EPI >= 1) { bv0 = bias[col]; bv1 = bias[col + 1]; }
#pragma unroll
        for (int mf = 0; mf < 4; mf++) {
            const int row = by * 128 + r0 + mf * 16 + g;
            float d0 = acc[mf][nf][0], d1 = acc[mf][nf][1];
            float d2 = acc[mf][nf][2], d3 = acc[mf][nf][3];
            if (EPI >= 1) { d0 += bv0; d1 += bv1; d2 += bv0; d3 += bv1; }
            d0 *= scale; d1 *= scale; d2 *= scale; d3 *= scale;
            if (EPI == 2) {
                d0 = d0 * normcdff(d0); d1 = d1 * normcdff(d1);
                d2 = d2 * normcdff(d2); d3 = d3 * normcdff(d3);
            }
            *(float2*)(C + (size_t)row * N + col)       = make_float2(d0, d1);
            *(float2*)(C + (size_t)(row + 8) * N + col) = make_float2(d2, d3);
        }
    }
}

// ---------------------------------------------------------------------------
// mgemm_ln: out = sc + LN(A@W + bias)*gamma + beta   (N == 128)
// Batched over blockIdx.z with element strides zA / zSc / zOut.
// ---------------------------------------------------------------------------
__global__ void __launch_bounds__(256, 2)
mgemm_ln(const float* __restrict__ A, const float* __restrict__ W,
         const float* __restrict__ bias, const float* __restrict__ sc,
         const float* __restrict__ gamma, const float* __restrict__ beta,
         float* __restrict__ out, int K,
         long long zA, long long zSc, long long zOut) {
    MG_PROLOG
    float (*redS)[4][2] = (float(*)[4][2])(dsm + SM_ASF_F + SM_BS_F);
    const int by = blockIdx.y;
    A += (size_t)blockIdx.z * zA;
    sc += (size_t)blockIdx.z * zSc;
    out += (size_t)blockIdx.z * zOut;
    const float* Ablk = A + (size_t)by * 128 * K;
    const float* Wblk = W;
    const int N = 128;
    const int nc = K / 32;
    const int wq = wid >> 1;
    float4 ra0, ra1, ra2, ra3;
    MG_MAINLOOP(MG_LDGA2, MG_CPB2)

#pragma unroll
    for (int nf = 0; nf < 4; nf++) {
        const float2 bv = *(const float2*)&bias[c0 + nf * 8 + 2 * tg];
#pragma unroll
        for (int mf = 0; mf < 4; mf++) {
            acc[mf][nf][0] += bv.x; acc[mf][nf][1] += bv.y;
            acc[mf][nf][2] += bv.x; acc[mf][nf][3] += bv.y;
        }
    }

#pragma unroll
    for (int mf = 0; mf < 4; mf++) {
        float s1A = 0.f, s2A = 0.f, s1B = 0.f, s2B = 0.f;
#pragma unroll
        for (int nf = 0; nf < 4; nf++) {
            s1A += acc[mf][nf][0] + acc[mf][nf][1];
            s2A += acc[mf][nf][0] * acc[mf][nf][0] + acc[mf][nf][1] * acc[mf][nf][1];
            s1B += acc[mf][nf][2] + acc[mf][nf][3];
            s2B += acc[mf][nf][2] * acc[mf][nf][2] + acc[mf][nf][3] * acc[mf][nf][3];
        }
#pragma unroll
        for (int m = 1; m <= 2; m <<= 1) {
            s1A += __shfl_xor_sync(0xffffffffu, s1A, m);
            s2A += __shfl_xor_sync(0xffffffffu, s2A, m);
            s1B += __shfl_xor_sync(0xffffffffu, s1B, m);
            s2B += __shfl_xor_sync(0xffffffffu, s2B, m);
        }
        if (tg == 0) {
            const int rA = r0 + mf * 16 + g;
            redS[rA][wq][0] = s1A;     redS[rA][wq][1] = s2A;
            redS[rA + 8][wq][0] = s1B; redS[rA + 8][wq][1] = s2B;
        }
    }
    __syncthreads();

    float gj[4][2], bj[4][2];
#pragma unroll
    for (int nf = 0; nf < 4; nf++) {
        const int col = c0 + nf * 8 + 2 * tg;
        *(float2*)gj[nf] = *(const float2*)&gamma[col];
        *(float2*)bj[nf] = *(const float2*)&beta[col];
    }
#pragma unroll
    for (int mf = 0; mf < 4; mf++) {
        const int rA = r0 + mf * 16 + g;
        float s1A = redS[rA][0][0] + redS[rA][1][0] + redS[rA][2][0] + redS[rA][3][0];
        float s2A = redS[rA][0][1] + redS[rA][1][1] + redS[rA][2][1] + redS[rA][3][1];
        float s1B = redS[rA + 8][0][0] + redS[rA + 8][1][0] + redS[rA + 8][2][0] + redS[rA + 8][3][0];
        float s2B = redS[rA + 8][0][1] + redS[rA + 8][1][1] + redS[rA + 8][2][1] + redS[rA + 8][3][1];
        const float muA = s1A * (1.f / 128.f);
        const float rsA = rsqrtf(s2A * (1.f / 128.f) - muA * muA + EPS_V);
        const float muB = s1B * (1.f / 128.f);
        const float rsB = rsqrtf(s2B * (1.f / 128.f) - muB * muB + EPS_V);
        const int rowA = by * 128 + rA;
#pragma unroll
        for (int nf = 0; nf < 4; nf++) {
            const int col = c0 + nf * 8 + 2 * tg;
            float2 scA = *(const float2*)(sc + (size_t)rowA * N + col);
            float2 scB = *(const float2*)(sc + (size_t)(rowA + 8) * N + col);
            float o0 = scA.x + (acc[mf][nf][0] - muA) * rsA * gj[nf][0] + bj[nf][0];
            float o1 = scA.y + (acc[mf][nf][1] - muA) * rsA * gj[nf][1] + bj[nf][1];
            float o2 = scB.x + (acc[mf][nf][2] - muB) * rsB * gj[nf][0] + bj[nf][0];
            float o3 = scB.y + (acc[mf][nf][3] - muB) * rsB * gj[nf][1] + bj[nf][1];
            *(float2*)(out + (size_t)rowA * N + col)       = make_float2(o0, o1);
            *(float2*)(out + (size_t)(rowA + 8) * N + col) = make_float2(o2, o3);
        }
    }
}

// ---------------------------------------------------------------------------
// Conv implicit GEMM (K=2304, nc=72); epilogue bias + PReLU.
// ---------------------------------------------------------------------------
__global__ void __launch_bounds__(256, 2)
conv_igemm(const float* __restrict__ sa, const float* __restrict__ ta,
           const float* __restrict__ Wg, const float* __restrict__ bias,
           const float* __restrict__ pa, float* __restrict__ out) {
    MG_PROLOG
    const int by = blockIdx.y;
    const int pixel = by * 128 + arow;
    const int xcrd = pixel % WW2;
    const int ycrd = (pixel / WW2) % HH;
    const int nc = CONVK / 32;   // 72
    const float* Wblk = Wg;
    const int N = CC;
    float4 ra0, ra1, ra2, ra3;

#define CV_LDGA_HALF(kk, p0, p1)                                               \
    {                                                                          \
        const int tap  = (kk) >> 8;                                            \
        const int rem  = (kk) & 255;                                           \
        const int half = rem >> 7;                                             \
        const int ic0  = (rem & 127) + acol;                                   \
        const int dy = tap / 3 - 1, dx = tap % 3 - 1;                          \
        const int ys = ycrd + dy, xs = xcrd + dx;                              \
        const bool valid = ((unsigned)ys < HH) && ((unsigned)xs < WW2);        \
        const float* src = half ? ta : sa;                                     \
        const float* ap = src + ((size_t)pixel + dy * WW2 + dx) * CC + ic0;    \
        p0 = make_float4(0.f, 0.f, 0.f, 0.f); p1 = p0;                         \
        if (valid) { p0 = *(const float4*)ap; p1 = *(const float4*)(ap + 4); } \
        cvt4(p0); cvt4(p1);                                                    \
    }
#define CV_LDGA2(c)                                                            \
    {                                                                          \
        CV_LDGA_HALF((c) * 32,      ra0, ra1)                                  \
        CV_LDGA_HALF((c) * 32 + 16, ra2, ra3)                                  \
    }

    MG_MAINLOOP(CV_LDGA2, MG_CPB2)

#pragma unroll
    for (int nf = 0; nf < 4; nf++) {
        const int col = c0 + nf * 8 + 2 * tg;
        const float bv0 = bias[col], bv1 = bias[col + 1];
        const float pv0 = pa[col],   pv1 = pa[col + 1];
#pragma unroll
        for (int mf = 0; mf < 4; mf++) {
            const int row = by * 128 + r0 + mf * 16 + g;
            float d0 = acc[mf][nf][0] + bv0, d1 = acc[mf][nf][1] + bv1;
            float d2 = acc[mf][nf][2] + bv0, d3 = acc[mf][nf][3] + bv1;
            if (d0 < 0.f) d0 *= pv0;
            if (d1 < 0.f) d1 *= pv1;
            if (d2 < 0.f) d2 *= pv0;
            if (d3 < 0.f) d3 *= pv1;
            *(float2*)(out + (size_t)row * CC + col)       = make_float2(d0, d1);
            *(float2*)(out + (size_t)(row + 8) * CC + col) = make_float2(d2, d3);
        }
    }
}

// ---------------------------------------------------------------------------
// Windowed attention: one 256-thr block per (window, batch, branch).
// ---------------------------------------------------------------------------
__device__ __forceinline__ int region_label(int h, int w) {
    int rh = (h < HH - WS) ? 0 : ((h < HH - WS / 2) ? 1 : 2);
    int rw = (w < WW2 - WS) ? 0 : ((w < WW2 - WS / 2) ? 1 : 2);
    return rh * 3 + rw;
}

__global__ void __launch_bounds__(256)
attn_kernel(const float* __restrict__ q, const float* __restrict__ kv,
            const float* __restrict__ relb, float* __restrict__ out,
            int shift) {
    const int win = blockIdx.x;
    const int b   = blockIdx.y;
    const int br  = blockIdx.z;
    const int gy = win / (WW2 / WS), gx = win % (WW2 / WS);
    const int tid = threadIdx.x;
    const int h = tid >> 6;
    const int t = tid & 63;
    const int ty = t >> 3, tx = t & 7;

    const float* kvB = kv + (size_t)br * NTOK * 2 * CC;
    float* outB = out + (size_t)br * NTOK * CC;

    __shared__ float ks[64][132];
    __shared__ float vs[64][132];
    __shared__ float rb[225 * NHEAD];

    for (int i = tid; i < 225 * NHEAD; i += 256) rb[i] = relb[i];

    {
        const int tt = tid >> 2;
        const int j  = tid & 3;
        const int tty = tt >> 3, ttx = tt & 7;
        const int lpy = (gy * WS + tty + shift) % HH;
        const int lpx = (gx * WS + ttx + shift) % WW2;
        const float4* src = (const float4*)(kvB + (((size_t)b * HH + lpy) * WW2 + lpx) * (2 * CC));
#pragma unroll
        for (int k4 = 0; k4 < 16; k4++) {
            const int fi = j + k4 * 4;
            float4 v = src[fi];
            if (fi < 32) *(float4*)&ks[tt][fi * 4] = v;
            else         *(float4*)&vs[tt][(fi - 32) * 4] = v;
        }
    }

    const int py = (gy * WS + ty + shift) % HH;
    const int px = (gx * WS + tx + shift) % WW2;
    const size_t pix = ((size_t)b * HH + py) * WW2 + px;

    float4 qr[HD / 4];
    const float4* qrow = (const float4*)(q + pix * CC + h * HD);
#pragma unroll
    for (int d4 = 0; d4 < HD / 4; d4++) qr[d4] = qrow[d4];
    __syncthreads();

    int li = 0;
    if (shift) li = region_label(gy * WS + ty, gx * WS + tx);

    float s[64];
    float mx = -1e30f;
#pragma unroll
    for (int j = 0; j < 64; j++) {
        float acc = 0.f;
        const float4* kr = (const float4*)&ks[j][h * HD];
#pragma unroll
        for (int d4 = 0; d4 < HD / 4; d4++) {
            float4 kk = kr[d4];
            acc += qr[d4].x * kk.x + qr[d4].y * kk.y + qr[d4].z * kk.z + qr[d4].w * kk.w;
        }
        int jy = j >> 3, jx = j & 7;
        acc += rb[((ty - jy + WS - 1) * (2 * WS - 1) + (tx - jx + WS - 1)) * NHEAD + h];
        if (shift) {
            int lj = region_label(gy * WS + jy, gx * WS + jx);
            if (lj != li) acc -= 100.0f;
        }
        s[j] = acc;
        mx = fmaxf(mx, acc);
    }
    float sum = 0.f;
#pragma unroll
    for (int j = 0; j < 64; j++) { s[j] = expf(s[j] - mx); sum += s[j]; }
    const float inv = 1.0f / sum;

    float4 o4[HD / 4];
#pragma unroll
    for (int d4 = 0; d4 < HD / 4; d4++) o4[d4] = make_float4(0.f, 0.f, 0.f, 0.f);
#pragma unroll
    for (int j = 0; j < 64; j++) {
        const float sj = s[j];
        const float4* vr = (const float4*)&vs[j][h * HD];
#pragma unroll
        for (int d4 = 0; d4 < HD / 4; d4++) {
            float4 vv = vr[d4];
            o4[d4].x += sj * vv.x; o4[d4].y += sj * vv.y;
            o4[d4].z += sj * vv.z; o4[d4].w += sj * vv.w;
        }
    }
    float4* orow = (float4*)(outB + pix * CC + h * HD);
#pragma unroll
    for (int d4 = 0; d4 < HD / 4; d4++) {
        float4 o = o4[d4];
        o.x *= inv; o.y *= inv; o.z *= inv; o.w *= inv;
        orow[d4] = o;
    }
}

// ---------------------------------------------------------------------------
// Host driver (graph-capturable: launches only)
// ---------------------------------------------------------------------------
template <typename T>
static float* sym(const T& s) {
    void* p = nullptr;
    cudaGetSymbolAddress(&p, s);
    return (float*)p;
}

extern "C" void kernel_launch(void* const* d_in, const int* in_sizes, int n_in,
                              void* d_out, int out_size) {
    const float* x      = (const float*)d_in[0];
    const float* source = (const float*)d_in[1];
    const float* target = (const float*)d_in[2];
    const float* qW     = (const float*)d_in[3];
    const float* qb     = (const float*)d_in[4];
    const float* kvW    = (const float*)d_in[5];
    const float* kvb    = (const float*)d_in[6];
    const float* pW     = (const float*)d_in[7];
    const float* pb     = (const float*)d_in[8];
    const float* relb   = (const float*)d_in[9];
    const float* mW     = (const float*)d_in[10];
    const float* n1g    = (const float*)d_in[11];
    const float* n1b    = (const float*)d_in[12];
    const float* f1W    = (const float*)d_in[13];
    const float* f1b    = (const float*)d_in[14];
    const float* f2W    = (const float*)d_in[15];
    const float* f2b    = (const float*)d_in[16];
    const float* n2g    = (const float*)d_in[17];
    const float* n2b    = (const float*)d_in[18];
    const float* convW  = (const float*)d_in[19];
    const float* convb  = (const float*)d_in[20];
    const float* pa     = (const float*)d_in[21];

    float* bx    = sym(g_x);
    float* bst   = sym(g_st);
    float* bq    = sym(g_q);
    float* bkv   = sym(g_kv);
    float* battn = sym(g_attn);
    float* bx1   = sym(g_x1);
    float* bh    = sym(g_h);
    float* bbr   = sym(g_br);
    float* bwg   = sym(g_wg);
    float* bpwm  = sym(g_pwm);
    float* bpbm  = sym(g_pbm);
    float* bwq   = sym(g_wq);
    float* bwkv  = sym(g_wkv);
    float* bwf1  = sym(g_wf1);
    float* bwf2  = sym(g_wf2);

    // opt in to >48KB dynamic smem (host-side, idempotent, capture-safe)
    cudaFuncSetAttribute(mgemm<1>, cudaFuncAttributeMaxDynamicSharedMemorySize, SM_GEMM_B);
    cudaFuncSetAttribute(mgemm<2>, cudaFuncAttributeMaxDynamicSharedMemorySize, SM_GEMM_B);
    cudaFuncSetAttribute(mgemm_ln, cudaFuncAttributeMaxDynamicSharedMemorySize, SM_LN_B);
    cudaFuncSetAttribute(conv_igemm, cudaFuncAttributeMaxDynamicSharedMemorySize, SM_GEMM_B);

    const float SCALE = 0.1767766952966369f;   // 32^-0.5
    const long long ZC = (long long)NTOK * CC;
    const long long ZK = (long long)NTOK * 2 * CC;
    const long long ZH = (long long)NTOK * HID;
    const dim3 gT(NPIX / 32, CC / 32, BB);

    t_nchw2nhwc<<<gT, 256>>>(x, bx);
    t_nchw2nhwc<<<gT, 256>>>(source, bst);
    t_nchw2nhwc<<<gT, 256>>>(target, bst + ZC);

    prep_all<<<(NPREP + 255) / 256, 256>>>(qW, kvW, f1W, f2W, convW);
    fuse_pwm_bias<<<dim3(CC + 1, 2), CC>>>(pW, pb, mW);

    for (int d = 0; d < 2; d++) {
        const int shift = (d % 2) ? (WS / 2) : 0;

        // q = (x @ qW + qb) * scale   (shared by both branches)
        mgemm<1><<<dim3(1, NTOK / 128, 1), 256, SM_GEMM_B>>>(
            bx, bwq + (size_t)d * CC * CC, qb + d * CC, bq, CC, CC, SCALE, 0, 0);
        // kv (both branches)
        mgemm<1><<<dim3(2, NTOK / 128, 2), 256, SM_GEMM_B>>>(
            bst, bwkv + (size_t)d * CC * 2 * CC, kvb + d * 2 * CC, bkv, 2 * CC, CC, 1.f, ZC, ZK);
        // attention (both branches)
        attn_kernel<<<dim3(576, BB, 2), 256>>>(bq, bkv, relb + (size_t)d * 225 * NHEAD,
                                               battn, shift);
        // x1 = x + LN(attn @ pWm + pbm)
        mgemm_ln<<<dim3(1, NTOK / 128, 2), 256, SM_LN_B>>>(
            battn, bpwm + (size_t)d * CC * CC, bpbm + d * CC, bx,
            n1g + d * CC, n1b + d * CC, bx1, CC, ZC, 0, ZC);
        // h = gelu(x1 @ f1W + f1b)
        mgemm<2><<<dim3(4, NTOK / 128, 2), 256, SM_GEMM_B>>>(
            bx1, bwf1 + (size_t)d * CC * HID, f1b + d * HID, bh, HID, CC, 1.f, ZC, ZH);
        // branch out = x1 + LN(h @ f2W + f2b)
        mgemm_ln<<<dim3(1, NTOK / 128, 2), 256, SM_LN_B>>>(
            bh, bwf2 + (size_t)d * HID * CC, f2b + d * CC, bx1,
            n2g + d * CC, n2b + d * CC, bbr, HID, ZH, ZC, ZC);
        // conv([sa; ta]) + bias + PReLU -> new x (NHWC)
        conv_igemm<<<dim3(1, NTOK / 128), 256, SM_GEMM_B>>>(
            bbr, bbr + ZC, bwg + (size_t)d * CONVK * CC, convb + d * CC, pa + d * CC, bx);
    }

    t_nhwc2nchw<<<gT, 256>>>(bx, (float*)d_out);
}

// round 17
// speedup vs baseline: 6.8654x; 1.0228x over previous
#include <cuda_runtime.h>
#include <math.h>
#include <stdint.h>

// ---------------------------------------------------------------------------
// Problem constants
// ---------------------------------------------------------------------------
#define BB 2
#define CC 128
#define HH 192
#define WW2 192
#define NHEAD 4
#define HD 32
#define WS 8
#define NTOK 73728           // B*H*W
#define NPIX 36864           // H*W
#define HID 512
#define EPS_V 1e-5f
#define CONVK 2304           // 9 taps * 2 halves * 128 ic
#define SMS 136              // B smem row stride (conflict-free b-frag reads)

// dynamic smem layouts (floats)
#define SM_ASF_F   (2 * 4096)
#define SM_BS_F    (2 * 32 * SMS)
#define SM_GEMM_B  ((SM_ASF_F + SM_BS_F) * 4)
#define SM_LN_B    (SM_GEMM_B + 128 * 4 * 2 * 4)
// mlp: Asf[4][4096] | Bs[2][32][SMS] | Hs[128][136] | redS[128][4][2]
#define SM_MLP_F   (4 * 4096 + SM_BS_F + 128 * 136 + 128 * 4 * 2)
#define SM_MLP_B   (SM_MLP_F * 4)

// ---------------------------------------------------------------------------
// Scratch buffers (device globals; allocation-free). [2]-indexed = per branch.
// ---------------------------------------------------------------------------
__device__ float g_x   [NTOK * CC];
__device__ float g_st  [2 * NTOK * CC];       // src | tgt
__device__ float g_q   [NTOK * CC];
__device__ float g_kv  [2 * NTOK * 2 * CC];
__device__ float g_attn[2 * NTOK * CC];
__device__ float g_x1  [2 * NTOK * CC];
__device__ float g_br  [2 * NTOK * CC];       // sa | ta
__device__ float g_wg  [2 * CONVK * CC];      // repacked conv weights (tf32)
__device__ float g_pwm [2 * CC * CC];         // fused pW @ mW (tf32)
__device__ float g_pbm [2 * CC];              // fused pb @ mW (exact)
__device__ float g_wq  [2 * CC * CC];
__device__ float g_wkv [2 * CC * 2 * CC];
__device__ float g_wf1 [2 * CC * HID];
__device__ float g_wf2 [2 * HID * CC];

// ---------------------------------------------------------------------------
// tf32 / cp.async helpers
// ---------------------------------------------------------------------------
__device__ __forceinline__ float to_tf32(float x) {
    float r;
    asm("cvt.rna.tf32.f32 %0, %1;" : "=f"(r) : "f"(x));
    return r;
}
__device__ __forceinline__ void cvt4(float4& v) {
    v.x = to_tf32(v.x); v.y = to_tf32(v.y); v.z = to_tf32(v.z); v.w = to_tf32(v.w);
}
__device__ __forceinline__ void mma8(float* d, const float* a, const float* b) {
    asm volatile(
        "mma.sync.aligned.m16n8k8.row.col.f32.tf32.tf32.f32 "
        "{%0,%1,%2,%3}, {%4,%5,%6,%7}, {%8,%9}, {%0,%1,%2,%3};\n"
        : "+f"(d[0]), "+f"(d[1]), "+f"(d[2]), "+f"(d[3])
        : "r"(__float_as_uint(a[0])), "r"(__float_as_uint(a[1])),
          "r"(__float_as_uint(a[2])), "r"(__float_as_uint(a[3])),
          "r"(__float_as_uint(b[0])), "r"(__float_as_uint(b[1])));
}
#define CP_ASYNC16(dst_u32, src_ptr)                                           \
    asm volatile("cp.async.cg.shared.global [%0], [%1], 16;\n"                 \
                 :: "r"(dst_u32), "l"(src_ptr))
#define CP_COMMIT  asm volatile("cp.async.commit_group;\n" ::: "memory")
#define CP_WAIT0   asm volatile("cp.async.wait_group 0;\n" ::: "memory")

// ---------------------------------------------------------------------------
// Layout transforms (32x32 smem tiles, coalesced both sides)
// ---------------------------------------------------------------------------
__global__ void t_nchw2nhwc(const float* __restrict__ in, float* __restrict__ out) {
    __shared__ float tile[32][33];
    const int b = blockIdx.z;
    const int c0 = blockIdx.y * 32, p0 = blockIdx.x * 32;
    const int tr = threadIdx.x >> 5, tc = threadIdx.x & 31;
#pragma unroll
    for (int i = 0; i < 32; i += 8)
        tile[tr + i][tc] = in[((size_t)b * CC + c0 + tr + i) * NPIX + p0 + tc];
    __syncthreads();
#pragma unroll
    for (int i = 0; i < 32; i += 8)
        out[((size_t)b * NPIX + p0 + tr + i) * CC + c0 + tc] = tile[tc][tr + i];
}

__global__ void t_nhwc2nchw(const float* __restrict__ in, float* __restrict__ out) {
    __shared__ float tile[32][33];
    const int b = blockIdx.z;
    const int c0 = blockIdx.y * 32, p0 = blockIdx.x * 32;
    const int tr = threadIdx.x >> 5, tc = threadIdx.x & 31;
#pragma unroll
    for (int i = 0; i < 32; i += 8)
        tile[tr + i][tc] = in[((size_t)b * NPIX + p0 + tr + i) * CC + c0 + tc];
    __syncthreads();
#pragma unroll
    for (int i = 0; i < 32; i += 8)
        out[((size_t)b * CC + c0 + tr + i) * NPIX + p0 + tc] = tile[tc][tr + i];
}

// ---------------------------------------------------------------------------
// Mega weight prep: tf32-round all GEMM weights (both depths) + repack conv.
// ---------------------------------------------------------------------------
#define NQ_  (2 * CC * CC)
#define NKV_ (2 * CC * 2 * CC)
#define NF1_ (2 * CC * HID)
#define NF2_ (2 * HID * CC)
#define NCV_ (2 * CONVK * CC)
#define NPREP (NQ_ + NKV_ + NF1_ + NF2_ + NCV_)

__global__ void prep_all(const float* __restrict__ qW, const float* __restrict__ kvW,
                         const float* __restrict__ f1W, const float* __restrict__ f2W,
                         const float* __restrict__ convW) {
    int i = blockIdx.x * 256 + threadIdx.x;
    if (i < NQ_) { g_wq[i] = to_tf32(qW[i]); return; }
    i -= NQ_;
    if (i < NKV_) { g_wkv[i] = to_tf32(kvW[i]); return; }
    i -= NKV_;
    if (i < NF1_) { g_wf1[i] = to_tf32(f1W[i]); return; }
    i -= NF1_;
    if (i < NF2_) { g_wf2[i] = to_tf32(f2W[i]); return; }
    i -= NF2_;
    if (i < NCV_) {
        const int d = i / (CONVK * CC);
        const int idx = i % (CONVK * CC);
        const int oc = idx % CC;
        const int k  = idx / CC;
        const int tap = k >> 8;
        const int cin = k & 255;
        const int ky = tap / 3, kx = tap % 3;
        g_wg[i] = to_tf32(convW[(size_t)d * CC * 256 * 9 +
                                (((size_t)oc * 256 + cin) * 3 + ky) * 3 + kx]);
    }
}

// exact fp32 fused projection; grid (129, 2 depths)
__global__ void fuse_pwm_bias(const float* __restrict__ pW, const float* __restrict__ pb,
                              const float* __restrict__ mW) {
    __shared__ float arow[CC];
    const int d = blockIdx.y;
    const int i = blockIdx.x, j = threadIdx.x;
    const float* pWd = pW + (size_t)d * CC * CC;
    const float* mWd = mW + (size_t)d * CC * CC;
    arow[j] = (i < CC) ? pWd[i * CC + j] : pb[d * CC + j];
    __syncthreads();
    float s = 0.f;
    for (int k = 0; k < CC; k++) s += arow[k] * mWd[k * CC + j];
    if (i < CC) g_pwm[(size_t)d * CC * CC + i * CC + j] = to_tf32(s);
    else g_pbm[d * CC + j] = s;
}

// ---------------------------------------------------------------------------
// tf32 tensor-core GEMM core. BM=BN=128, BK=32, 256 thr, warps 2(m) x 4(n),
// warp tile 64x32 (m16n8k8). A staged reg->smem fragment-major (XOR swizzle);
// B via cp.async from pre-rounded tf32 weights.
// ---------------------------------------------------------------------------
#define MG_IDS                                                                 \
    const int tid = threadIdx.x;                                               \
    const int lane = tid & 31;                                                 \
    const int g = lane >> 2, tg = lane & 3;                                    \
    const int wid = tid >> 5;                                                  \
    const int r0 = (wid & 1) * 64;                                             \
    const int c0 = (wid >> 1) * 32;                                            \
    const int arow = tid >> 1, acol = (tid & 1) * 8;                           \
    const int brow = tid >> 4, bcol = (tid & 15) * 8;                          \
    const int x7 = arow & 7;                                                   \
    const int S0 = ((x7 << 2) ^ x7);                                           \
    const int regb = (arow >> 3) & 1;                                          \
    const int atile = ((tid & 1) << 3) + (arow >> 4);                          \
    const int lswz = (lane ^ ((lane >> 2) & 7)) << 2;

#define MG_ACC_INIT(ACC)                                                       \
    _Pragma("unroll")                                                          \
    for (int mf = 0; mf < 4; mf++)                                             \
        _Pragma("unroll")                                                      \
        for (int nf = 0; nf < 4; nf++)                                         \
            _Pragma("unroll")                                                  \
            for (int r = 0; r < 4; r++) ACC[mf][nf][r] = 0.f;

#define MG_PROLOG                                                              \
    extern __shared__ float dsm[];                                             \
    float (*Asf)[4096] = (float(*)[4096])dsm;                                  \
    float (*Bs)[32][SMS] = (float(*)[32][SMS])(dsm + SM_ASF_F);                \
    MG_IDS                                                                     \
    float acc[4][4][4];                                                        \
    MG_ACC_INIT(acc)                                                           \
    uint32_t bsm[2];                                                           \
    bsm[0] = (uint32_t)__cvta_generic_to_shared(&Bs[0][brow][bcol]);           \
    bsm[1] = (uint32_t)__cvta_generic_to_shared(&Bs[1][brow][bcol]);

// stage one 16k half (regs p0,p1) into dst sub-block (frag-major)
#define MG_STSA_HALF(dst, sub, p0, p1)                                         \
    {                                                                          \
        float* At = &(dst)[(sub) * 2048 + atile * 128];                        \
        At[((S0 ^ 0) << 2) + regb]     = p0.x;                                 \
        At[((S0 ^ 1) << 2) + regb]     = p0.y;                                 \
        At[((S0 ^ 2) << 2) + regb]     = p0.z;                                 \
        At[((S0 ^ 3) << 2) + regb]     = p0.w;                                 \
        At[((S0 ^ 0) << 2) + regb + 2] = p1.x;                                 \
        At[((S0 ^ 1) << 2) + regb + 2] = p1.y;                                 \
        At[((S0 ^ 2) << 2) + regb + 2] = p1.z;                                 \
        At[((S0 ^ 3) << 2) + regb + 2] = p1.w;                                 \
    }
#define MG_STSA2X(dst)                                                         \
    { MG_STSA_HALF(dst, 0, ra0, ra1) MG_STSA_HALF(dst, 1, ra2, ra3) }
#define MG_STSA2(buf) MG_STSA2X(Asf[buf])

// compute one BK=32 chunk: A from frag-major abuf, B from bbuf, into ACC
#define MG_COMPUTE2X(abuf, bbuf, ACC)                                          \
    {                                                                          \
        _Pragma("unroll")                                                      \
        for (int sub = 0; sub < 2; sub++) {                                    \
            _Pragma("unroll")                                                  \
            for (int ks = 0; ks < 16; ks += 8) {                               \
                float4 a4[4];                                                  \
                _Pragma("unroll")                                              \
                for (int mf = 0; mf < 4; mf++)                                 \
                    a4[mf] = *(const float4*)&(abuf)[sub * 2048 +              \
                              (ks + (wid & 1) * 4 + mf) * 128 + lswz];         \
                float b[4][2];                                                 \
                _Pragma("unroll")                                              \
                for (int nf = 0; nf < 4; nf++) {                               \
                    b[nf][0] = (bbuf)[sub * 16 + ks + tg][c0 + nf * 8 + g];    \
                    b[nf][1] = (bbuf)[sub * 16 + ks + tg + 4][c0 + nf * 8 + g]; \
                }                                                              \
                _Pragma("unroll")                                              \
                for (int mf = 0; mf < 4; mf++)                                 \
                    _Pragma("unroll")                                          \
                    for (int nf = 0; nf < 4; nf++)                             \
                        mma8(ACC[mf][nf], (const float*)&a4[mf], b[nf]);       \
            }                                                                  \
        }                                                                      \
    }
#define MG_COMPUTE2(buf) MG_COMPUTE2X(Asf[buf], Bs[buf], acc)

// A LDG + cvt for one BK=32 chunk
#define MG_LDGA2(c)                                                            \
    {                                                                          \
        const int k0 = (c) * 32;                                               \
        ra0 = *(const float4*)(Ablk + (size_t)arow * K + k0 + acol);           \
        ra1 = *(const float4*)(Ablk + (size_t)arow * K + k0 + acol + 4);       \
        ra2 = *(const float4*)(Ablk + (size_t)arow * K + k0 + 16 + acol);      \
        ra3 = *(const float4*)(Ablk + (size_t)arow * K + k0 + 16 + acol + 4);  \
        cvt4(ra0); cvt4(ra1); cvt4(ra2); cvt4(ra3);                            \
    }
// B cp.async for one BK=32 chunk (parameterized source)
#define MG_CPB2X(Wp, Nn, c, buf)                                               \
    {                                                                          \
        const float* w0 = (Wp) + (size_t)((c) * 32 + brow) * (Nn) + bcol;      \
        const float* w1 = w0 + (size_t)16 * (Nn);                              \
        CP_ASYNC16(bsm[buf], w0);                                              \
        CP_ASYNC16(bsm[buf] + 16, w0 + 4);                                     \
        CP_ASYNC16(bsm[buf] + 16 * SMS * 4, w1);                               \
        CP_ASYNC16(bsm[buf] + 16 * SMS * 4 + 16, w1 + 4);                      \
        CP_COMMIT;                                                             \
    }
#define MG_CPB2(c, buf) MG_CPB2X(Wblk, N, c, buf)

#define MG_MAINLOOP(LDGA_MACRO, CPB_MACRO)                                     \
    {                                                                          \
        LDGA_MACRO(0); CPB_MACRO(0, 0); MG_STSA2(0);                           \
        for (int c = 0; c < nc; c++) {                                         \
            const int cur = c & 1;                                             \
            CP_WAIT0;                                                          \
            __syncthreads();                                                   \
            if (c + 1 < nc) {                                                  \
                LDGA_MACRO(c + 1);                                             \
                CPB_MACRO(c + 1, cur ^ 1);                                     \
            }                                                                  \
            MG_COMPUTE2(cur);                                                  \
            if (c + 1 < nc) MG_STSA2(cur ^ 1);                                 \
        }                                                                      \
    }

// ---------------------------------------------------------------------------
// mgemm: C = epi(A @ W); EPI 0:*scale 1:(+bias)*scale 2:gelu(+bias)
// ---------------------------------------------------------------------------
template <int EPI>
__global__ void __launch_bounds__(256, 2)
mgemm(const float* __restrict__ A, const float* __restrict__ W,
      const float* __restrict__ bias, float* __restrict__ C,
      int N, int K, float scale, long long zA, long long zC) {
    MG_PROLOG
    const int bx = blockIdx.x, by = blockIdx.y;
    A += (size_t)blockIdx.z * zA;
    C += (size_t)blockIdx.z * zC;
    const float* Ablk = A + (size_t)by * 128 * K;
    const float* Wblk = W + (size_t)bx * 128;
    const int nc = K / 32;
    float4 ra0, ra1, ra2, ra3;
    MG_MAINLOOP(MG_LDGA2, MG_CPB2)

#pragma unroll
    for (int nf = 0; nf < 4; nf++) {
        const int col = bx * 128 + c0 + nf * 8 + 2 * tg;
        float bv0 = 0.f, bv1 = 0.f;
        if (EPI >= 1) { bv0 = bias[col]; bv1 = bias[col + 1]; }
#pragma unroll
        for (int mf = 0; mf < 4; mf++) {
            const int row = by * 128 + r0 + mf * 16 + g;
            float d0 = acc[mf][nf][0], d1 = acc[mf][nf][1];
            float d2 = acc[mf][nf][2], d3 = acc[mf][nf][3];
            if (EPI >= 1) { d0 += bv0; d1 += bv1; d2 += bv0; d3 += bv1; }
            d0 *= scale; d1 *= scale; d2 *= scale; d3 *= scale;
            if (EPI == 2) {
                d0 = d0 * normcdff(d0); d1 = d1 * normcdff(d1);
                d2 = d2 * normcdff(d2); d3 = d3 * normcdff(d3);
            }
            *(float2*)(C + (size_t)row * N + col)       = make_float2(d0, d1);
            *(float2*)(C + (size_t)(row + 8) * N + col) = make_float2(d2, d3);
        }
    }
}

// shared LN epilogue body (acc must hold A@W result; bias added inside)
#define MG_LN_EPILOG(biasp, scp, gammap, betap, outp)                          \
    {                                                                          \
        const int wq = wid >> 1;                                               \
        _Pragma("unroll")                                                      \
        for (int nf = 0; nf < 4; nf++) {                                       \
            const float2 bv = *(const float2*)&(biasp)[c0 + nf * 8 + 2 * tg];  \
            _Pragma("unroll")                                                  \
            for (int mf = 0; mf < 4; mf++) {                                   \
                acc[mf][nf][0] += bv.x; acc[mf][nf][1] += bv.y;                \
                acc[mf][nf][2] += bv.x; acc[mf][nf][3] += bv.y;                \
            }                                                                  \
        }                                                                      \
        _Pragma("unroll")                                                      \
        for (int mf = 0; mf < 4; mf++) {                                       \
            float s1A = 0.f, s2A = 0.f, s1B = 0.f, s2B = 0.f;                  \
            _Pragma("unroll")                                                  \
            for (int nf = 0; nf < 4; nf++) {                                   \
                s1A += acc[mf][nf][0] + acc[mf][nf][1];                        \
                s2A += acc[mf][nf][0] * acc[mf][nf][0] + acc[mf][nf][1] * acc[mf][nf][1]; \
                s1B += acc[mf][nf][2] + acc[mf][nf][3];                        \
                s2B += acc[mf][nf][2] * acc[mf][nf][2] + acc[mf][nf][3] * acc[mf][nf][3]; \
            }                                                                  \
            _Pragma("unroll")                                                  \
            for (int m = 1; m <= 2; m <<= 1) {                                 \
                s1A += __shfl_xor_sync(0xffffffffu, s1A, m);                   \
                s2A += __shfl_xor_sync(0xffffffffu, s2A, m);                   \
                s1B += __shfl_xor_sync(0xffffffffu, s1B, m);                   \
                s2B += __shfl_xor_sync(0xffffffffu, s2B, m);                   \
            }                                                                  \
            if (tg == 0) {                                                     \
                const int rA = r0 + mf * 16 + g;                               \
                redS[rA][wq][0] = s1A;     redS[rA][wq][1] = s2A;              \
                redS[rA + 8][wq][0] = s1B; redS[rA + 8][wq][1] = s2B;          \
            }                                                                  \
        }                                                                      \
        __syncthreads();                                                       \
        float gj[4][2], bj[4][2];                                              \
        _Pragma("unroll")                                                      \
        for (int nf = 0; nf < 4; nf++) {                                       \
            const int col = c0 + nf * 8 + 2 * tg;                              \
            *(float2*)gj[nf] = *(const float2*)&(gammap)[col];                 \
            *(float2*)bj[nf] = *(const float2*)&(betap)[col];                  \
        }                                                                      \
        _Pragma("unroll")                                                      \
        for (int mf = 0; mf < 4; mf++) {                                       \
            const int rA = r0 + mf * 16 + g;                                   \
            float s1A = redS[rA][0][0] + redS[rA][1][0] + redS[rA][2][0] + redS[rA][3][0]; \
            float s2A = redS[rA][0][1] + redS[rA][1][1] + redS[rA][2][1] + redS[rA][3][1]; \
            float s1B = redS[rA + 8][0][0] + redS[rA + 8][1][0] + redS[rA + 8][2][0] + redS[rA + 8][3][0]; \
            float s2B = redS[rA + 8][0][1] + redS[rA + 8][1][1] + redS[rA + 8][2][1] + redS[rA + 8][3][1]; \
            const float muA = s1A * (1.f / 128.f);                             \
            const float rsA = rsqrtf(s2A * (1.f / 128.f) - muA * muA + EPS_V); \
            const float muB = s1B * (1.f / 128.f);                             \
            const float rsB = rsqrtf(s2B * (1.f / 128.f) - muB * muB + EPS_V); \
            const int rowA = blockIdx.y * 128 + rA;                            \
            _Pragma("unroll")                                                  \
            for (int nf = 0; nf < 4; nf++) {                                   \
                const int col = c0 + nf * 8 + 2 * tg;                          \
                float2 scA = *(const float2*)((scp) + (size_t)rowA * 128 + col); \
                float2 scB = *(const float2*)((scp) + (size_t)(rowA + 8) * 128 + col); \
                float o0 = scA.x + (acc[mf][nf][0] - muA) * rsA * gj[nf][0] + bj[nf][0]; \
                float o1 = scA.y + (acc[mf][nf][1] - muA) * rsA * gj[nf][1] + bj[nf][1]; \
                float o2 = scB.x + (acc[mf][nf][2] - muB) * rsB * gj[nf][0] + bj[nf][0]; \
                float o3 = scB.y + (acc[mf][nf][3] - muB) * rsB * gj[nf][1] + bj[nf][1]; \
                *(float2*)((outp) + (size_t)rowA * 128 + col)       = make_float2(o0, o1); \
                *(float2*)((outp) + (size_t)(rowA + 8) * 128 + col) = make_float2(o2, o3); \
            }                                                                  \
        }                                                                      \
    }

// ---------------------------------------------------------------------------
// mgemm_ln: out = sc + LN(A@W + bias)*gamma + beta   (N == 128)
// ---------------------------------------------------------------------------
__global__ void __launch_bounds__(256, 2)
mgemm_ln(const float* __restrict__ A, const float* __restrict__ W,
         const float* __restrict__ bias, const float* __restrict__ sc,
         const float* __restrict__ gamma, const float* __restrict__ beta,
         float* __restrict__ out, int K,
         long long zA, long long zSc, long long zOut) {
    MG_PROLOG
    float (*redS)[4][2] = (float(*)[4][2])(dsm + SM_ASF_F + SM_BS_F);
    const int by = blockIdx.y;
    A += (size_t)blockIdx.z * zA;
    sc += (size_t)blockIdx.z * zSc;
    out += (size_t)blockIdx.z * zOut;
    const float* Ablk = A + (size_t)by * 128 * K;
    const float* Wblk = W;
    const int N = 128;
    const int nc = K / 32;
    float4 ra0, ra1, ra2, ra3;
    MG_MAINLOOP(MG_LDGA2, MG_CPB2)
    (void)N;
    MG_LN_EPILOG(bias, sc, gamma, beta, out)
}

// ---------------------------------------------------------------------------
// mlp_ln: out = x1 + LN(gelu(x1@W1 + b1) @ W2 + b2)*gamma + beta
// x1 tile staged once (4 frag-major buffers); H chunk lives only in smem Hs.
// Accumulation / rounding order bitwise-identical to the separate f1+f2 path.
// ---------------------------------------------------------------------------
__global__ void __launch_bounds__(256, 1)
mlp_ln(const float* __restrict__ A, const float* __restrict__ W1,
       const float* __restrict__ b1, const float* __restrict__ W2,
       const float* __restrict__ b2, const float* __restrict__ gamma,
       const float* __restrict__ beta, float* __restrict__ out,
       long long zA, long long zOut) {
    extern __shared__ float dsm[];
    float (*Asf)[4096] = (float(*)[4096])dsm;                       // 4 bufs
    float (*Bs)[32][SMS] = (float(*)[32][SMS])(dsm + 4 * 4096);
    float (*Hs)[136] = (float(*)[136])(dsm + 4 * 4096 + SM_BS_F);
    float (*redS)[4][2] = (float(*)[4][2])(dsm + 4 * 4096 + SM_BS_F + 128 * 136);
    MG_IDS
    float acc[4][4][4];           // f2 accumulator (persistent)
    MG_ACC_INIT(acc)
    uint32_t bsm[2];
    bsm[0] = (uint32_t)__cvta_generic_to_shared(&Bs[0][brow][bcol]);
    bsm[1] = (uint32_t)__cvta_generic_to_shared(&Bs[1][brow][bcol]);

    const int by = blockIdx.y;
    A += (size_t)blockIdx.z * zA;
    out += (size_t)blockIdx.z * zOut;
    const float* sc = A;                       // residual shortcut = x1
    const float* Ablk = A + (size_t)by * 128 * 128;
    const int K = 128;

    // stage x1 tile: 4 BK=32 chunks, frag-major, once
    {
        float4 ra0, ra1, ra2, ra3;
#pragma unroll
        for (int c = 0; c < 4; c++) {
            MG_LDGA2(c)
            MG_STSA2X(Asf[c])
        }
    }

#pragma unroll 1
    for (int oc = 0; oc < 4; oc++) {
        // ---- GEMM1: acca = x1 @ W1[:, oc*128 .. +128), K=128 ----
        float acca[4][4][4];
        MG_ACC_INIT(acca)
        const float* W1b = W1 + oc * 128;      // row stride HID
        MG_CPB2X(W1b, HID, 0, 0);
#pragma unroll
        for (int c = 0; c < 4; c++) {
            const int cur = c & 1;
            CP_WAIT0;
            __syncthreads();
            if (c < 3) MG_CPB2X(W1b, HID, c + 1, cur ^ 1);
            MG_COMPUTE2X(Asf[c], Bs[cur], acca);
        }
        __syncthreads();   // all Bs reads of GEMM1 retired before GEMM2 CPB

        // ---- epilogue1: h = gelu(acca + b1), tf32-round, -> Hs[k][m] ----
#pragma unroll
        for (int nf = 0; nf < 4; nf++) {
            const int col = c0 + nf * 8 + 2 * tg;
            const float bv0 = b1[oc * 128 + col];
            const float bv1 = b1[oc * 128 + col + 1];
#pragma unroll
            for (int mf = 0; mf < 4; mf++) {
                const int row = r0 + mf * 16 + g;
                float v0 = acca[mf][nf][0] + bv0; v0 *= 1.f; v0 = v0 * normcdff(v0);
                float v1 = acca[mf][nf][1] + bv1; v1 *= 1.f; v1 = v1 * normcdff(v1);
                float v2 = acca[mf][nf][2] + bv0; v2 *= 1.f; v2 = v2 * normcdff(v2);
                float v3 = acca[mf][nf][3] + bv1; v3 *= 1.f; v3 = v3 * normcdff(v3);
                Hs[col][row]         = to_tf32(v0);
                Hs[col + 1][row]     = to_tf32(v1);
                Hs[col][row + 8]     = to_tf32(v2);
                Hs[col + 1][row + 8] = to_tf32(v3);
            }
        }

        // ---- GEMM2: acc += Hs @ W2[oc*128 .. , :], K=128 ----
        const float* W2b = W2 + (size_t)(oc * 128) * 128;
        MG_CPB2X(W2b, 128, 0, 0);
#pragma unroll
        for (int c2 = 0; c2 < 4; c2++) {
            const int cur = c2 & 1;
            CP_WAIT0;
            __syncthreads();   // also makes Hs stores visible on first iter
            if (c2 < 3) MG_CPB2X(W2b, 128, c2 + 1, cur ^ 1);
            // A-frags from Hs (scalar LDS, conflict-free via pad 136)
#pragma unroll
            for (int sub = 0; sub < 2; sub++) {
#pragma unroll
                for (int ks = 0; ks < 16; ks += 8) {
                    const int kb = c2 * 32 + sub * 16 + ks;
                    float a[4][4], b[4][2];
#pragma unroll
                    for (int mf = 0; mf < 4; mf++) {
                        const float* h0 = &Hs[kb + tg][r0 + mf * 16 + g];
                        const float* h1 = &Hs[kb + tg + 4][r0 + mf * 16 + g];
                        a[mf][0] = h0[0]; a[mf][1] = h0[8];
                        a[mf][2] = h1[0]; a[mf][3] = h1[8];
                    }
#pragma unroll
                    for (int nf = 0; nf < 4; nf++) {
                        b[nf][0] = Bs[cur][sub * 16 + ks + tg][c0 + nf * 8 + g];
                        b[nf][1] = Bs[cur][sub * 16 + ks + tg + 4][c0 + nf * 8 + g];
                    }
#pragma unroll
                    for (int mf = 0; mf < 4; mf++)
#pragma unroll
                        for (int nf = 0; nf < 4; nf++)
                            mma8(acc[mf][nf], a[mf], b[nf]);
                }
            }
        }
        __syncthreads();   // Hs reads retired before next oc's epilogue1 writes
    }

    MG_LN_EPILOG(b2, sc, gamma, beta, out)
}

// ---------------------------------------------------------------------------
// Conv implicit GEMM (K=2304, nc=72); epilogue bias + PReLU.
// ---------------------------------------------------------------------------
__global__ void __launch_bounds__(256, 2)
conv_igemm(const float* __restrict__ sa, const float* __restrict__ ta,
           const float* __restrict__ Wg, const float* __restrict__ bias,
           const float* __restrict__ pa, float* __restrict__ out) {
    MG_PROLOG
    const int by = blockIdx.y;
    const int pixel = by * 128 + arow;
    const int xcrd = pixel % WW2;
    const int ycrd = (pixel / WW2) % HH;
    const int nc = CONVK / 32;   // 72
    const float* Wblk = Wg;
    const int N = CC;
    float4 ra0, ra1, ra2, ra3;

#define CV_LDGA_HALF(kk, p0, p1)                                               \
    {                                                                          \
        const int tap  = (kk) >> 8;                                            \
        const int rem  = (kk) & 255;                                           \
        const int half = rem >> 7;                                             \
        const int ic0  = (rem & 127) + acol;                                   \
        const int dy = tap / 3 - 1, dx = tap % 3 - 1;                          \
        const int ys = ycrd + dy, xs = xcrd + dx;                              \
        const bool valid = ((unsigned)ys < HH) && ((unsigned)xs < WW2);        \
        const float* src = half ? ta : sa;                                     \
        const float* ap = src + ((size_t)pixel + dy * WW2 + dx) * CC + ic0;    \
        p0 = make_float4(0.f, 0.f, 0.f, 0.f); p1 = p0;                         \
        if (valid) { p0 = *(const float4*)ap; p1 = *(const float4*)(ap + 4); } \
        cvt4(p0); cvt4(p1);                                                    \
    }
#define CV_LDGA2(c)                                                            \
    {                                                                          \
        CV_LDGA_HALF((c) * 32,      ra0, ra1)                                  \
        CV_LDGA_HALF((c) * 32 + 16, ra2, ra3)                                  \
    }

    MG_MAINLOOP(CV_LDGA2, MG_CPB2)

#pragma unroll
    for (int nf = 0; nf < 4; nf++) {
        const int col = c0 + nf * 8 + 2 * tg;
        const float bv0 = bias[col], bv1 = bias[col + 1];
        const float pv0 = pa[col],   pv1 = pa[col + 1];
#pragma unroll
        for (int mf = 0; mf < 4; mf++) {
            const int row = by * 128 + r0 + mf * 16 + g;
            float d0 = acc[mf][nf][0] + bv0, d1 = acc[mf][nf][1] + bv1;
            float d2 = acc[mf][nf][2] + bv0, d3 = acc[mf][nf][3] + bv1;
            if (d0 < 0.f) d0 *= pv0;
            if (d1 < 0.f) d1 *= pv1;
            if (d2 < 0.f) d2 *= pv0;
            if (d3 < 0.f) d3 *= pv1;
            *(float2*)(out + (size_t)row * CC + col)       = make_float2(d0, d1);
            *(float2*)(out + (size_t)(row + 8) * CC + col) = make_float2(d2, d3);
        }
    }
}

// ---------------------------------------------------------------------------
// Windowed attention: one 256-thr block per (window, batch, branch).
// ---------------------------------------------------------------------------
__device__ __forceinline__ int region_label(int h, int w) {
    int rh = (h < HH - WS) ? 0 : ((h < HH - WS / 2) ? 1 : 2);
    int rw = (w < WW2 - WS) ? 0 : ((w < WW2 - WS / 2) ? 1 : 2);
    return rh * 3 + rw;
}

__global__ void __launch_bounds__(256)
attn_kernel(const float* __restrict__ q, const float* __restrict__ kv,
            const float* __restrict__ relb, float* __restrict__ out,
            int shift) {
    const int win = blockIdx.x;
    const int b   = blockIdx.y;
    const int br  = blockIdx.z;
    const int gy = win / (WW2 / WS), gx = win % (WW2 / WS);
    const int tid = threadIdx.x;
    const int h = tid >> 6;
    const int t = tid & 63;
    const int ty = t >> 3, tx = t & 7;

    const float* kvB = kv + (size_t)br * NTOK * 2 * CC;
    float* outB = out + (size_t)br * NTOK * CC;

    __shared__ float ks[64][132];
    __shared__ float vs[64][132];
    __shared__ float rb[225 * NHEAD];

    for (int i = tid; i < 225 * NHEAD; i += 256) rb[i] = relb[i];

    {
        const int tt = tid >> 2;
        const int j  = tid & 3;
        const int tty = tt >> 3, ttx = tt & 7;
        const int lpy = (gy * WS + tty + shift) % HH;
        const int lpx = (gx * WS + ttx + shift) % WW2;
        const float4* src = (const float4*)(kvB + (((size_t)b * HH + lpy) * WW2 + lpx) * (2 * CC));
#pragma unroll
        for (int k4 = 0; k4 < 16; k4++) {
            const int fi = j + k4 * 4;
            float4 v = src[fi];
            if (fi < 32) *(float4*)&ks[tt][fi * 4] = v;
            else         *(float4*)&vs[tt][(fi - 32) * 4] = v;
        }
    }

    const int py = (gy * WS + ty + shift) % HH;
    const int px = (gx * WS + tx + shift) % WW2;
    const size_t pix = ((size_t)b * HH + py) * WW2 + px;

    float4 qr[HD / 4];
    const float4* qrow = (const float4*)(q + pix * CC + h * HD);
#pragma unroll
    for (int d4 = 0; d4 < HD / 4; d4++) qr[d4] = qrow[d4];
    __syncthreads();

    int li = 0;
    if (shift) li = region_label(gy * WS + ty, gx * WS + tx);

    float s[64];
    float mx = -1e30f;
#pragma unroll
    for (int j = 0; j < 64; j++) {
        float acc = 0.f;
        const float4* kr = (const float4*)&ks[j][h * HD];
#pragma unroll
        for (int d4 = 0; d4 < HD / 4; d4++) {
            float4 kk = kr[d4];
            acc += qr[d4].x * kk.x + qr[d4].y * kk.y + qr[d4].z * kk.z + qr[d4].w * kk.w;
        }
        int jy = j >> 3, jx = j & 7;
        acc += rb[((ty - jy + WS - 1) * (2 * WS - 1) + (tx - jx + WS - 1)) * NHEAD + h];
        if (shift) {
            int lj = region_label(gy * WS + jy, gx * WS + jx);
            if (lj != li) acc -= 100.0f;
        }
        s[j] = acc;
        mx = fmaxf(mx, acc);
    }
    float sum = 0.f;
#pragma unroll
    for (int j = 0; j < 64; j++) { s[j] = expf(s[j] - mx); sum += s[j]; }
    const float inv = 1.0f / sum;

    float4 o4[HD / 4];
#pragma unroll
    for (int d4 = 0; d4 < HD / 4; d4++) o4[d4] = make_float4(0.f, 0.f, 0.f, 0.f);
#pragma unroll
    for (int j = 0; j < 64; j++) {
        const float sj = s[j];
        const float4* vr = (const float4*)&vs[j][h * HD];
#pragma unroll
        for (int d4 = 0; d4 < HD / 4; d4++) {
            float4 vv = vr[d4];
            o4[d4].x += sj * vv.x; o4[d4].y += sj * vv.y;
            o4[d4].z += sj * vv.z; o4[d4].w += sj * vv.w;
        }
    }
    float4* orow = (float4*)(outB + pix * CC + h * HD);
#pragma unroll
    for (int d4 = 0; d4 < HD / 4; d4++) {
        float4 o = o4[d4];
        o.x *= inv; o.y *= inv; o.z *= inv; o.w *= inv;
        orow[d4] = o;
    }
}

// ---------------------------------------------------------------------------
// Host driver (graph-capturable: launches only)
// ---------------------------------------------------------------------------
template <typename T>
static float* sym(const T& s) {
    void* p = nullptr;
    cudaGetSymbolAddress(&p, s);
    return (float*)p;
}

extern "C" void kernel_launch(void* const* d_in, const int* in_sizes, int n_in,
                              void* d_out, int out_size) {
    const float* x      = (const float*)d_in[0];
    const float* source = (const float*)d_in[1];
    const float* target = (const float*)d_in[2];
    const float* qW     = (const float*)d_in[3];
    const float* qb     = (const float*)d_in[4];
    const float* kvW    = (const float*)d_in[5];
    const float* kvb    = (const float*)d_in[6];
    const float* pW     = (const float*)d_in[7];
    const float* pb     = (const float*)d_in[8];
    const float* relb   = (const float*)d_in[9];
    const float* mW     = (const float*)d_in[10];
    const float* n1g    = (const float*)d_in[11];
    const float* n1b    = (const float*)d_in[12];
    const float* f1W    = (const float*)d_in[13];
    const float* f1b    = (const float*)d_in[14];
    const float* f2W    = (const float*)d_in[15];
    const float* f2b    = (const float*)d_in[16];
    const float* n2g    = (const float*)d_in[17];
    const float* n2b    = (const float*)d_in[18];
    const float* convW  = (const float*)d_in[19];
    const float* convb  = (const float*)d_in[20];
    const float* pa     = (const float*)d_in[21];

    float* bx    = sym(g_x);
    float* bst   = sym(g_st);
    float* bq    = sym(g_q);
    float* bkv   = sym(g_kv);
    float* battn = sym(g_attn);
    float* bx1   = sym(g_x1);
    float* bbr   = sym(g_br);
    float* bwg   = sym(g_wg);
    float* bpwm  = sym(g_pwm);
    float* bpbm  = sym(g_pbm);
    float* bwq   = sym(g_wq);
    float* bwkv  = sym(g_wkv);
    float* bwf1  = sym(g_wf1);
    float* bwf2  = sym(g_wf2);

    // opt in to >48KB dynamic smem (host-side, idempotent, capture-safe)
    cudaFuncSetAttribute(mgemm<1>, cudaFuncAttributeMaxDynamicSharedMemorySize, SM_GEMM_B);
    cudaFuncSetAttribute(mgemm_ln, cudaFuncAttributeMaxDynamicSharedMemorySize, SM_LN_B);
    cudaFuncSetAttribute(mlp_ln, cudaFuncAttributeMaxDynamicSharedMemorySize, SM_MLP_B);
    cudaFuncSetAttribute(conv_igemm, cudaFuncAttributeMaxDynamicSharedMemorySize, SM_GEMM_B);

    const float SCALE = 0.1767766952966369f;   // 32^-0.5
    const long long ZC = (long long)NTOK * CC;
    const long long ZK = (long long)NTOK * 2 * CC;
    const dim3 gT(NPIX / 32, CC / 32, BB);

    t_nchw2nhwc<<<gT, 256>>>(x, bx);
    t_nchw2nhwc<<<gT, 256>>>(source, bst);
    t_nchw2nhwc<<<gT, 256>>>(target, bst + ZC);

    prep_all<<<(NPREP + 255) / 256, 256>>>(qW, kvW, f1W, f2W, convW);
    fuse_pwm_bias<<<dim3(CC + 1, 2), CC>>>(pW, pb, mW);

    for (int d = 0; d < 2; d++) {
        const int shift = (d % 2) ? (WS / 2) : 0;

        // q = (x @ qW + qb) * scale   (shared by both branches)
        mgemm<1><<<dim3(1, NTOK / 128, 1), 256, SM_GEMM_B>>>(
            bx, bwq + (size_t)d * CC * CC, qb + d * CC, bq, CC, CC, SCALE, 0, 0);
        // kv (both branches)
        mgemm<1><<<dim3(2, NTOK / 128, 2), 256, SM_GEMM_B>>>(
            bst, bwkv + (size_t)d * CC * 2 * CC, kvb + d * 2 * CC, bkv, 2 * CC, CC, 1.f, ZC, ZK);
        // attention (both branches)
        attn_kernel<<<dim3(576, BB, 2), 256>>>(bq, bkv, relb + (size_t)d * 225 * NHEAD,
                                               battn, shift);
        // x1 = x + LN(attn @ pWm + pbm)
        mgemm_ln<<<dim3(1, NTOK / 128, 2), 256, SM_LN_B>>>(
            battn, bpwm + (size_t)d * CC * CC, bpbm + d * CC, bx,
            n1g + d * CC, n1b + d * CC, bx1, CC, ZC, 0, ZC);
        // branch out = x1 + LN(gelu(x1@f1W+f1b)@f2W + f2b)   (fused MLP, h in smem)
        mlp_ln<<<dim3(1, NTOK / 128, 2), 256, SM_MLP_B>>>(
            bx1, bwf1 + (size_t)d * CC * HID, f1b + d * HID,
            bwf2 + (size_t)d * HID * CC, f2b + d * CC,
            n2g + d * CC, n2b + d * CC, bbr, ZC, ZC);
        // conv([sa; ta]) + bias + PReLU -> new x (NHWC)
        conv_igemm<<<dim3(1, NTOK / 128), 256, SM_GEMM_B>>>(
            bbr, bbr + ZC, bwg + (size_t)d * CONVK * CC, convb + d * CC, pa + d * CC, bx);
    }

    t_nhwc2nchw<<<gT, 256>>>(bx, (float*)d_out);
}